// round 3
// baseline (speedup 1.0000x reference)
#include <cuda_runtime.h>
#include <cstdint>

#define NN   100000
#define NG   512
#define HID  192
#define H4   48      // HID/4
#define EPSN 1e-5f

// ---------------- scratch (no allocs allowed) ----------------
__device__ float  g_dinv[NN];        // deg -> dinv (in place)
__device__ float  g_xs[NN];          // x * dinv
__device__ float  g_acc1[NN];        // scalar conv1 accumulator
__device__ float  g_agg[NN];         // conv1 scalar result
__device__ int    g_start[NG + 1];   // per-graph node range (batch is sorted)
__device__ float  g_gmean[NG];
__device__ float  g_gvar[NG];
__device__ float  g_P[NG * HID];
__device__ float  g_Q[NG * HID];
__device__ __align__(16) float4 g_ts4[NN * H4];    // dinv * (h1n @ W2)
__device__ __align__(16) float4 g_acc2_4[NN * H4]; // scatter accumulator (init = ts)
__device__ float  g_mean2[NG * HID];
__device__ float  g_scale2[NG * HID];
__device__ float  g_pooled[NG * HID];

// ---------------- small kernels ----------------
__global__ void k_deg_init(int n) {
    int i = blockIdx.x * blockDim.x + threadIdx.x;
    if (i < n) g_dinv[i] = 1.0f;  // self-loop
}

__global__ void k_deg(const int* __restrict__ ei, int e) {
    int idx = blockIdx.x * blockDim.x + threadIdx.x;
    if (idx < e) {
        int c = __ldg(&ei[e + idx]);
        atomicAdd(&g_dinv[c], 1.0f);
    }
}

__global__ void k_node1(const float* __restrict__ x, int n) {
    int i = blockIdx.x * blockDim.x + threadIdx.x;
    if (i < n) {
        float v = rsqrtf(g_dinv[i]);
        g_dinv[i] = v;
        g_xs[i]   = x[i] * v;
        g_acc1[i] = 0.0f;
    }
}

__global__ void k_edge1(const int* __restrict__ ei, int e) {
    int idx = blockIdx.x * blockDim.x + threadIdx.x;
    if (idx < e) {
        int r = __ldg(&ei[idx]);
        int c = __ldg(&ei[e + idx]);
        atomicAdd(&g_acc1[c], g_xs[r]);
    }
}

__global__ void k_agg(int n) {
    int i = blockIdx.x * blockDim.x + threadIdx.x;
    if (i < n) g_agg[i] = g_dinv[i] * (g_acc1[i] + g_xs[i]);
}

__global__ void k_start(const int* __restrict__ batch, int n) {
    int g = blockIdx.x * blockDim.x + threadIdx.x;
    if (g > NG) return;
    int lo = 0, hi = n;
    while (lo < hi) {
        int mid = (lo + hi) >> 1;
        if (batch[mid] < g) lo = mid + 1; else hi = mid;
    }
    g_start[g] = lo;
}

__global__ void k_gstats() {
    int g = blockIdx.x;
    int s = g_start[g], t = g_start[g + 1];
    int tid = threadIdx.x;
    float sum = 0.f, sq = 0.f;
    for (int i = s + tid; i < t; i += 128) {
        float a = g_agg[i];
        sum += a; sq += a * a;
    }
    __shared__ float ssum[128], ssq[128];
    ssum[tid] = sum; ssq[tid] = sq;
    __syncthreads();
    for (int o = 64; o > 0; o >>= 1) {
        if (tid < o) { ssum[tid] += ssum[tid + o]; ssq[tid] += ssq[tid + o]; }
        __syncthreads();
    }
    if (tid == 0) {
        float cnt = fmaxf((float)(t - s), 1.f);
        float m = ssum[0] / cnt;
        float v = ssq[0] / cnt - m * m;
        g_gmean[g] = m;
        g_gvar[g]  = fmaxf(v, 0.f);
    }
}

// h1n[i,j] = relu(P[g,j]*agg[i] + Q[g,j])   (graph_norm1 folded analytically)
__global__ void k_pq(const float* __restrict__ W1, const float* __restrict__ b1,
                     const float* __restrict__ g1, const float* __restrict__ be1,
                     const float* __restrict__ a1) {
    int idx = blockIdx.x * blockDim.x + threadIdx.x;
    if (idx >= NG * HID) return;
    int g = idx / HID, j = idx % HID;
    float w = W1[j], bj = b1[j], aj = a1[j], gj = g1[j], bej = be1[j];
    float m = g_gmean[g], va = g_gvar[g];
    float eo  = (1.f - aj) * (w * m + bj);      // E[out]
    float var = w * w * va + eo * eo;           // E[out^2]
    float sc  = gj * rsqrtf(var + EPSN);
    g_P[idx] = sc * w;
    g_Q[idx] = sc * (bj * (1.f - aj) - w * aj * m) + bej;
}

// ---------------- fused GEMM: ts = dinv * (relu(P*agg+Q) @ W2) ----------------
__global__ __launch_bounds__(256) void k_gemm(const float* __restrict__ W2,
                                              const int* __restrict__ batch,
                                              int n) {
    __shared__ __align__(16) float As[32][64];    // h1n tile, transposed (k, row)
    __shared__ __align__(16) float Bs[32][192];   // W2 tile (k, col)
    __shared__ float s_agg[64];
    __shared__ int   s_gb[64];

    int tid  = threadIdx.x;
    int row0 = blockIdx.x * 64;
    if (tid < 64) {
        int i = row0 + tid;
        s_agg[tid] = (i < n) ? g_agg[i] : 0.f;
        s_gb[tid]  = (i < n) ? batch[i] : 0;
    }
    __syncthreads();

    int tx = tid & 15, ty = tid >> 4;
    float acc[4][12];
#pragma unroll
    for (int r = 0; r < 4; r++)
#pragma unroll
        for (int c = 0; c < 12; c++) acc[r][c] = 0.f;

    const float4* W24 = (const float4*)W2;
    for (int kt = 0; kt < 6; kt++) {
        int k0 = kt * 32;
#pragma unroll
        for (int u = 0; u < 6; u++) {           // 1536 float4 / 256 thr
            int idx = tid + u * 256;
            int kk = idx / 48, c4 = idx % 48;
            ((float4*)Bs[kk])[c4] = W24[(k0 + kk) * 48 + c4];
        }
#pragma unroll
        for (int u = 0; u < 8; u++) {           // 2048 floats / 256 thr
            int idx = tid + u * 256;
            int kk = idx >> 6, rr = idx & 63;
            int gb = s_gb[rr];
            int j  = k0 + kk;
            float v = fmaf(g_P[gb * HID + j], s_agg[rr], g_Q[gb * HID + j]);
            As[kk][rr] = fmaxf(v, 0.f);
        }
        __syncthreads();
#pragma unroll
        for (int kk = 0; kk < 32; kk++) {
            float4 a4 = *(const float4*)&As[kk][ty * 4];
            float a[4] = {a4.x, a4.y, a4.z, a4.w};
            float b[12];
#pragma unroll
            for (int q = 0; q < 3; q++) {
                float4 b4 = ((const float4*)Bs[kk])[tx * 3 + q];
                b[q * 4 + 0] = b4.x; b[q * 4 + 1] = b4.y;
                b[q * 4 + 2] = b4.z; b[q * 4 + 3] = b4.w;
            }
#pragma unroll
            for (int r = 0; r < 4; r++)
#pragma unroll
                for (int c = 0; c < 12; c++) acc[r][c] = fmaf(a[r], b[c], acc[r][c]);
        }
        __syncthreads();
    }
    // epilogue: scale by dinv, write ts and init acc2 = ts (self-loop folded)
#pragma unroll
    for (int r = 0; r < 4; r++) {
        int row = row0 + ty * 4 + r;
        if (row < n) {
            float dv = g_dinv[row];
#pragma unroll
            for (int q = 0; q < 3; q++) {
                float4 v;
                v.x = acc[r][q * 4 + 0] * dv;
                v.y = acc[r][q * 4 + 1] * dv;
                v.z = acc[r][q * 4 + 2] * dv;
                v.w = acc[r][q * 4 + 3] * dv;
                int o = row * H4 + tx * 3 + q;
                g_ts4[o]    = v;
                g_acc2_4[o] = v;
            }
        }
    }
}

// ---------------- conv2 edge scatter: acc2[c] += ts[r] (vector red) ----------------
__global__ void k_scatter(const int* __restrict__ ei, int e) {
    int gid = blockIdx.x * blockDim.x + threadIdx.x;
    int total = e * H4;
    if (gid >= total) return;
    int eidx = gid / H4;
    int q    = gid % H4;
    int r = __ldg(&ei[eidx]);
    int c = __ldg(&ei[e + eidx]);
    float4 v = g_ts4[r * H4 + q];
    float* dst = (float*)&g_acc2_4[c * H4 + q];
    asm volatile("red.global.add.v4.f32 [%0], {%1,%2,%3,%4};"
                 :: "l"(dst), "f"(v.x), "f"(v.y), "f"(v.z), "f"(v.w) : "memory");
}

// ---------------- graph_norm2 stats (uncentered-variance trick) ----------------
__global__ void k_stats2(const float* __restrict__ b2, const float* __restrict__ a2,
                         const float* __restrict__ g2) {
    int g = blockIdx.x, j = threadIdx.x;      // 192 threads
    int s = g_start[g], t = g_start[g + 1];
    float bj = b2[j];
    float sum = 0.f, sq = 0.f;
    const float* acc2 = (const float*)g_acc2_4;
    for (int i = s; i < t; i++) {
        float v = fmaf(g_dinv[i], __ldg(&acc2[i * HID + j]), bj);   // h2pre
        sum += v; sq += v * v;
    }
    float cnt = fmaxf((float)(t - s), 1.f);
    float mean = sum / cnt;
    float aj = a2[j];
    float var = sq / cnt - (2.f * aj - aj * aj) * mean * mean;  // E[(v-a*mean)^2]
    var = fmaxf(var, 0.f);
    g_mean2[g * HID + j]  = mean;
    g_scale2[g * HID + j] = g2[j] * rsqrtf(var + EPSN);
}

// ---------------- norm2 + relu + mean-pool (h2n never materialized) ----------------
__global__ void k_pool(const float* __restrict__ b2, const float* __restrict__ a2,
                       const float* __restrict__ be2) {
    int g = blockIdx.x, j = threadIdx.x;      // 192 threads
    int s = g_start[g], t = g_start[g + 1];
    float bj = b2[j], aj = a2[j], bej = be2[j];
    float m  = g_mean2[g * HID + j];
    float sc = g_scale2[g * HID + j];
    float am = aj * m;
    const float* acc2 = (const float*)g_acc2_4;
    float p = 0.f;
    for (int i = s; i < t; i++) {
        float v = fmaf(g_dinv[i], __ldg(&acc2[i * HID + j]), bj);
        float y = fmaf(sc, v - am, bej);
        p += fmaxf(y, 0.f);
    }
    g_pooled[g * HID + j] = p / fmaxf((float)(t - s), 1.f);
}

// ---------------- classifier head ----------------
__global__ void k_head(const float* __restrict__ Wc1, const float* __restrict__ bc1,
                       const float* __restrict__ Wc2, const float* __restrict__ bc2,
                       float* __restrict__ out) {
    __shared__ float sp[HID];
    __shared__ float sz[96];
    int g = blockIdx.x, t = threadIdx.x;      // 96 threads
    sp[t]      = g_pooled[g * HID + t];
    sp[t + 96] = g_pooled[g * HID + 96 + t];
    __syncthreads();
    float d = bc1[t];
#pragma unroll 8
    for (int k = 0; k < HID; k++) d = fmaf(sp[k], Wc1[k * 96 + t], d);
    sz[t] = fmaxf(d, 0.f);
    __syncthreads();
    if (t < 4) {
        float o = bc2[t];
#pragma unroll 8
        for (int k = 0; k < 96; k++) o = fmaf(sz[k], Wc2[k * 4 + t], o);
        out[g * 4 + t] = o;
    }
}

// ---------------- launch ----------------
extern "C" void kernel_launch(void* const* d_in, const int* in_sizes, int n_in,
                              void* d_out, int out_size) {
    const float* x     = (const float*)d_in[0];
    const int*   ei    = (const int*)d_in[1];    // int32 (JAX x64 disabled)
    const int*   batch = (const int*)d_in[2];    // int32
    const float* W1  = (const float*)d_in[3];
    const float* b1  = (const float*)d_in[4];
    const float* g1  = (const float*)d_in[5];
    const float* be1 = (const float*)d_in[6];
    const float* a1  = (const float*)d_in[7];
    const float* W2  = (const float*)d_in[8];
    const float* b2  = (const float*)d_in[9];
    const float* g2  = (const float*)d_in[10];
    const float* be2 = (const float*)d_in[11];
    const float* a2  = (const float*)d_in[12];
    const float* Wc1 = (const float*)d_in[13];
    const float* bc1 = (const float*)d_in[14];
    const float* Wc2 = (const float*)d_in[15];
    const float* bc2 = (const float*)d_in[16];

    int n = in_sizes[0];        // 100000
    int e = in_sizes[1] / 2;    // 1600000

    k_deg_init<<<(n + 255) / 256, 256>>>(n);
    k_deg<<<(e + 255) / 256, 256>>>(ei, e);
    k_node1<<<(n + 255) / 256, 256>>>(x, n);
    k_edge1<<<(e + 255) / 256, 256>>>(ei, e);
    k_agg<<<(n + 255) / 256, 256>>>(n);
    k_start<<<(NG + 1 + 127) / 128, 128>>>(batch, n);
    k_gstats<<<NG, 128>>>();
    k_pq<<<(NG * HID + 255) / 256, 256>>>(W1, b1, g1, be1, a1);
    k_gemm<<<(n + 63) / 64, 256>>>(W2, batch, n);
    k_scatter<<<(e * H4 + 255) / 256, 256>>>(ei, e);
    k_stats2<<<NG, HID>>>(b2, a2, g2);
    k_pool<<<NG, HID>>>(b2, a2, be2);
    k_head<<<NG, 96>>>(Wc1, bc1, Wc2, bc2, (float*)d_out);
}

// round 4
// speedup vs baseline: 1.1796x; 1.1796x over previous
#include <cuda_runtime.h>
#include <cstdint>

#define NN   100000
#define NE   1600000
#define NG   512
#define HID  192
#define H4   48      // HID/4
#define EPSN 1e-5f

// ---------------- scratch (no allocs allowed) ----------------
__device__ int    g_cnt[NN];         // in-degree histogram (no self-loop)
__device__ int    g_off[NN + 1];     // CSR offsets by destination
__device__ int    g_cur[NN];         // fill cursors
__device__ int    g_srcs[NE];        // CSR: src list grouped by dst
__device__ float  g_dinv[NN];
__device__ float  g_xs[NN];          // x * dinv
__device__ float  g_acc1[NN];        // scalar conv1 accumulator
__device__ float  g_agg[NN];         // conv1 scalar result
__device__ int    g_start[NG + 1];   // per-graph node range (batch sorted)
__device__ float  g_gmean[NG];
__device__ float  g_gvar[NG];
__device__ float  g_P[NG * HID];
__device__ float  g_Q[NG * HID];
__device__ __align__(16) float4 g_ts4[NN * H4];    // dinv * (h1n @ W2)
__device__ __align__(16) float4 g_acc2_4[NN * H4]; // h2pre = dinv*sum + b2
__device__ float  g_mean2[NG * HID];
__device__ float  g_scale2[NG * HID];
__device__ float  g_pooled[NG * HID];

// ---------------- degree / conv1 scalar path ----------------
__global__ void k_init(int n) {
    int i = blockIdx.x * blockDim.x + threadIdx.x;
    if (i < n) g_cnt[i] = 0;
}

__global__ void k_deg(const int* __restrict__ ei, int e) {
    int idx = blockIdx.x * blockDim.x + threadIdx.x;
    if (idx < e) atomicAdd(&g_cnt[__ldg(&ei[e + idx])], 1);
}

__global__ void k_node1(const float* __restrict__ x, int n) {
    int i = blockIdx.x * blockDim.x + threadIdx.x;
    if (i < n) {
        float v = rsqrtf((float)(g_cnt[i] + 1));   // +1 self-loop
        g_dinv[i] = v;
        g_xs[i]   = x[i] * v;
        g_acc1[i] = 0.0f;
    }
}

__global__ void k_edge1(const int* __restrict__ ei, int e) {
    int idx = blockIdx.x * blockDim.x + threadIdx.x;
    if (idx < e) {
        int r = __ldg(&ei[idx]);
        int c = __ldg(&ei[e + idx]);
        atomicAdd(&g_acc1[c], g_xs[r]);
    }
}

__global__ void k_agg(int n) {
    int i = blockIdx.x * blockDim.x + threadIdx.x;
    if (i < n) g_agg[i] = g_dinv[i] * (g_acc1[i] + g_xs[i]);
}

// ---------------- CSR build ----------------
__global__ __launch_bounds__(1024) void k_scan(int n) {     // single block
    __shared__ int part[1024];
    int tid = threadIdx.x;
    int chunk = (n + 1023) / 1024;
    int s0 = tid * chunk, s1 = min(s0 + chunk, n);
    int s = 0;
    for (int i = s0; i < s1; i++) s += g_cnt[i];
    part[tid] = s;
    __syncthreads();
    for (int off = 1; off < 1024; off <<= 1) {
        int v = part[tid];
        int add = (tid >= off) ? part[tid - off] : 0;
        __syncthreads();
        part[tid] = v + add;
        __syncthreads();
    }
    int run = (tid > 0) ? part[tid - 1] : 0;
    for (int i = s0; i < s1; i++) {
        g_off[i] = run;
        g_cur[i] = run;
        run += g_cnt[i];
    }
    if (tid == 0) g_off[n] = part[1023];
}

__global__ void k_fill(const int* __restrict__ ei, int e) {
    int idx = blockIdx.x * blockDim.x + threadIdx.x;
    if (idx < e) {
        int r = __ldg(&ei[idx]);
        int c = __ldg(&ei[e + idx]);
        int p = atomicAdd(&g_cur[c], 1);
        g_srcs[p] = r;
    }
}

// ---------------- graph stats for norm1 ----------------
__global__ void k_start(const int* __restrict__ batch, int n) {
    int g = blockIdx.x * blockDim.x + threadIdx.x;
    if (g > NG) return;
    int lo = 0, hi = n;
    while (lo < hi) {
        int mid = (lo + hi) >> 1;
        if (batch[mid] < g) lo = mid + 1; else hi = mid;
    }
    g_start[g] = lo;
}

__global__ void k_gstats() {
    int g = blockIdx.x;
    int s = g_start[g], t = g_start[g + 1];
    int tid = threadIdx.x;
    float sum = 0.f, sq = 0.f;
    for (int i = s + tid; i < t; i += 128) {
        float a = g_agg[i];
        sum += a; sq += a * a;
    }
    __shared__ float ssum[128], ssq[128];
    ssum[tid] = sum; ssq[tid] = sq;
    __syncthreads();
    for (int o = 64; o > 0; o >>= 1) {
        if (tid < o) { ssum[tid] += ssum[tid + o]; ssq[tid] += ssq[tid + o]; }
        __syncthreads();
    }
    if (tid == 0) {
        float cnt = fmaxf((float)(t - s), 1.f);
        float m = ssum[0] / cnt;
        float v = ssq[0] / cnt - m * m;
        g_gmean[g] = m;
        g_gvar[g]  = fmaxf(v, 0.f);
    }
}

// h1n[i,j] = relu(P[g,j]*agg[i] + Q[g,j])
__global__ void k_pq(const float* __restrict__ W1, const float* __restrict__ b1,
                     const float* __restrict__ g1, const float* __restrict__ be1,
                     const float* __restrict__ a1) {
    int idx = blockIdx.x * blockDim.x + threadIdx.x;
    if (idx >= NG * HID) return;
    int g = idx / HID, j = idx % HID;
    float w = W1[j], bj = b1[j], aj = a1[j], gj = g1[j], bej = be1[j];
    float m = g_gmean[g], va = g_gvar[g];
    float eo  = (1.f - aj) * (w * m + bj);
    float var = w * w * va + eo * eo;
    float sc  = gj * rsqrtf(var + EPSN);
    g_P[idx] = sc * w;
    g_Q[idx] = sc * (bj * (1.f - aj) - w * aj * m) + bej;
}

// ---------------- fused GEMM: ts = dinv * (relu(P*agg+Q) @ W2) ----------------
__global__ __launch_bounds__(256) void k_gemm(const float* __restrict__ W2,
                                              const int* __restrict__ batch,
                                              int n) {
    __shared__ __align__(16) float As[32][64];
    __shared__ __align__(16) float Bs[32][192];
    __shared__ float s_agg[64];
    __shared__ int   s_gb[64];

    int tid  = threadIdx.x;
    int row0 = blockIdx.x * 64;
    if (tid < 64) {
        int i = row0 + tid;
        s_agg[tid] = (i < n) ? g_agg[i] : 0.f;
        s_gb[tid]  = (i < n) ? batch[i] : 0;
    }
    __syncthreads();

    int tx = tid & 15, ty = tid >> 4;
    float acc[4][12];
#pragma unroll
    for (int r = 0; r < 4; r++)
#pragma unroll
        for (int c = 0; c < 12; c++) acc[r][c] = 0.f;

    const float4* W24 = (const float4*)W2;
    for (int kt = 0; kt < 6; kt++) {
        int k0 = kt * 32;
#pragma unroll
        for (int u = 0; u < 6; u++) {
            int idx = tid + u * 256;
            int kk = idx / 48, c4 = idx % 48;
            ((float4*)Bs[kk])[c4] = W24[(k0 + kk) * 48 + c4];
        }
#pragma unroll
        for (int u = 0; u < 8; u++) {
            int idx = tid + u * 256;
            int kk = idx >> 6, rr = idx & 63;
            int gb = s_gb[rr];
            int j  = k0 + kk;
            float v = fmaf(g_P[gb * HID + j], s_agg[rr], g_Q[gb * HID + j]);
            As[kk][rr] = fmaxf(v, 0.f);
        }
        __syncthreads();
#pragma unroll
        for (int kk = 0; kk < 32; kk++) {
            float4 a4 = *(const float4*)&As[kk][ty * 4];
            float a[4] = {a4.x, a4.y, a4.z, a4.w};
            float b[12];
#pragma unroll
            for (int q = 0; q < 3; q++) {
                float4 b4 = ((const float4*)Bs[kk])[tx * 3 + q];
                b[q * 4 + 0] = b4.x; b[q * 4 + 1] = b4.y;
                b[q * 4 + 2] = b4.z; b[q * 4 + 3] = b4.w;
            }
#pragma unroll
            for (int r = 0; r < 4; r++)
#pragma unroll
                for (int c = 0; c < 12; c++) acc[r][c] = fmaf(a[r], b[c], acc[r][c]);
        }
        __syncthreads();
    }
#pragma unroll
    for (int r = 0; r < 4; r++) {
        int row = row0 + ty * 4 + r;
        if (row < n) {
            float dv = g_dinv[row];
#pragma unroll
            for (int q = 0; q < 3; q++) {
                float4 v;
                v.x = acc[r][q * 4 + 0] * dv;
                v.y = acc[r][q * 4 + 1] * dv;
                v.z = acc[r][q * 4 + 2] * dv;
                v.w = acc[r][q * 4 + 3] * dv;
                g_ts4[row * H4 + tx * 3 + q] = v;
            }
        }
    }
}

// ---------------- conv2 aggregate (CSR gather, half-warp per dst) ----------------
// acc2[c,:] = dinv[c] * (ts[c,:] + sum_{r in N(c)} ts[r,:]) + b2[:]
__global__ __launch_bounds__(256) void k_aggregate(const float* __restrict__ b2, int n) {
    int t = blockIdx.x * blockDim.x + threadIdx.x;
    int node = t >> 4;
    int lane = t & 15;
    if (node >= n) return;

    const float4* base = &g_ts4[(size_t)node * H4];
    float4 a0 = base[lane];
    float4 a1 = base[16 + lane];
    float4 a2 = base[32 + lane];

    int off = g_off[node], end = g_off[node + 1];
    for (int k = off; k < end; k++) {
        int s = __ldg(&g_srcs[k]);
        const float4* row = &g_ts4[(size_t)s * H4];
        float4 v0 = __ldg(&row[lane]);
        float4 v1 = __ldg(&row[16 + lane]);
        float4 v2 = __ldg(&row[32 + lane]);
        a0.x += v0.x; a0.y += v0.y; a0.z += v0.z; a0.w += v0.w;
        a1.x += v1.x; a1.y += v1.y; a1.z += v1.z; a1.w += v1.w;
        a2.x += v2.x; a2.y += v2.y; a2.z += v2.z; a2.w += v2.w;
    }

    float dv = g_dinv[node];
    const float4* b24 = (const float4*)b2;
    float4 b_0 = __ldg(&b24[lane]);
    float4 b_1 = __ldg(&b24[16 + lane]);
    float4 b_2 = __ldg(&b24[32 + lane]);
    float4 o0, o1, o2;
    o0.x = fmaf(dv, a0.x, b_0.x); o0.y = fmaf(dv, a0.y, b_0.y);
    o0.z = fmaf(dv, a0.z, b_0.z); o0.w = fmaf(dv, a0.w, b_0.w);
    o1.x = fmaf(dv, a1.x, b_1.x); o1.y = fmaf(dv, a1.y, b_1.y);
    o1.z = fmaf(dv, a1.z, b_1.z); o1.w = fmaf(dv, a1.w, b_1.w);
    o2.x = fmaf(dv, a2.x, b_2.x); o2.y = fmaf(dv, a2.y, b_2.y);
    o2.z = fmaf(dv, a2.z, b_2.z); o2.w = fmaf(dv, a2.w, b_2.w);
    float4* out = &g_acc2_4[(size_t)node * H4];
    out[lane]      = o0;
    out[16 + lane] = o1;
    out[32 + lane] = o2;
}

// ---------------- graph_norm2 stats (h2pre already materialized) ----------------
__global__ void k_stats2(const float* __restrict__ a2, const float* __restrict__ g2) {
    int g = blockIdx.x, j = threadIdx.x;      // 192 threads
    int s = g_start[g], t = g_start[g + 1];
    float sum = 0.f, sq = 0.f;
    const float* acc2 = (const float*)g_acc2_4;
    for (int i = s; i < t; i++) {
        float v = __ldg(&acc2[(size_t)i * HID + j]);
        sum += v; sq += v * v;
    }
    float cnt = fmaxf((float)(t - s), 1.f);
    float mean = sum / cnt;
    float aj = a2[j];
    float var = sq / cnt - (2.f * aj - aj * aj) * mean * mean;
    var = fmaxf(var, 0.f);
    g_mean2[g * HID + j]  = mean;
    g_scale2[g * HID + j] = g2[j] * rsqrtf(var + EPSN);
}

// ---------------- norm2 + relu + mean-pool ----------------
__global__ void k_pool(const float* __restrict__ a2, const float* __restrict__ be2) {
    int g = blockIdx.x, j = threadIdx.x;      // 192 threads
    int s = g_start[g], t = g_start[g + 1];
    float aj = a2[j], bej = be2[j];
    float m  = g_mean2[g * HID + j];
    float sc = g_scale2[g * HID + j];
    float am = aj * m;
    const float* acc2 = (const float*)g_acc2_4;
    float p = 0.f;
    for (int i = s; i < t; i++) {
        float v = __ldg(&acc2[(size_t)i * HID + j]);
        float y = fmaf(sc, v - am, bej);
        p += fmaxf(y, 0.f);
    }
    g_pooled[g * HID + j] = p / fmaxf((float)(t - s), 1.f);
}

// ---------------- classifier head ----------------
__global__ void k_head(const float* __restrict__ Wc1, const float* __restrict__ bc1,
                       const float* __restrict__ Wc2, const float* __restrict__ bc2,
                       float* __restrict__ out) {
    __shared__ float sp[HID];
    __shared__ float sz[96];
    int g = blockIdx.x, t = threadIdx.x;      // 96 threads
    sp[t]      = g_pooled[g * HID + t];
    sp[t + 96] = g_pooled[g * HID + 96 + t];
    __syncthreads();
    float d = bc1[t];
#pragma unroll 8
    for (int k = 0; k < HID; k++) d = fmaf(sp[k], Wc1[k * 96 + t], d);
    sz[t] = fmaxf(d, 0.f);
    __syncthreads();
    if (t < 4) {
        float o = bc2[t];
#pragma unroll 8
        for (int k = 0; k < 96; k++) o = fmaf(sz[k], Wc2[k * 4 + t], o);
        out[g * 4 + t] = o;
    }
}

// ---------------- launch ----------------
extern "C" void kernel_launch(void* const* d_in, const int* in_sizes, int n_in,
                              void* d_out, int out_size) {
    const float* x     = (const float*)d_in[0];
    const int*   ei    = (const int*)d_in[1];
    const int*   batch = (const int*)d_in[2];
    const float* W1  = (const float*)d_in[3];
    const float* b1  = (const float*)d_in[4];
    const float* g1  = (const float*)d_in[5];
    const float* be1 = (const float*)d_in[6];
    const float* a1  = (const float*)d_in[7];
    const float* W2  = (const float*)d_in[8];
    const float* b2  = (const float*)d_in[9];
    const float* g2  = (const float*)d_in[10];
    const float* be2 = (const float*)d_in[11];
    const float* a2  = (const float*)d_in[12];
    const float* Wc1 = (const float*)d_in[13];
    const float* bc1 = (const float*)d_in[14];
    const float* Wc2 = (const float*)d_in[15];
    const float* bc2 = (const float*)d_in[16];

    int n = in_sizes[0];        // 100000
    int e = in_sizes[1] / 2;    // 1600000

    k_init<<<(n + 255) / 256, 256>>>(n);
    k_deg<<<(e + 255) / 256, 256>>>(ei, e);
    k_node1<<<(n + 255) / 256, 256>>>(x, n);
    k_edge1<<<(e + 255) / 256, 256>>>(ei, e);
    k_agg<<<(n + 255) / 256, 256>>>(n);
    k_scan<<<1, 1024>>>(n);
    k_fill<<<(e + 255) / 256, 256>>>(ei, e);
    k_start<<<(NG + 1 + 127) / 128, 128>>>(batch, n);
    k_gstats<<<NG, 128>>>();
    k_pq<<<(NG * HID + 255) / 256, 256>>>(W1, b1, g1, be1, a1);
    k_gemm<<<(n + 63) / 64, 256>>>(W2, batch, n);
    k_aggregate<<<(n * 16 + 255) / 256, 256>>>(b2, n);
    k_stats2<<<NG, HID>>>(a2, g2);
    k_pool<<<NG, HID>>>(a2, be2);
    k_head<<<NG, 96>>>(Wc1, bc1, Wc2, bc2, (float*)d_out);
}

// round 6
// speedup vs baseline: 1.2032x; 1.0200x over previous
#include <cuda_runtime.h>
#include <cuda_fp16.h>
#include <cstdint>

#define NN   100000
#define NE   1600000
#define NG   512
#define HID  192
#define H4   48      // HID/4
#define EPSN 1e-5f

// ---------------- scratch (no allocs allowed) ----------------
__device__ int    g_cnt[NN];         // in-degree histogram (no self-loop)
__device__ int    g_off[NN + 1];     // CSR offsets by destination
__device__ int    g_cur[NN];         // fill cursors
__device__ int    g_srcs[NE];        // CSR: src list grouped by dst
__device__ float  g_dinv[NN];
__device__ float  g_xs[NN];          // x * dinv
__device__ float  g_agg[NN];         // conv1 scalar result
__device__ int    g_start[NG + 1];   // per-graph node range (batch sorted)
__device__ float  g_gmean[NG];
__device__ float  g_gvar[NG];
__device__ float  g_P[NG * HID];
__device__ float  g_Q[NG * HID];
__device__ __align__(16) float4  g_ts4[NN * H4];    // dinv * (h1n @ W2), fp32
__device__ __align__(16) __half2 g_ts16[NN * 96];   // same, fp16 (gather payload)
__device__ __align__(16) float4  g_acc2_4[NN * H4]; // h2pre = dinv*sum + b2
__device__ float  g_pooled[NG * HID];

// ---------------- CSR build ----------------
__global__ void k_init(int n) {
    int i = blockIdx.x * blockDim.x + threadIdx.x;
    if (i < n) g_cnt[i] = 0;
}

__global__ void k_deg(const int* __restrict__ ei, int e) {
    int idx = blockIdx.x * blockDim.x + threadIdx.x;
    if (idx < e) atomicAdd(&g_cnt[__ldg(&ei[e + idx])], 1);
}

__global__ __launch_bounds__(1024) void k_scan(int n) {     // single block
    __shared__ int part[1024];
    int tid = threadIdx.x;
    int chunk = (n + 1023) / 1024;
    int s0 = tid * chunk, s1 = min(s0 + chunk, n);
    int s = 0;
    for (int i = s0; i < s1; i++) s += g_cnt[i];
    part[tid] = s;
    __syncthreads();
    for (int off = 1; off < 1024; off <<= 1) {
        int v = part[tid];
        int add = (tid >= off) ? part[tid - off] : 0;
        __syncthreads();
        part[tid] = v + add;
        __syncthreads();
    }
    int run = (tid > 0) ? part[tid - 1] : 0;
    for (int i = s0; i < s1; i++) {
        g_off[i] = run;
        g_cur[i] = run;
        run += g_cnt[i];
    }
    if (tid == 0) g_off[n] = part[1023];
}

__global__ void k_fill(const int* __restrict__ ei, int e) {
    int idx = blockIdx.x * blockDim.x + threadIdx.x;
    if (idx < e) {
        int r = __ldg(&ei[idx]);
        int c = __ldg(&ei[e + idx]);
        int p = atomicAdd(&g_cur[c], 1);
        g_srcs[p] = r;
    }
}

// ---------------- conv1 (scalar, CSR) ----------------
__global__ void k_node1(const float* __restrict__ x, int n) {
    int i = blockIdx.x * blockDim.x + threadIdx.x;
    if (i < n) {
        float v = rsqrtf((float)(g_cnt[i] + 1));   // +1 self-loop
        g_dinv[i] = v;
        g_xs[i]   = x[i] * v;
    }
}

__global__ void k_conv1(int n) {
    int i = blockIdx.x * blockDim.x + threadIdx.x;
    if (i >= n) return;
    int off = g_off[i], end = g_off[i + 1];
    float s = g_xs[i];                              // self-loop
    for (int k = off; k < end; k++) s += __ldg(&g_xs[g_srcs[k]]);
    g_agg[i] = g_dinv[i] * s;
}

// ---------------- graph stats for norm1 ----------------
__global__ void k_start(const int* __restrict__ batch, int n) {
    int g = blockIdx.x * blockDim.x + threadIdx.x;
    if (g > NG) return;
    int lo = 0, hi = n;
    while (lo < hi) {
        int mid = (lo + hi) >> 1;
        if (batch[mid] < g) lo = mid + 1; else hi = mid;
    }
    g_start[g] = lo;
}

__global__ void k_gstats() {
    int g = blockIdx.x;
    int s = g_start[g], t = g_start[g + 1];
    int tid = threadIdx.x;
    float sum = 0.f, sq = 0.f;
    for (int i = s + tid; i < t; i += 128) {
        float a = g_agg[i];
        sum += a; sq += a * a;
    }
    __shared__ float ssum[128], ssq[128];
    ssum[tid] = sum; ssq[tid] = sq;
    __syncthreads();
    for (int o = 64; o > 0; o >>= 1) {
        if (tid < o) { ssum[tid] += ssum[tid + o]; ssq[tid] += ssq[tid + o]; }
        __syncthreads();
    }
    if (tid == 0) {
        float cnt = fmaxf((float)(t - s), 1.f);
        float m = ssum[0] / cnt;
        float v = ssq[0] / cnt - m * m;
        g_gmean[g] = m;
        g_gvar[g]  = fmaxf(v, 0.f);
    }
}

// h1n[i,j] = relu(P[g,j]*agg[i] + Q[g,j])
__global__ void k_pq(const float* __restrict__ W1, const float* __restrict__ b1,
                     const float* __restrict__ g1, const float* __restrict__ be1,
                     const float* __restrict__ a1) {
    int idx = blockIdx.x * blockDim.x + threadIdx.x;
    if (idx >= NG * HID) return;
    int g = idx / HID, j = idx % HID;
    float w = W1[j], bj = b1[j], aj = a1[j], gj = g1[j], bej = be1[j];
    float m = g_gmean[g], va = g_gvar[g];
    float eo  = (1.f - aj) * (w * m + bj);
    float var = w * w * va + eo * eo;
    float sc  = gj * rsqrtf(var + EPSN);
    g_P[idx] = sc * w;
    g_Q[idx] = sc * (bj * (1.f - aj) - w * aj * m) + bej;
}

// ---------------- fused GEMM: ts = dinv * (relu(P*agg+Q) @ W2) ----------------
__global__ __launch_bounds__(256) void k_gemm(const float* __restrict__ W2,
                                              const int* __restrict__ batch,
                                              int n) {
    __shared__ __align__(16) float As[32][64];
    __shared__ __align__(16) float Bs[32][192];
    __shared__ float s_agg[64];
    __shared__ int   s_gb[64];

    int tid  = threadIdx.x;
    int row0 = blockIdx.x * 64;
    if (tid < 64) {
        int i = row0 + tid;
        s_agg[tid] = (i < n) ? g_agg[i] : 0.f;
        s_gb[tid]  = (i < n) ? batch[i] : 0;
    }
    __syncthreads();

    int tx = tid & 15, ty = tid >> 4;
    float acc[4][12];
#pragma unroll
    for (int r = 0; r < 4; r++)
#pragma unroll
        for (int c = 0; c < 12; c++) acc[r][c] = 0.f;

    const float4* W24 = (const float4*)W2;
    for (int kt = 0; kt < 6; kt++) {
        int k0 = kt * 32;
#pragma unroll
        for (int u = 0; u < 6; u++) {
            int idx = tid + u * 256;
            int kk = idx / 48, c4 = idx % 48;
            ((float4*)Bs[kk])[c4] = W24[(k0 + kk) * 48 + c4];
        }
#pragma unroll
        for (int u = 0; u < 8; u++) {
            int idx = tid + u * 256;
            int kk = idx >> 6, rr = idx & 63;
            int gb = s_gb[rr];
            int j  = k0 + kk;
            float v = fmaf(g_P[gb * HID + j], s_agg[rr], g_Q[gb * HID + j]);
            As[kk][rr] = fmaxf(v, 0.f);
        }
        __syncthreads();
#pragma unroll
        for (int kk = 0; kk < 32; kk++) {
            float4 a4 = *(const float4*)&As[kk][ty * 4];
            float a[4] = {a4.x, a4.y, a4.z, a4.w};
            float b[12];
#pragma unroll
            for (int q = 0; q < 3; q++) {
                float4 b4 = ((const float4*)Bs[kk])[tx * 3 + q];
                b[q * 4 + 0] = b4.x; b[q * 4 + 1] = b4.y;
                b[q * 4 + 2] = b4.z; b[q * 4 + 3] = b4.w;
            }
#pragma unroll
            for (int r = 0; r < 4; r++)
#pragma unroll
                for (int c = 0; c < 12; c++) acc[r][c] = fmaf(a[r], b[c], acc[r][c]);
        }
        __syncthreads();
    }
#pragma unroll
    for (int r = 0; r < 4; r++) {
        int row = row0 + ty * 4 + r;
        if (row < n) {
            float dv = g_dinv[row];
#pragma unroll
            for (int q = 0; q < 3; q++) {
                float4 v;
                v.x = acc[r][q * 4 + 0] * dv;
                v.y = acc[r][q * 4 + 1] * dv;
                v.z = acc[r][q * 4 + 2] * dv;
                v.w = acc[r][q * 4 + 3] * dv;
                int cf = tx * 3 + q;                // float4-column index [0,48)
                g_ts4[row * H4 + cf] = v;
                g_ts16[row * 96 + cf * 2]     = __floats2half2_rn(v.x, v.y);
                g_ts16[row * 96 + cf * 2 + 1] = __floats2half2_rn(v.z, v.w);
            }
        }
    }
}

// ---------------- conv2 aggregate (CSR gather, half-warp per dst) ----------------
// acc2[c,:] = dinv[c] * (ts[c,:] + sum_{r in N(c)} ts16[r,:]) + b2[:]
__device__ __forceinline__ void add_u2(float4& a, uint2 u) {
    __half2 h0 = *reinterpret_cast<__half2*>(&u.x);
    __half2 h1 = *reinterpret_cast<__half2*>(&u.y);
    float2 f0 = __half22float2(h0);
    float2 f1 = __half22float2(h1);
    a.x += f0.x; a.y += f0.y; a.z += f1.x; a.w += f1.y;
}

__global__ __launch_bounds__(256) void k_aggregate(const float* __restrict__ b2, int n) {
    int t = blockIdx.x * blockDim.x + threadIdx.x;
    int node = t >> 4;
    int lane = t & 15;
    if (node >= n) return;

    const float4* base = &g_ts4[(size_t)node * H4];
    float4 a0 = base[lane];
    float4 a1 = base[16 + lane];
    float4 a2 = base[32 + lane];

    const uint2* ts16 = (const uint2*)g_ts16;
    int off = g_off[node], end = g_off[node + 1];
    int s_next = (off < end) ? __ldg(&g_srcs[off]) : 0;
    for (int k = off; k < end; k++) {
        int s = s_next;
        if (k + 1 < end) s_next = __ldg(&g_srcs[k + 1]);
        const uint2* rp = ts16 + (size_t)s * 48 + lane;
        uint2 u0 = __ldg(rp);
        uint2 u1 = __ldg(rp + 16);
        uint2 u2 = __ldg(rp + 32);
        add_u2(a0, u0);
        add_u2(a1, u1);
        add_u2(a2, u2);
    }

    float dv = g_dinv[node];
    const float4* b24 = (const float4*)b2;
    float4 b_0 = __ldg(&b24[lane]);
    float4 b_1 = __ldg(&b24[16 + lane]);
    float4 b_2 = __ldg(&b24[32 + lane]);
    float4 o0, o1, o2;
    o0.x = fmaf(dv, a0.x, b_0.x); o0.y = fmaf(dv, a0.y, b_0.y);
    o0.z = fmaf(dv, a0.z, b_0.z); o0.w = fmaf(dv, a0.w, b_0.w);
    o1.x = fmaf(dv, a1.x, b_1.x); o1.y = fmaf(dv, a1.y, b_1.y);
    o1.z = fmaf(dv, a1.z, b_1.z); o1.w = fmaf(dv, a1.w, b_1.w);
    o2.x = fmaf(dv, a2.x, b_2.x); o2.y = fmaf(dv, a2.y, b_2.y);
    o2.z = fmaf(dv, a2.z, b_2.z); o2.w = fmaf(dv, a2.w, b_2.w);
    float4* out = &g_acc2_4[(size_t)node * H4];
    out[lane]      = o0;
    out[16 + lane] = o1;
    out[32 + lane] = o2;
}

// ---------------- fused graph_norm2 stats + relu + mean-pool ----------------
__global__ void k_norm2pool(const float* __restrict__ a2, const float* __restrict__ g2,
                            const float* __restrict__ be2) {
    int g = blockIdx.x, j = threadIdx.x;      // 192 threads
    int s = g_start[g], t = g_start[g + 1];
    const float* acc2 = (const float*)g_acc2_4;
    float sum = 0.f, sq = 0.f;
    for (int i = s; i < t; i++) {
        float v = __ldg(&acc2[(size_t)i * HID + j]);
        sum += v; sq += v * v;
    }
    float cnt  = fmaxf((float)(t - s), 1.f);
    float mean = sum / cnt;
    float aj   = a2[j];
    float var  = sq / cnt - (2.f * aj - aj * aj) * mean * mean;
    var = fmaxf(var, 0.f);
    float sc  = g2[j] * rsqrtf(var + EPSN);
    float am  = aj * mean;
    float bej = be2[j];
    float p = 0.f;
    for (int i = s; i < t; i++) {
        float v = __ldg(&acc2[(size_t)i * HID + j]);
        float y = fmaf(sc, v - am, bej);
        p += fmaxf(y, 0.f);
    }
    g_pooled[g * HID + j] = p / cnt;
}

// ---------------- classifier head ----------------
__global__ void k_head(const float* __restrict__ Wc1, const float* __restrict__ bc1,
                       const float* __restrict__ Wc2, const float* __restrict__ bc2,
                       float* __restrict__ out) {
    __shared__ float sp[HID];
    __shared__ float sz[96];
    int g = blockIdx.x, t = threadIdx.x;      // 96 threads
    sp[t]      = g_pooled[g * HID + t];
    sp[t + 96] = g_pooled[g * HID + 96 + t];
    __syncthreads();
    float d = bc1[t];
#pragma unroll 8
    for (int k = 0; k < HID; k++) d = fmaf(sp[k], Wc1[k * 96 + t], d);
    sz[t] = fmaxf(d, 0.f);
    __syncthreads();
    if (t < 4) {
        float o = bc2[t];
#pragma unroll 8
        for (int k = 0; k < 96; k++) o = fmaf(sz[k], Wc2[k * 4 + t], o);
        out[g * 4 + t] = o;
    }
}

// ---------------- launch ----------------
extern "C" void kernel_launch(void* const* d_in, const int* in_sizes, int n_in,
                              void* d_out, int out_size) {
    const float* x     = (const float*)d_in[0];
    const int*   ei    = (const int*)d_in[1];
    const int*   batch = (const int*)d_in[2];
    const float* W1  = (const float*)d_in[3];
    const float* b1  = (const float*)d_in[4];
    const float* g1  = (const float*)d_in[5];
    const float* be1 = (const float*)d_in[6];
    const float* a1  = (const float*)d_in[7];
    const float* W2  = (const float*)d_in[8];
    const float* b2  = (const float*)d_in[9];
    const float* g2  = (const float*)d_in[10];
    const float* be2 = (const float*)d_in[11];
    const float* a2  = (const float*)d_in[12];
    const float* Wc1 = (const float*)d_in[13];
    const float* bc1 = (const float*)d_in[14];
    const float* Wc2 = (const float*)d_in[15];
    const float* bc2 = (const float*)d_in[16];

    int n = in_sizes[0];        // 100000
    int e = in_sizes[1] / 2;    // 1600000

    k_init<<<(n + 255) / 256, 256>>>(n);
    k_deg<<<(e + 255) / 256, 256>>>(ei, e);
    k_scan<<<1, 1024>>>(n);
    k_fill<<<(e + 255) / 256, 256>>>(ei, e);
    k_node1<<<(n + 255) / 256, 256>>>(x, n);
    k_conv1<<<(n + 255) / 256, 256>>>(n);
    k_start<<<(NG + 1 + 127) / 128, 128>>>(batch, n);
    k_gstats<<<NG, 128>>>();
    k_pq<<<(NG * HID + 255) / 256, 256>>>(W1, b1, g1, be1, a1);
    k_gemm<<<(n + 63) / 64, 256>>>(W2, batch, n);
    k_aggregate<<<(n * 16 + 255) / 256, 256>>>(b2, n);
    k_norm2pool<<<NG, HID>>>(a2, g2, be2);
    k_head<<<NG, 96>>>(Wc1, bc1, Wc2, bc2, (float*)d_out);
}

// round 8
// speedup vs baseline: 1.4913x; 1.2395x over previous
#include <cuda_runtime.h>
#include <cuda_fp16.h>
#include <cstdint>

#define NN   100000
#define NE   1600000
#define NG   512
#define HID  192
#define H4   48      // HID/4
#define EPSN 1e-5f

#define SA_STRIDE 200   // halfs, conflict-free for ldmatrix
#define SB_STRIDE 200

// ---------------- scratch (no allocs allowed) ----------------
__device__ int    g_cnt[NN];
__device__ int    g_off[NN + 1];
__device__ int    g_cur[NN];
__device__ int    g_srcs[NE];
__device__ float  g_dinv[NN];
__device__ float  g_xs[NN];
__device__ float  g_agg[NN];
__device__ int    g_start[NG + 1];
__device__ float  g_gmean[NG];
__device__ float  g_gvar[NG];
__device__ float  g_P[NG * HID];
__device__ float  g_Q[NG * HID];
__device__ __half g_W2h[HID * HID];                 // fp16 copy of W2
__device__ __align__(16) float4  g_ts4[NN * H4];    // dinv*(h1n@W2), fp32
__device__ __align__(16) __half2 g_ts16[NN * 96];   // fp16 gather payload
__device__ __align__(16) float4  g_acc2_4[NN * H4]; // h2pre
__device__ float  g_pooled[NG * HID];

// ---------------- CSR build ----------------
__global__ void k_init(int n) {
    int i = blockIdx.x * blockDim.x + threadIdx.x;
    if (i < n) g_cnt[i] = 0;
}

__global__ void k_deg(const int* __restrict__ ei, int e) {
    int idx = blockIdx.x * blockDim.x + threadIdx.x;
    if (idx < e) atomicAdd(&g_cnt[__ldg(&ei[e + idx])], 1);
}

__global__ __launch_bounds__(1024) void k_scan(int n) {     // single block
    __shared__ int part[1024];
    int tid = threadIdx.x;
    int chunk = (n + 1023) / 1024;
    int s0 = tid * chunk, s1 = min(s0 + chunk, n);
    int s = 0;
    for (int i = s0; i < s1; i++) s += g_cnt[i];
    part[tid] = s;
    __syncthreads();
    for (int off = 1; off < 1024; off <<= 1) {
        int v = part[tid];
        int add = (tid >= off) ? part[tid - off] : 0;
        __syncthreads();
        part[tid] = v + add;
        __syncthreads();
    }
    int run = (tid > 0) ? part[tid - 1] : 0;
    for (int i = s0; i < s1; i++) {
        g_off[i] = run;
        g_cur[i] = run;
        run += g_cnt[i];
    }
    if (tid == 0) g_off[n] = part[1023];
}

__global__ void k_fill(const int* __restrict__ ei, int e) {
    int idx = blockIdx.x * blockDim.x + threadIdx.x;
    if (idx < e) {
        int r = __ldg(&ei[idx]);
        int c = __ldg(&ei[e + idx]);
        int p = atomicAdd(&g_cur[c], 1);
        g_srcs[p] = r;
    }
}

// ---------------- conv1 (scalar, CSR) ----------------
__global__ void k_node1(const float* __restrict__ x, int n) {
    int i = blockIdx.x * blockDim.x + threadIdx.x;
    if (i < n) {
        float v = rsqrtf((float)(g_cnt[i] + 1));
        g_dinv[i] = v;
        g_xs[i]   = x[i] * v;
    }
}

__global__ void k_conv1(int n) {
    int i = blockIdx.x * blockDim.x + threadIdx.x;
    if (i >= n) return;
    int off = g_off[i], end = g_off[i + 1];
    float s = g_xs[i];
    for (int k = off; k < end; k++) s += __ldg(&g_xs[g_srcs[k]]);
    g_agg[i] = g_dinv[i] * s;
}

// ---------------- graph stats for norm1 ----------------
__global__ void k_start(const int* __restrict__ batch, int n) {
    int g = blockIdx.x * blockDim.x + threadIdx.x;
    if (g > NG) return;
    int lo = 0, hi = n;
    while (lo < hi) {
        int mid = (lo + hi) >> 1;
        if (batch[mid] < g) lo = mid + 1; else hi = mid;
    }
    g_start[g] = lo;
}

__global__ void k_gstats() {
    int g = blockIdx.x;
    int s = g_start[g], t = g_start[g + 1];
    int tid = threadIdx.x;
    float sum = 0.f, sq = 0.f;
    for (int i = s + tid; i < t; i += 128) {
        float a = g_agg[i];
        sum += a; sq += a * a;
    }
    __shared__ float ssum[128], ssq[128];
    ssum[tid] = sum; ssq[tid] = sq;
    __syncthreads();
    for (int o = 64; o > 0; o >>= 1) {
        if (tid < o) { ssum[tid] += ssum[tid + o]; ssq[tid] += ssq[tid + o]; }
        __syncthreads();
    }
    if (tid == 0) {
        float cnt = fmaxf((float)(t - s), 1.f);
        float m = ssum[0] / cnt;
        float v = ssq[0] / cnt - m * m;
        g_gmean[g] = m;
        g_gvar[g]  = fmaxf(v, 0.f);
    }
}

__global__ void k_pq(const float* __restrict__ W1, const float* __restrict__ b1,
                     const float* __restrict__ g1, const float* __restrict__ be1,
                     const float* __restrict__ a1) {
    int idx = blockIdx.x * blockDim.x + threadIdx.x;
    if (idx >= NG * HID) return;
    int g = idx / HID, j = idx % HID;
    float w = W1[j], bj = b1[j], aj = a1[j], gj = g1[j], bej = be1[j];
    float m = g_gmean[g], va = g_gvar[g];
    float eo  = (1.f - aj) * (w * m + bj);
    float var = w * w * va + eo * eo;
    float sc  = gj * rsqrtf(var + EPSN);
    g_P[idx] = sc * w;
    g_Q[idx] = sc * (bj * (1.f - aj) - w * aj * m) + bej;
}

// ---------------- W2 -> fp16 ----------------
__global__ void k_w2h(const float* __restrict__ W2) {
    int i = blockIdx.x * blockDim.x + threadIdx.x;
    if (i < HID * HID) g_W2h[i] = __float2half_rn(W2[i]);
}

// ---------------- tensor-core GEMM: ts = dinv * (relu(P*agg+Q) @ W2) --------
// 128-row tile per block, full K=192 and full W2 in smem, 8 warps, HMMA m16n8k16.
__global__ __launch_bounds__(256, 1) void k_gemm_mma(const int* __restrict__ batch, int n) {
    extern __shared__ __half smem[];
    __half* sA = smem;                       // [128][SA_STRIDE]
    __half* sB = smem + 128 * SA_STRIDE;     // [192][SB_STRIDE]

    int tid  = threadIdx.x;
    int row0 = blockIdx.x * 128;

    // load W2 (fp16) into smem
#pragma unroll
    for (int u = 0; u < 144; u++) {
        int idx = u * 256 + tid;             // 36864 elems
        int k = idx / HID, nn2 = idx % HID;
        sB[k * SB_STRIDE + nn2] = g_W2h[idx];
    }

    // generate h1n tile in fp16: 2 threads per row, 96 cols each
    {
        int row  = tid >> 1;
        int half = tid & 1;
        int grow = row0 + row;
        float ag = 0.f; int gb = 0;
        if (grow < n) { ag = g_agg[grow]; gb = __ldg(&batch[grow]); }
        const float* Pg = &g_P[gb * HID];
        const float* Qg = &g_Q[gb * HID];
        __half* dst = &sA[row * SA_STRIDE + half * 96];
#pragma unroll
        for (int c = 0; c < 96; c++) {
            int j = half * 96 + c;
            float v = fmaxf(fmaf(__ldg(&Pg[j]), ag, __ldg(&Qg[j])), 0.f);
            dst[c] = __float2half_rn(v);
        }
    }
    __syncthreads();

    int wid  = tid >> 5;
    int lane = tid & 31;
    int g8 = lane >> 3, r8 = lane & 7;

    float c[24][4];
#pragma unroll
    for (int t = 0; t < 24; t++)
#pragma unroll
        for (int q = 0; q < 4; q++) c[t][q] = 0.f;

    for (int ks = 0; ks < 12; ks++) {
        int k0 = ks * 16;
        // A fragment (16x16 at rows wid*16, cols k0)
        uint32_t a0, a1, a2, a3;
        {
            int arow = wid * 16 + (g8 & 1) * 8 + r8;
            int acol = k0 + (g8 >> 1) * 8;
            uint32_t addr = (uint32_t)__cvta_generic_to_shared(&sA[arow * SA_STRIDE + acol]);
            asm volatile("ldmatrix.sync.aligned.m8n8.x4.shared.b16 {%0,%1,%2,%3}, [%4];"
                         : "=r"(a0), "=r"(a1), "=r"(a2), "=r"(a3) : "r"(addr));
        }
#pragma unroll
        for (int bt = 0; bt < 12; bt++) {
            int n0 = bt * 16;
            uint32_t b0, b1, b2, b3;
            int brow = k0 + (g8 & 1) * 8 + r8;
            int bcol = n0 + (g8 >> 1) * 8;
            uint32_t addr = (uint32_t)__cvta_generic_to_shared(&sB[brow * SB_STRIDE + bcol]);
            asm volatile("ldmatrix.sync.aligned.m8n8.x4.trans.shared.b16 {%0,%1,%2,%3}, [%4];"
                         : "=r"(b0), "=r"(b1), "=r"(b2), "=r"(b3) : "r"(addr));
            float* c0 = c[bt * 2];
            float* c1 = c[bt * 2 + 1];
            asm volatile("mma.sync.aligned.m16n8k16.row.col.f32.f16.f16.f32 "
                         "{%0,%1,%2,%3}, {%4,%5,%6,%7}, {%8,%9}, {%0,%1,%2,%3};"
                         : "+f"(c0[0]), "+f"(c0[1]), "+f"(c0[2]), "+f"(c0[3])
                         : "r"(a0), "r"(a1), "r"(a2), "r"(a3), "r"(b0), "r"(b1));
            asm volatile("mma.sync.aligned.m16n8k16.row.col.f32.f16.f16.f32 "
                         "{%0,%1,%2,%3}, {%4,%5,%6,%7}, {%8,%9}, {%0,%1,%2,%3};"
                         : "+f"(c1[0]), "+f"(c1[1]), "+f"(c1[2]), "+f"(c1[3])
                         : "r"(a0), "r"(a1), "r"(a2), "r"(a3), "r"(b2), "r"(b3));
        }
    }

    // epilogue: scale by dinv, emit fp32 + fp16
    int r0 = row0 + wid * 16 + (lane >> 2);
    int r1 = r0 + 8;
    float dv0 = (r0 < n) ? g_dinv[r0] : 0.f;
    float dv1 = (r1 < n) ? g_dinv[r1] : 0.f;
    float2*  ts2  = (float2*)g_ts4;
#pragma unroll
    for (int t = 0; t < 24; t++) {
        int cc = t * 8 + (lane & 3) * 2;
        int o2 = cc >> 1;
        if (r0 < n) {
            float vx = c[t][0] * dv0, vy = c[t][1] * dv0;
            ts2[(size_t)r0 * 96 + o2]  = make_float2(vx, vy);
            g_ts16[(size_t)r0 * 96 + o2] = __floats2half2_rn(vx, vy);
        }
        if (r1 < n) {
            float vx = c[t][2] * dv1, vy = c[t][3] * dv1;
            ts2[(size_t)r1 * 96 + o2]  = make_float2(vx, vy);
            g_ts16[(size_t)r1 * 96 + o2] = __floats2half2_rn(vx, vy);
        }
    }
}

// ---------------- conv2 aggregate (CSR gather, half-warp per dst) ------------
__device__ __forceinline__ void add_u2(float4& a, uint2 u) {
    __half2 h0 = *reinterpret_cast<__half2*>(&u.x);
    __half2 h1 = *reinterpret_cast<__half2*>(&u.y);
    float2 f0 = __half22float2(h0);
    float2 f1 = __half22float2(h1);
    a.x += f0.x; a.y += f0.y; a.z += f1.x; a.w += f1.y;
}

__global__ __launch_bounds__(256) void k_aggregate(const float* __restrict__ b2, int n) {
    int t = blockIdx.x * blockDim.x + threadIdx.x;
    int node = t >> 4;
    int lane = t & 15;
    if (node >= n) return;

    const float4* base = &g_ts4[(size_t)node * H4];
    float4 a0 = base[lane];
    float4 a1 = base[16 + lane];
    float4 a2 = base[32 + lane];

    const uint2* ts16 = (const uint2*)g_ts16;
    int off = g_off[node], end = g_off[node + 1];
    int s_next = (off < end) ? __ldg(&g_srcs[off]) : 0;
    for (int k = off; k < end; k++) {
        int s = s_next;
        if (k + 1 < end) s_next = __ldg(&g_srcs[k + 1]);
        const uint2* rp = ts16 + (size_t)s * 48 + lane;
        uint2 u0 = __ldg(rp);
        uint2 u1 = __ldg(rp + 16);
        uint2 u2 = __ldg(rp + 32);
        add_u2(a0, u0);
        add_u2(a1, u1);
        add_u2(a2, u2);
    }

    float dv = g_dinv[node];
    const float4* b24 = (const float4*)b2;
    float4 b_0 = __ldg(&b24[lane]);
    float4 b_1 = __ldg(&b24[16 + lane]);
    float4 b_2 = __ldg(&b24[32 + lane]);
    float4 o0, o1, o2;
    o0.x = fmaf(dv, a0.x, b_0.x); o0.y = fmaf(dv, a0.y, b_0.y);
    o0.z = fmaf(dv, a0.z, b_0.z); o0.w = fmaf(dv, a0.w, b_0.w);
    o1.x = fmaf(dv, a1.x, b_1.x); o1.y = fmaf(dv, a1.y, b_1.y);
    o1.z = fmaf(dv, a1.z, b_1.z); o1.w = fmaf(dv, a1.w, b_1.w);
    o2.x = fmaf(dv, a2.x, b_2.x); o2.y = fmaf(dv, a2.y, b_2.y);
    o2.z = fmaf(dv, a2.z, b_2.z); o2.w = fmaf(dv, a2.w, b_2.w);
    float4* out = &g_acc2_4[(size_t)node * H4];
    out[lane]      = o0;
    out[16 + lane] = o1;
    out[32 + lane] = o2;
}

// ---------------- fused graph_norm2 stats + relu + mean-pool ----------------
__global__ void k_norm2pool(const float* __restrict__ a2, const float* __restrict__ g2,
                            const float* __restrict__ be2) {
    int g = blockIdx.x, j = threadIdx.x;      // 192 threads
    int s = g_start[g], t = g_start[g + 1];
    const float* acc2 = (const float*)g_acc2_4;
    float sum = 0.f, sq = 0.f;
    for (int i = s; i < t; i++) {
        float v = __ldg(&acc2[(size_t)i * HID + j]);
        sum += v; sq += v * v;
    }
    float cnt  = fmaxf((float)(t - s), 1.f);
    float mean = sum / cnt;
    float aj   = a2[j];
    float var  = sq / cnt - (2.f * aj - aj * aj) * mean * mean;
    var = fmaxf(var, 0.f);
    float sc  = g2[j] * rsqrtf(var + EPSN);
    float am  = aj * mean;
    float bej = be2[j];
    float p = 0.f;
    for (int i = s; i < t; i++) {
        float v = __ldg(&acc2[(size_t)i * HID + j]);
        float y = fmaf(sc, v - am, bej);
        p += fmaxf(y, 0.f);
    }
    g_pooled[g * HID + j] = p / cnt;
}

// ---------------- classifier head ----------------
__global__ void k_head(const float* __restrict__ Wc1, const float* __restrict__ bc1,
                       const float* __restrict__ Wc2, const float* __restrict__ bc2,
                       float* __restrict__ out) {
    __shared__ float sp[HID];
    __shared__ float sz[96];
    int g = blockIdx.x, t = threadIdx.x;      // 96 threads
    sp[t]      = g_pooled[g * HID + t];
    sp[t + 96] = g_pooled[g * HID + 96 + t];
    __syncthreads();
    float d = bc1[t];
#pragma unroll 8
    for (int k = 0; k < HID; k++) d = fmaf(sp[k], Wc1[k * 96 + t], d);
    sz[t] = fmaxf(d, 0.f);
    __syncthreads();
    if (t < 4) {
        float o = bc2[t];
#pragma unroll 8
        for (int k = 0; k < 96; k++) o = fmaf(sz[k], Wc2[k * 4 + t], o);
        out[g * 4 + t] = o;
    }
}

// ---------------- launch ----------------
extern "C" void kernel_launch(void* const* d_in, const int* in_sizes, int n_in,
                              void* d_out, int out_size) {
    const float* x     = (const float*)d_in[0];
    const int*   ei    = (const int*)d_in[1];
    const int*   batch = (const int*)d_in[2];
    const float* W1  = (const float*)d_in[3];
    const float* b1  = (const float*)d_in[4];
    const float* g1  = (const float*)d_in[5];
    const float* be1 = (const float*)d_in[6];
    const float* a1  = (const float*)d_in[7];
    const float* W2  = (const float*)d_in[8];
    const float* b2  = (const float*)d_in[9];
    const float* g2  = (const float*)d_in[10];
    const float* be2 = (const float*)d_in[11];
    const float* a2  = (const float*)d_in[12];
    const float* Wc1 = (const float*)d_in[13];
    const float* bc1 = (const float*)d_in[14];
    const float* Wc2 = (const float*)d_in[15];
    const float* bc2 = (const float*)d_in[16];

    int n = in_sizes[0];        // 100000
    int e = in_sizes[1] / 2;    // 1600000

    const int SMEM_GEMM = (128 * SA_STRIDE + HID * SB_STRIDE) * 2;  // 128000 B
    cudaFuncSetAttribute(k_gemm_mma, cudaFuncAttributeMaxDynamicSharedMemorySize, SMEM_GEMM);

    k_init<<<(n + 255) / 256, 256>>>(n);
    k_deg<<<(e + 255) / 256, 256>>>(ei, e);
    k_scan<<<1, 1024>>>(n);
    k_fill<<<(e + 255) / 256, 256>>>(ei, e);
    k_node1<<<(n + 255) / 256, 256>>>(x, n);
    k_conv1<<<(n + 255) / 256, 256>>>(n);
    k_start<<<(NG + 1 + 127) / 128, 128>>>(batch, n);
    k_gstats<<<NG, 128>>>();
    k_pq<<<(NG * HID + 255) / 256, 256>>>(W1, b1, g1, be1, a1);
    k_w2h<<<(HID * HID + 255) / 256, 256>>>(W2);
    k_gemm_mma<<<(n + 127) / 128, 256, SMEM_GEMM>>>(batch, n);
    k_aggregate<<<(n * 16 + 255) / 256, 256>>>(b2, n);
    k_norm2pool<<<NG, HID>>>(a2, g2, be2);
    k_head<<<NG, 96>>>(Wc1, bc1, Wc2, bc2, (float*)d_out);
}

// round 9
// speedup vs baseline: 1.5614x; 1.0470x over previous
#include <cuda_runtime.h>
#include <cuda_fp16.h>
#include <cstdint>

#define NN   100000
#define NE   1600000
#define NG   512
#define HID  192
#define H4   48      // HID/4
#define EPSN 1e-5f

#define SA_STRIDE 200   // halfs, conflict-free for ldmatrix
#define SB_STRIDE 200

// ---------------- scratch (no allocs allowed) ----------------
__device__ int    g_cnt[NN];
__device__ int    g_off[NN + 1];
__device__ int    g_cur[NN];
__device__ int    g_srcs[NE];
__device__ float  g_dinv[NN];
__device__ float  g_xs[NN];
__device__ float  g_agg[NN];
__device__ int    g_start[NG + 1];
__device__ float  g_gmean[NG];
__device__ float  g_gvar[NG];
__device__ float  g_P[NG * HID];
__device__ float  g_Q[NG * HID];
__device__ __half g_W2h[HID * HID];                 // fp16 copy of W2
__device__ __align__(16) float4  g_ts4[NN * H4];    // dinv*(h1n@W2), fp32
__device__ __align__(16) __half2 g_ts16[NN * 96];   // fp16 gather payload
__device__ __align__(16) float4  g_acc2_4[NN * H4]; // h2pre
__device__ float  g_pooled[NG * HID];

// ---------------- CSR build ----------------
__global__ void k_init(int n) {
    int i = blockIdx.x * blockDim.x + threadIdx.x;
    if (i < n) g_cnt[i] = 0;
}

__global__ void k_deg(const int* __restrict__ ei, int e) {
    int idx = (blockIdx.x * blockDim.x + threadIdx.x) * 2;
    if (idx + 1 < e) {
        int2 c2 = *(const int2*)&ei[e + idx];
        atomicAdd(&g_cnt[c2.x], 1);
        atomicAdd(&g_cnt[c2.y], 1);
    } else if (idx < e) {
        atomicAdd(&g_cnt[__ldg(&ei[e + idx])], 1);
    }
}

__global__ __launch_bounds__(1024) void k_scan(int n) {     // single block
    __shared__ int part[1024];
    int tid = threadIdx.x;
    int chunk = (n + 1023) / 1024;
    int s0 = tid * chunk, s1 = min(s0 + chunk, n);
    int s = 0;
    for (int i = s0; i < s1; i++) s += g_cnt[i];
    part[tid] = s;
    __syncthreads();
    for (int off = 1; off < 1024; off <<= 1) {
        int v = part[tid];
        int add = (tid >= off) ? part[tid - off] : 0;
        __syncthreads();
        part[tid] = v + add;
        __syncthreads();
    }
    int run = (tid > 0) ? part[tid - 1] : 0;
    for (int i = s0; i < s1; i++) {
        g_off[i] = run;
        g_cur[i] = run;
        run += g_cnt[i];
    }
    if (tid == 0) g_off[n] = part[1023];
}

__global__ void k_fill(const int* __restrict__ ei, int e) {
    int idx = (blockIdx.x * blockDim.x + threadIdx.x) * 2;
    if (idx + 1 < e) {
        int2 r2 = *(const int2*)&ei[idx];
        int2 c2 = *(const int2*)&ei[e + idx];
        int p0 = atomicAdd(&g_cur[c2.x], 1);
        int p1 = atomicAdd(&g_cur[c2.y], 1);
        g_srcs[p0] = r2.x;
        g_srcs[p1] = r2.y;
    } else if (idx < e) {
        int r = __ldg(&ei[idx]);
        int c = __ldg(&ei[e + idx]);
        int p = atomicAdd(&g_cur[c], 1);
        g_srcs[p] = r;
    }
}

// ---------------- conv1 (scalar, CSR) ----------------
__global__ void k_node1(const float* __restrict__ x, int n) {
    int i = blockIdx.x * blockDim.x + threadIdx.x;
    if (i < n) {
        float v = rsqrtf((float)(g_cnt[i] + 1));
        g_dinv[i] = v;
        g_xs[i]   = x[i] * v;
    }
}

__global__ void k_conv1(int n) {
    int i = blockIdx.x * blockDim.x + threadIdx.x;
    if (i >= n) return;
    int off = g_off[i], end = g_off[i + 1];
    float s = g_xs[i];
    for (int k = off; k < end; k++) s += __ldg(&g_xs[g_srcs[k]]);
    g_agg[i] = g_dinv[i] * s;
}

// ---------------- graph stats for norm1 ----------------
__global__ void k_start(const int* __restrict__ batch, int n) {
    int g = blockIdx.x * blockDim.x + threadIdx.x;
    if (g > NG) return;
    int lo = 0, hi = n;
    while (lo < hi) {
        int mid = (lo + hi) >> 1;
        if (batch[mid] < g) lo = mid + 1; else hi = mid;
    }
    g_start[g] = lo;
}

__global__ void k_gstats() {
    int g = blockIdx.x;
    int s = g_start[g], t = g_start[g + 1];
    int tid = threadIdx.x;
    float sum = 0.f, sq = 0.f;
    for (int i = s + tid; i < t; i += 128) {
        float a = g_agg[i];
        sum += a; sq += a * a;
    }
    __shared__ float ssum[128], ssq[128];
    ssum[tid] = sum; ssq[tid] = sq;
    __syncthreads();
    for (int o = 64; o > 0; o >>= 1) {
        if (tid < o) { ssum[tid] += ssum[tid + o]; ssq[tid] += ssq[tid + o]; }
        __syncthreads();
    }
    if (tid == 0) {
        float cnt = fmaxf((float)(t - s), 1.f);
        float m = ssum[0] / cnt;
        float v = ssq[0] / cnt - m * m;
        g_gmean[g] = m;
        g_gvar[g]  = fmaxf(v, 0.f);
    }
}

__global__ void k_pq(const float* __restrict__ W1, const float* __restrict__ b1,
                     const float* __restrict__ g1, const float* __restrict__ be1,
                     const float* __restrict__ a1) {
    int idx = blockIdx.x * blockDim.x + threadIdx.x;
    if (idx >= NG * HID) return;
    int g = idx / HID, j = idx % HID;
    float w = W1[j], bj = b1[j], aj = a1[j], gj = g1[j], bej = be1[j];
    float m = g_gmean[g], va = g_gvar[g];
    float eo  = (1.f - aj) * (w * m + bj);
    float var = w * w * va + eo * eo;
    float sc  = gj * rsqrtf(var + EPSN);
    g_P[idx] = sc * w;
    g_Q[idx] = sc * (bj * (1.f - aj) - w * aj * m) + bej;
}

// ---------------- W2 -> fp16 ----------------
__global__ void k_w2h(const float* __restrict__ W2) {
    int i = blockIdx.x * blockDim.x + threadIdx.x;
    if (i < HID * HID) g_W2h[i] = __float2half_rn(W2[i]);
}

// ---------------- tensor-core GEMM: ts = dinv * (relu(P*agg+Q) @ W2) --------
__global__ __launch_bounds__(256, 1) void k_gemm_mma(const int* __restrict__ batch, int n) {
    extern __shared__ __half smem[];
    __half* sA = smem;                       // [128][SA_STRIDE]
    __half* sB = smem + 128 * SA_STRIDE;     // [192][SB_STRIDE]

    int tid  = threadIdx.x;
    int row0 = blockIdx.x * 128;

    // load W2 (fp16) into smem
#pragma unroll
    for (int u = 0; u < 144; u++) {
        int idx = u * 256 + tid;             // 36864 elems
        int k = idx / HID, nn2 = idx % HID;
        sB[k * SB_STRIDE + nn2] = g_W2h[idx];
    }

    // generate h1n tile in fp16: 2 threads per row, 96 cols each
    {
        int row  = tid >> 1;
        int half = tid & 1;
        int grow = row0 + row;
        float ag = 0.f; int gb = 0;
        if (grow < n) { ag = g_agg[grow]; gb = __ldg(&batch[grow]); }
        const float* Pg = &g_P[gb * HID];
        const float* Qg = &g_Q[gb * HID];
        __half* dst = &sA[row * SA_STRIDE + half * 96];
#pragma unroll
        for (int c = 0; c < 96; c++) {
            int j = half * 96 + c;
            float v = fmaxf(fmaf(__ldg(&Pg[j]), ag, __ldg(&Qg[j])), 0.f);
            dst[c] = __float2half_rn(v);
        }
    }
    __syncthreads();

    int wid  = tid >> 5;
    int lane = tid & 31;
    int g8 = lane >> 3, r8 = lane & 7;

    float c[24][4];
#pragma unroll
    for (int t = 0; t < 24; t++)
#pragma unroll
        for (int q = 0; q < 4; q++) c[t][q] = 0.f;

    for (int ks = 0; ks < 12; ks++) {
        int k0 = ks * 16;
        uint32_t a0, a1, a2, a3;
        {
            int arow = wid * 16 + (g8 & 1) * 8 + r8;
            int acol = k0 + (g8 >> 1) * 8;
            uint32_t addr = (uint32_t)__cvta_generic_to_shared(&sA[arow * SA_STRIDE + acol]);
            asm volatile("ldmatrix.sync.aligned.m8n8.x4.shared.b16 {%0,%1,%2,%3}, [%4];"
                         : "=r"(a0), "=r"(a1), "=r"(a2), "=r"(a3) : "r"(addr));
        }
#pragma unroll
        for (int bt = 0; bt < 12; bt++) {
            int n0 = bt * 16;
            uint32_t b0, b1, b2, b3;
            int brow = k0 + (g8 & 1) * 8 + r8;
            int bcol = n0 + (g8 >> 1) * 8;
            uint32_t addr = (uint32_t)__cvta_generic_to_shared(&sB[brow * SB_STRIDE + bcol]);
            asm volatile("ldmatrix.sync.aligned.m8n8.x4.trans.shared.b16 {%0,%1,%2,%3}, [%4];"
                         : "=r"(b0), "=r"(b1), "=r"(b2), "=r"(b3) : "r"(addr));
            float* c0 = c[bt * 2];
            float* c1 = c[bt * 2 + 1];
            asm volatile("mma.sync.aligned.m16n8k16.row.col.f32.f16.f16.f32 "
                         "{%0,%1,%2,%3}, {%4,%5,%6,%7}, {%8,%9}, {%0,%1,%2,%3};"
                         : "+f"(c0[0]), "+f"(c0[1]), "+f"(c0[2]), "+f"(c0[3])
                         : "r"(a0), "r"(a1), "r"(a2), "r"(a3), "r"(b0), "r"(b1));
            asm volatile("mma.sync.aligned.m16n8k16.row.col.f32.f16.f16.f32 "
                         "{%0,%1,%2,%3}, {%4,%5,%6,%7}, {%8,%9}, {%0,%1,%2,%3};"
                         : "+f"(c1[0]), "+f"(c1[1]), "+f"(c1[2]), "+f"(c1[3])
                         : "r"(a0), "r"(a1), "r"(a2), "r"(a3), "r"(b2), "r"(b3));
        }
    }

    // epilogue
    int r0 = row0 + wid * 16 + (lane >> 2);
    int r1 = r0 + 8;
    float dv0 = (r0 < n) ? g_dinv[r0] : 0.f;
    float dv1 = (r1 < n) ? g_dinv[r1] : 0.f;
    float2* ts2 = (float2*)g_ts4;
#pragma unroll
    for (int t = 0; t < 24; t++) {
        int cc = t * 8 + (lane & 3) * 2;
        int o2 = cc >> 1;
        if (r0 < n) {
            float vx = c[t][0] * dv0, vy = c[t][1] * dv0;
            ts2[(size_t)r0 * 96 + o2]  = make_float2(vx, vy);
            g_ts16[(size_t)r0 * 96 + o2] = __floats2half2_rn(vx, vy);
        }
        if (r1 < n) {
            float vx = c[t][2] * dv1, vy = c[t][3] * dv1;
            ts2[(size_t)r1 * 96 + o2]  = make_float2(vx, vy);
            g_ts16[(size_t)r1 * 96 + o2] = __floats2half2_rn(vx, vy);
        }
    }
}

// ---------------- conv2 aggregate (CSR gather, half-warp per dst) ------------
// unroll-by-4 neighbor batching: 12 payload loads in flight per lane
__device__ __forceinline__ void add_u2(float4& a, uint2 u) {
    __half2 h0 = *reinterpret_cast<__half2*>(&u.x);
    __half2 h1 = *reinterpret_cast<__half2*>(&u.y);
    float2 f0 = __half22float2(h0);
    float2 f1 = __half22float2(h1);
    a.x += f0.x; a.y += f0.y; a.z += f1.x; a.w += f1.y;
}

__global__ __launch_bounds__(256) void k_aggregate(const float* __restrict__ b2, int n) {
    int t = blockIdx.x * blockDim.x + threadIdx.x;
    int node = t >> 4;
    int lane = t & 15;
    if (node >= n) return;

    const float4* base = &g_ts4[(size_t)node * H4];
    float4 a0 = base[lane];
    float4 a1 = base[16 + lane];
    float4 a2 = base[32 + lane];

    const uint2* ts16 = (const uint2*)g_ts16;
    int off = g_off[node], end = g_off[node + 1];

    int k = off;
    for (; k + 4 <= end; k += 4) {
        int s0 = __ldg(&g_srcs[k]);
        int s1 = __ldg(&g_srcs[k + 1]);
        int s2 = __ldg(&g_srcs[k + 2]);
        int s3 = __ldg(&g_srcs[k + 3]);
        const uint2* p0 = ts16 + (size_t)s0 * 48 + lane;
        const uint2* p1 = ts16 + (size_t)s1 * 48 + lane;
        const uint2* p2 = ts16 + (size_t)s2 * 48 + lane;
        const uint2* p3 = ts16 + (size_t)s3 * 48 + lane;
        uint2 u00 = __ldg(p0),      u01 = __ldg(p0 + 16), u02 = __ldg(p0 + 32);
        uint2 u10 = __ldg(p1),      u11 = __ldg(p1 + 16), u12 = __ldg(p1 + 32);
        uint2 u20 = __ldg(p2),      u21 = __ldg(p2 + 16), u22 = __ldg(p2 + 32);
        uint2 u30 = __ldg(p3),      u31 = __ldg(p3 + 16), u32 = __ldg(p3 + 32);
        add_u2(a0, u00); add_u2(a1, u01); add_u2(a2, u02);
        add_u2(a0, u10); add_u2(a1, u11); add_u2(a2, u12);
        add_u2(a0, u20); add_u2(a1, u21); add_u2(a2, u22);
        add_u2(a0, u30); add_u2(a1, u31); add_u2(a2, u32);
    }
    for (; k < end; k++) {
        int s = __ldg(&g_srcs[k]);
        const uint2* rp = ts16 + (size_t)s * 48 + lane;
        uint2 u0 = __ldg(rp);
        uint2 u1 = __ldg(rp + 16);
        uint2 u2 = __ldg(rp + 32);
        add_u2(a0, u0);
        add_u2(a1, u1);
        add_u2(a2, u2);
    }

    float dv = g_dinv[node];
    const float4* b24 = (const float4*)b2;
    float4 b_0 = __ldg(&b24[lane]);
    float4 b_1 = __ldg(&b24[16 + lane]);
    float4 b_2 = __ldg(&b24[32 + lane]);
    float4 o0, o1, o2;
    o0.x = fmaf(dv, a0.x, b_0.x); o0.y = fmaf(dv, a0.y, b_0.y);
    o0.z = fmaf(dv, a0.z, b_0.z); o0.w = fmaf(dv, a0.w, b_0.w);
    o1.x = fmaf(dv, a1.x, b_1.x); o1.y = fmaf(dv, a1.y, b_1.y);
    o1.z = fmaf(dv, a1.z, b_1.z); o1.w = fmaf(dv, a1.w, b_1.w);
    o2.x = fmaf(dv, a2.x, b_2.x); o2.y = fmaf(dv, a2.y, b_2.y);
    o2.z = fmaf(dv, a2.z, b_2.z); o2.w = fmaf(dv, a2.w, b_2.w);
    float4* out = &g_acc2_4[(size_t)node * H4];
    out[lane]      = o0;
    out[16 + lane] = o1;
    out[32 + lane] = o2;
}

// ---------------- fused graph_norm2 stats + relu + mean-pool ----------------
__global__ void k_norm2pool(const float* __restrict__ a2, const float* __restrict__ g2,
                            const float* __restrict__ be2) {
    int g = blockIdx.x, j = threadIdx.x;      // 192 threads
    int s = g_start[g], t = g_start[g + 1];
    const float* acc2 = (const float*)g_acc2_4;
    float sum = 0.f, sq = 0.f;
    for (int i = s; i < t; i++) {
        float v = __ldg(&acc2[(size_t)i * HID + j]);
        sum += v; sq += v * v;
    }
    float cnt  = fmaxf((float)(t - s), 1.f);
    float mean = sum / cnt;
    float aj   = a2[j];
    float var  = sq / cnt - (2.f * aj - aj * aj) * mean * mean;
    var = fmaxf(var, 0.f);
    float sc  = g2[j] * rsqrtf(var + EPSN);
    float am  = aj * mean;
    float bej = be2[j];
    float p = 0.f;
    for (int i = s; i < t; i++) {
        float v = __ldg(&acc2[(size_t)i * HID + j]);
        float y = fmaf(sc, v - am, bej);
        p += fmaxf(y, 0.f);
    }
    g_pooled[g * HID + j] = p / cnt;
}

// ---------------- classifier head ----------------
__global__ void k_head(const float* __restrict__ Wc1, const float* __restrict__ bc1,
                       const float* __restrict__ Wc2, const float* __restrict__ bc2,
                       float* __restrict__ out) {
    __shared__ float sp[HID];
    __shared__ float sz[96];
    int g = blockIdx.x, t = threadIdx.x;      // 96 threads
    sp[t]      = g_pooled[g * HID + t];
    sp[t + 96] = g_pooled[g * HID + 96 + t];
    __syncthreads();
    float d = bc1[t];
#pragma unroll 8
    for (int k = 0; k < HID; k++) d = fmaf(sp[k], Wc1[k * 96 + t], d);
    sz[t] = fmaxf(d, 0.f);
    __syncthreads();
    if (t < 4) {
        float o = bc2[t];
#pragma unroll 8
        for (int k = 0; k < 96; k++) o = fmaf(sz[k], Wc2[k * 4 + t], o);
        out[g * 4 + t] = o;
    }
}

// ---------------- launch ----------------
extern "C" void kernel_launch(void* const* d_in, const int* in_sizes, int n_in,
                              void* d_out, int out_size) {
    const float* x     = (const float*)d_in[0];
    const int*   ei    = (const int*)d_in[1];
    const int*   batch = (const int*)d_in[2];
    const float* W1  = (const float*)d_in[3];
    const float* b1  = (const float*)d_in[4];
    const float* g1  = (const float*)d_in[5];
    const float* be1 = (const float*)d_in[6];
    const float* a1  = (const float*)d_in[7];
    const float* W2  = (const float*)d_in[8];
    const float* b2  = (const float*)d_in[9];
    const float* g2  = (const float*)d_in[10];
    const float* be2 = (const float*)d_in[11];
    const float* a2  = (const float*)d_in[12];
    const float* Wc1 = (const float*)d_in[13];
    const float* bc1 = (const float*)d_in[14];
    const float* Wc2 = (const float*)d_in[15];
    const float* bc2 = (const float*)d_in[16];

    int n = in_sizes[0];        // 100000
    int e = in_sizes[1] / 2;    // 1600000

    const int SMEM_GEMM = (128 * SA_STRIDE + HID * SB_STRIDE) * 2;  // 128000 B
    cudaFuncSetAttribute(k_gemm_mma, cudaFuncAttributeMaxDynamicSharedMemorySize, SMEM_GEMM);

    k_init<<<(n + 255) / 256, 256>>>(n);
    k_deg<<<(e / 2 + 255) / 256, 256>>>(ei, e);
    k_scan<<<1, 1024>>>(n);
    k_fill<<<(e / 2 + 255) / 256, 256>>>(ei, e);
    k_node1<<<(n + 255) / 256, 256>>>(x, n);
    k_conv1<<<(n + 255) / 256, 256>>>(n);
    k_start<<<(NG + 1 + 127) / 128, 128>>>(batch, n);
    k_gstats<<<NG, 128>>>();
    k_pq<<<(NG * HID + 255) / 256, 256>>>(W1, b1, g1, be1, a1);
    k_w2h<<<(HID * HID + 255) / 256, 256>>>(W2);
    k_gemm_mma<<<(n + 127) / 128, 256, SMEM_GEMM>>>(batch, n);
    k_aggregate<<<(n * 16 + 255) / 256, 256>>>(b2, n);
    k_norm2pool<<<NG, HID>>>(a2, g2, be2);
    k_head<<<NG, 96>>>(Wc1, bc1, Wc2, bc2, (float*)d_out);
}

// round 10
// speedup vs baseline: 2.2690x; 1.4531x over previous
#include <cuda_runtime.h>
#include <cuda_fp16.h>
#include <cstdint>

#define NN   100000
#define NE   1600000
#define NG   512
#define HID  192
#define H4   48      // HID/4
#define EPSN 1e-5f

#define SA_STRIDE 200   // halfs, conflict-free for ldmatrix
#define SB_STRIDE 200

// ---------------- scratch (no allocs allowed) ----------------
__device__ int    g_cnt[NN];
__device__ int    g_off[NN + 1];
__device__ int    g_cur[NN];
__device__ int    g_srcs[NE];
__device__ int    g_bsum[1024];
__device__ int    g_bpre[1024];
__device__ float  g_dinv[NN];
__device__ float  g_xs[NN];
__device__ float  g_agg[NN];
__device__ int    g_start[NG + 1];
__device__ float  g_gmean[NG];
__device__ float  g_gvar[NG];
__device__ float  g_P[NG * HID];
__device__ float  g_Q[NG * HID];
__device__ __half g_W2h[HID * HID];                 // fp16 copy of W2
__device__ __align__(16) float4  g_ts4[NN * H4];    // dinv*(h1n@W2), fp32
__device__ __align__(16) __half2 g_ts16[NN * 96];   // fp16 gather payload
__device__ __align__(16) float4  g_acc2_4[NN * H4]; // h2pre
__device__ float  g_pooled[NG * HID];

// ---------------- CSR build ----------------
__global__ void k_init(int n) {
    int i = blockIdx.x * blockDim.x + threadIdx.x;
    if (i < n) g_cnt[i] = 0;
}

__global__ void k_deg(const int* __restrict__ ei, int e) {
    int idx = (blockIdx.x * blockDim.x + threadIdx.x) * 2;
    if (idx + 1 < e) {
        int2 c2 = *(const int2*)&ei[e + idx];
        atomicAdd(&g_cnt[c2.x], 1);
        atomicAdd(&g_cnt[c2.y], 1);
    } else if (idx < e) {
        atomicAdd(&g_cnt[__ldg(&ei[e + idx])], 1);
    }
}

// 3-phase coalesced exclusive scan of g_cnt -> g_off (+ g_cur copy)
__global__ void k_scan1(int n) {                    // grid = ceil(n/256)
    __shared__ int sh[256];
    int b = blockIdx.x, tid = threadIdx.x;
    int i = b * 256 + tid;
    int v = (i < n) ? g_cnt[i] : 0;
    sh[tid] = v;
    __syncthreads();
    for (int o = 1; o < 256; o <<= 1) {
        int x = sh[tid];
        int y = (tid >= o) ? sh[tid - o] : 0;
        __syncthreads();
        sh[tid] = x + y;
        __syncthreads();
    }
    if (i < n) g_off[i] = sh[tid] - v;              // intra-block exclusive
    if (tid == 255) g_bsum[b] = sh[255];
}

__global__ __launch_bounds__(1024) void k_scan2(int nb, int n) {  // single block
    __shared__ int sh[1024];
    int tid = threadIdx.x;
    int v = (tid < nb) ? g_bsum[tid] : 0;
    sh[tid] = v;
    __syncthreads();
    for (int o = 1; o < 1024; o <<= 1) {
        int x = sh[tid];
        int y = (tid >= o) ? sh[tid - o] : 0;
        __syncthreads();
        sh[tid] = x + y;
        __syncthreads();
    }
    if (tid < nb) g_bpre[tid] = sh[tid] - v;
    if (tid == 1023) g_off[n] = sh[1023];
}

__global__ void k_scan3(int n) {
    int i = blockIdx.x * blockDim.x + threadIdx.x;
    if (i < n) {
        int o = g_off[i] + g_bpre[i >> 8];
        g_off[i] = o;
        g_cur[i] = o;
    }
}

__global__ void k_fill(const int* __restrict__ ei, int e) {
    int idx = (blockIdx.x * blockDim.x + threadIdx.x) * 2;
    if (idx + 1 < e) {
        int2 r2 = *(const int2*)&ei[idx];
        int2 c2 = *(const int2*)&ei[e + idx];
        int p0 = atomicAdd(&g_cur[c2.x], 1);
        int p1 = atomicAdd(&g_cur[c2.y], 1);
        g_srcs[p0] = r2.x;
        g_srcs[p1] = r2.y;
    } else if (idx < e) {
        int r = __ldg(&ei[idx]);
        int c = __ldg(&ei[e + idx]);
        int p = atomicAdd(&g_cur[c], 1);
        g_srcs[p] = r;
    }
}

// ---------------- conv1 (scalar, CSR) ----------------
__global__ void k_node1(const float* __restrict__ x, int n) {
    int i = blockIdx.x * blockDim.x + threadIdx.x;
    if (i < n) {
        float v = rsqrtf((float)(g_cnt[i] + 1));
        g_dinv[i] = v;
        g_xs[i]   = x[i] * v;
    }
}

__global__ void k_conv1(int n) {
    int i = blockIdx.x * blockDim.x + threadIdx.x;
    if (i >= n) return;
    int off = g_off[i], end = g_off[i + 1];
    float s = g_xs[i];
    int k = off;
    for (; k + 4 <= end; k += 4) {
        int s0 = __ldg(&g_srcs[k]);
        int s1 = __ldg(&g_srcs[k + 1]);
        int s2 = __ldg(&g_srcs[k + 2]);
        int s3 = __ldg(&g_srcs[k + 3]);
        float x0 = __ldg(&g_xs[s0]);
        float x1 = __ldg(&g_xs[s1]);
        float x2 = __ldg(&g_xs[s2]);
        float x3 = __ldg(&g_xs[s3]);
        s += (x0 + x1) + (x2 + x3);
    }
    for (; k < end; k++) s += __ldg(&g_xs[__ldg(&g_srcs[k])]);
    g_agg[i] = g_dinv[i] * s;
}

// ---------------- graph stats for norm1 ----------------
__global__ void k_start(const int* __restrict__ batch, int n) {
    int g = blockIdx.x * blockDim.x + threadIdx.x;
    if (g > NG) return;
    int lo = 0, hi = n;
    while (lo < hi) {
        int mid = (lo + hi) >> 1;
        if (batch[mid] < g) lo = mid + 1; else hi = mid;
    }
    g_start[g] = lo;
}

__global__ void k_gstats() {
    int g = blockIdx.x;
    int s = g_start[g], t = g_start[g + 1];
    int tid = threadIdx.x;
    float sum = 0.f, sq = 0.f;
    for (int i = s + tid; i < t; i += 128) {
        float a = g_agg[i];
        sum += a; sq += a * a;
    }
    __shared__ float ssum[128], ssq[128];
    ssum[tid] = sum; ssq[tid] = sq;
    __syncthreads();
    for (int o = 64; o > 0; o >>= 1) {
        if (tid < o) { ssum[tid] += ssum[tid + o]; ssq[tid] += ssq[tid + o]; }
        __syncthreads();
    }
    if (tid == 0) {
        float cnt = fmaxf((float)(t - s), 1.f);
        float m = ssum[0] / cnt;
        float v = ssq[0] / cnt - m * m;
        g_gmean[g] = m;
        g_gvar[g]  = fmaxf(v, 0.f);
    }
}

__global__ void k_pq(const float* __restrict__ W1, const float* __restrict__ b1,
                     const float* __restrict__ g1, const float* __restrict__ be1,
                     const float* __restrict__ a1) {
    int idx = blockIdx.x * blockDim.x + threadIdx.x;
    if (idx >= NG * HID) return;
    int g = idx / HID, j = idx % HID;
    float w = W1[j], bj = b1[j], aj = a1[j], gj = g1[j], bej = be1[j];
    float m = g_gmean[g], va = g_gvar[g];
    float eo  = (1.f - aj) * (w * m + bj);
    float var = w * w * va + eo * eo;
    float sc  = gj * rsqrtf(var + EPSN);
    g_P[idx] = sc * w;
    g_Q[idx] = sc * (bj * (1.f - aj) - w * aj * m) + bej;
}

// ---------------- W2 -> fp16 ----------------
__global__ void k_w2h(const float* __restrict__ W2) {
    int i = blockIdx.x * blockDim.x + threadIdx.x;
    if (i < HID * HID) g_W2h[i] = __float2half_rn(W2[i]);
}

// ---------------- tensor-core GEMM: ts = dinv * (relu(P*agg+Q) @ W2) --------
__global__ __launch_bounds__(256, 1) void k_gemm_mma(const int* __restrict__ batch, int n) {
    extern __shared__ __half smem[];
    __half* sA = smem;                       // [128][SA_STRIDE]
    __half* sB = smem + 128 * SA_STRIDE;     // [192][SB_STRIDE]

    int tid  = threadIdx.x;
    int row0 = blockIdx.x * 128;

#pragma unroll
    for (int u = 0; u < 144; u++) {
        int idx = u * 256 + tid;             // 36864 elems
        int k = idx / HID, nn2 = idx % HID;
        sB[k * SB_STRIDE + nn2] = g_W2h[idx];
    }

    {
        int row  = tid >> 1;
        int half = tid & 1;
        int grow = row0 + row;
        float ag = 0.f; int gb = 0;
        if (grow < n) { ag = g_agg[grow]; gb = __ldg(&batch[grow]); }
        const float* Pg = &g_P[gb * HID];
        const float* Qg = &g_Q[gb * HID];
        __half* dst = &sA[row * SA_STRIDE + half * 96];
#pragma unroll
        for (int c = 0; c < 96; c++) {
            int j = half * 96 + c;
            float v = fmaxf(fmaf(__ldg(&Pg[j]), ag, __ldg(&Qg[j])), 0.f);
            dst[c] = __float2half_rn(v);
        }
    }
    __syncthreads();

    int wid  = tid >> 5;
    int lane = tid & 31;
    int g8 = lane >> 3, r8 = lane & 7;

    float c[24][4];
#pragma unroll
    for (int t = 0; t < 24; t++)
#pragma unroll
        for (int q = 0; q < 4; q++) c[t][q] = 0.f;

    for (int ks = 0; ks < 12; ks++) {
        int k0 = ks * 16;
        uint32_t a0, a1, a2, a3;
        {
            int arow = wid * 16 + (g8 & 1) * 8 + r8;
            int acol = k0 + (g8 >> 1) * 8;
            uint32_t addr = (uint32_t)__cvta_generic_to_shared(&sA[arow * SA_STRIDE + acol]);
            asm volatile("ldmatrix.sync.aligned.m8n8.x4.shared.b16 {%0,%1,%2,%3}, [%4];"
                         : "=r"(a0), "=r"(a1), "=r"(a2), "=r"(a3) : "r"(addr));
        }
#pragma unroll
        for (int bt = 0; bt < 12; bt++) {
            int n0 = bt * 16;
            uint32_t b0, b1, b2, b3;
            int brow = k0 + (g8 & 1) * 8 + r8;
            int bcol = n0 + (g8 >> 1) * 8;
            uint32_t addr = (uint32_t)__cvta_generic_to_shared(&sB[brow * SB_STRIDE + bcol]);
            asm volatile("ldmatrix.sync.aligned.m8n8.x4.trans.shared.b16 {%0,%1,%2,%3}, [%4];"
                         : "=r"(b0), "=r"(b1), "=r"(b2), "=r"(b3) : "r"(addr));
            float* c0 = c[bt * 2];
            float* c1 = c[bt * 2 + 1];
            asm volatile("mma.sync.aligned.m16n8k16.row.col.f32.f16.f16.f32 "
                         "{%0,%1,%2,%3}, {%4,%5,%6,%7}, {%8,%9}, {%0,%1,%2,%3};"
                         : "+f"(c0[0]), "+f"(c0[1]), "+f"(c0[2]), "+f"(c0[3])
                         : "r"(a0), "r"(a1), "r"(a2), "r"(a3), "r"(b0), "r"(b1));
            asm volatile("mma.sync.aligned.m16n8k16.row.col.f32.f16.f16.f32 "
                         "{%0,%1,%2,%3}, {%4,%5,%6,%7}, {%8,%9}, {%0,%1,%2,%3};"
                         : "+f"(c1[0]), "+f"(c1[1]), "+f"(c1[2]), "+f"(c1[3])
                         : "r"(a0), "r"(a1), "r"(a2), "r"(a3), "r"(b2), "r"(b3));
        }
    }

    int r0 = row0 + wid * 16 + (lane >> 2);
    int r1 = r0 + 8;
    float dv0 = (r0 < n) ? g_dinv[r0] : 0.f;
    float dv1 = (r1 < n) ? g_dinv[r1] : 0.f;
    float2* ts2 = (float2*)g_ts4;
#pragma unroll
    for (int t = 0; t < 24; t++) {
        int cc = t * 8 + (lane & 3) * 2;
        int o2 = cc >> 1;
        if (r0 < n) {
            float vx = c[t][0] * dv0, vy = c[t][1] * dv0;
            ts2[(size_t)r0 * 96 + o2]  = make_float2(vx, vy);
            g_ts16[(size_t)r0 * 96 + o2] = __floats2half2_rn(vx, vy);
        }
        if (r1 < n) {
            float vx = c[t][2] * dv1, vy = c[t][3] * dv1;
            ts2[(size_t)r1 * 96 + o2]  = make_float2(vx, vy);
            g_ts16[(size_t)r1 * 96 + o2] = __floats2half2_rn(vx, vy);
        }
    }
}

// ---------------- conv2 aggregate (warp per dst, even/odd split) -------------
__device__ __forceinline__ void add_u2(float4& a, uint2 u) {
    __half2 h0 = *reinterpret_cast<__half2*>(&u.x);
    __half2 h1 = *reinterpret_cast<__half2*>(&u.y);
    float2 f0 = __half22float2(h0);
    float2 f1 = __half22float2(h1);
    a.x += f0.x; a.y += f0.y; a.z += f1.x; a.w += f1.y;
}

__global__ __launch_bounds__(256) void k_aggregate(const float* __restrict__ b2, int n) {
    int t = blockIdx.x * blockDim.x + threadIdx.x;
    int node  = t >> 5;
    int lane  = t & 31;
    int hlane = lane & 15;
    int half  = lane >> 4;
    if (node >= n) return;

    float4 a0 = make_float4(0.f, 0.f, 0.f, 0.f);
    float4 a1 = a0, a2 = a0;
    if (half == 0) {
        const float4* base = &g_ts4[(size_t)node * H4];
        a0 = base[hlane];
        a1 = base[16 + hlane];
        a2 = base[32 + hlane];
    }

    const uint2* ts16 = (const uint2*)g_ts16;
    int off = g_off[node], end = g_off[node + 1];

    int k = off + half;                      // this half: every other neighbor
    for (; k + 6 < end; k += 8) {            // 4 neighbors per iteration
        int s0 = __ldg(&g_srcs[k]);
        int s1 = __ldg(&g_srcs[k + 2]);
        int s2 = __ldg(&g_srcs[k + 4]);
        int s3 = __ldg(&g_srcs[k + 6]);
        const uint2* p0 = ts16 + (size_t)s0 * 48 + hlane;
        const uint2* p1 = ts16 + (size_t)s1 * 48 + hlane;
        const uint2* p2 = ts16 + (size_t)s2 * 48 + hlane;
        const uint2* p3 = ts16 + (size_t)s3 * 48 + hlane;
        uint2 u00 = __ldg(p0), u01 = __ldg(p0 + 16), u02 = __ldg(p0 + 32);
        uint2 u10 = __ldg(p1), u11 = __ldg(p1 + 16), u12 = __ldg(p1 + 32);
        uint2 u20 = __ldg(p2), u21 = __ldg(p2 + 16), u22 = __ldg(p2 + 32);
        uint2 u30 = __ldg(p3), u31 = __ldg(p3 + 16), u32 = __ldg(p3 + 32);
        add_u2(a0, u00); add_u2(a1, u01); add_u2(a2, u02);
        add_u2(a0, u10); add_u2(a1, u11); add_u2(a2, u12);
        add_u2(a0, u20); add_u2(a1, u21); add_u2(a2, u22);
        add_u2(a0, u30); add_u2(a1, u31); add_u2(a2, u32);
    }
    for (; k < end; k += 2) {
        int s = __ldg(&g_srcs[k]);
        const uint2* rp = ts16 + (size_t)s * 48 + hlane;
        uint2 u0 = __ldg(rp);
        uint2 u1 = __ldg(rp + 16);
        uint2 u2 = __ldg(rp + 32);
        add_u2(a0, u0);
        add_u2(a1, u1);
        add_u2(a2, u2);
    }

    // combine halves (butterfly over lane bit 4)
    a0.x += __shfl_xor_sync(0xffffffffu, a0.x, 16);
    a0.y += __shfl_xor_sync(0xffffffffu, a0.y, 16);
    a0.z += __shfl_xor_sync(0xffffffffu, a0.z, 16);
    a0.w += __shfl_xor_sync(0xffffffffu, a0.w, 16);
    a1.x += __shfl_xor_sync(0xffffffffu, a1.x, 16);
    a1.y += __shfl_xor_sync(0xffffffffu, a1.y, 16);
    a1.z += __shfl_xor_sync(0xffffffffu, a1.z, 16);
    a1.w += __shfl_xor_sync(0xffffffffu, a1.w, 16);
    a2.x += __shfl_xor_sync(0xffffffffu, a2.x, 16);
    a2.y += __shfl_xor_sync(0xffffffffu, a2.y, 16);
    a2.z += __shfl_xor_sync(0xffffffffu, a2.z, 16);
    a2.w += __shfl_xor_sync(0xffffffffu, a2.w, 16);

    if (half == 0) {
        float dv = g_dinv[node];
        const float4* b24 = (const float4*)b2;
        float4 b_0 = __ldg(&b24[hlane]);
        float4 b_1 = __ldg(&b24[16 + hlane]);
        float4 b_2 = __ldg(&b24[32 + hlane]);
        float4 o0, o1, o2;
        o0.x = fmaf(dv, a0.x, b_0.x); o0.y = fmaf(dv, a0.y, b_0.y);
        o0.z = fmaf(dv, a0.z, b_0.z); o0.w = fmaf(dv, a0.w, b_0.w);
        o1.x = fmaf(dv, a1.x, b_1.x); o1.y = fmaf(dv, a1.y, b_1.y);
        o1.z = fmaf(dv, a1.z, b_1.z); o1.w = fmaf(dv, a1.w, b_1.w);
        o2.x = fmaf(dv, a2.x, b_2.x); o2.y = fmaf(dv, a2.y, b_2.y);
        o2.z = fmaf(dv, a2.z, b_2.z); o2.w = fmaf(dv, a2.w, b_2.w);
        float4* out = &g_acc2_4[(size_t)node * H4];
        out[hlane]      = o0;
        out[16 + hlane] = o1;
        out[32 + hlane] = o2;
    }
}

// ---------------- fused graph_norm2 stats + relu + mean-pool ----------------
__global__ void k_norm2pool(const float* __restrict__ a2, const float* __restrict__ g2,
                            const float* __restrict__ be2) {
    int g = blockIdx.x, j = threadIdx.x;      // 192 threads
    int s = g_start[g], t = g_start[g + 1];
    const float* acc2 = (const float*)g_acc2_4;
    float sum = 0.f, sq = 0.f;
    int i = s;
    for (; i + 4 <= t; i += 4) {
        float v0 = __ldg(&acc2[(size_t)(i + 0) * HID + j]);
        float v1 = __ldg(&acc2[(size_t)(i + 1) * HID + j]);
        float v2 = __ldg(&acc2[(size_t)(i + 2) * HID + j]);
        float v3 = __ldg(&acc2[(size_t)(i + 3) * HID + j]);
        sum += (v0 + v1) + (v2 + v3);
        sq  += (v0 * v0 + v1 * v1) + (v2 * v2 + v3 * v3);
    }
    for (; i < t; i++) {
        float v = __ldg(&acc2[(size_t)i * HID + j]);
        sum += v; sq += v * v;
    }
    float cnt  = fmaxf((float)(t - s), 1.f);
    float mean = sum / cnt;
    float aj   = a2[j];
    float var  = sq / cnt - (2.f * aj - aj * aj) * mean * mean;
    var = fmaxf(var, 0.f);
    float sc  = g2[j] * rsqrtf(var + EPSN);
    float am  = aj * mean;
    float bej = be2[j];
    float p = 0.f;
    i = s;
    for (; i + 4 <= t; i += 4) {
        float v0 = __ldg(&acc2[(size_t)(i + 0) * HID + j]);
        float v1 = __ldg(&acc2[(size_t)(i + 1) * HID + j]);
        float v2 = __ldg(&acc2[(size_t)(i + 2) * HID + j]);
        float v3 = __ldg(&acc2[(size_t)(i + 3) * HID + j]);
        p += fmaxf(fmaf(sc, v0 - am, bej), 0.f);
        p += fmaxf(fmaf(sc, v1 - am, bej), 0.f);
        p += fmaxf(fmaf(sc, v2 - am, bej), 0.f);
        p += fmaxf(fmaf(sc, v3 - am, bej), 0.f);
    }
    for (; i < t; i++) {
        float v = __ldg(&acc2[(size_t)i * HID + j]);
        p += fmaxf(fmaf(sc, v - am, bej), 0.f);
    }
    g_pooled[g * HID + j] = p / cnt;
}

// ---------------- classifier head ----------------
__global__ void k_head(const float* __restrict__ Wc1, const float* __restrict__ bc1,
                       const float* __restrict__ Wc2, const float* __restrict__ bc2,
                       float* __restrict__ out) {
    __shared__ float sp[HID];
    __shared__ float sz[96];
    int g = blockIdx.x, t = threadIdx.x;      // 96 threads
    sp[t]      = g_pooled[g * HID + t];
    sp[t + 96] = g_pooled[g * HID + 96 + t];
    __syncthreads();
    float d = bc1[t];
#pragma unroll 8
    for (int k = 0; k < HID; k++) d = fmaf(sp[k], Wc1[k * 96 + t], d);
    sz[t] = fmaxf(d, 0.f);
    __syncthreads();
    if (t < 4) {
        float o = bc2[t];
#pragma unroll 8
        for (int k = 0; k < 96; k++) o = fmaf(sz[k], Wc2[k * 4 + t], o);
        out[g * 4 + t] = o;
    }
}

// ---------------- launch ----------------
extern "C" void kernel_launch(void* const* d_in, const int* in_sizes, int n_in,
                              void* d_out, int out_size) {
    const float* x     = (const float*)d_in[0];
    const int*   ei    = (const int*)d_in[1];
    const int*   batch = (const int*)d_in[2];
    const float* W1  = (const float*)d_in[3];
    const float* b1  = (const float*)d_in[4];
    const float* g1  = (const float*)d_in[5];
    const float* be1 = (const float*)d_in[6];
    const float* a1  = (const float*)d_in[7];
    const float* W2  = (const float*)d_in[8];
    const float* b2  = (const float*)d_in[9];
    const float* g2  = (const float*)d_in[10];
    const float* be2 = (const float*)d_in[11];
    const float* a2  = (const float*)d_in[12];
    const float* Wc1 = (const float*)d_in[13];
    const float* bc1 = (const float*)d_in[14];
    const float* Wc2 = (const float*)d_in[15];
    const float* bc2 = (const float*)d_in[16];

    int n = in_sizes[0];        // 100000
    int e = in_sizes[1] / 2;    // 1600000
    int nb = (n + 255) / 256;   // scan blocks

    const int SMEM_GEMM = (128 * SA_STRIDE + HID * SB_STRIDE) * 2;  // 128000 B
    cudaFuncSetAttribute(k_gemm_mma, cudaFuncAttributeMaxDynamicSharedMemorySize, SMEM_GEMM);

    k_init<<<(n + 255) / 256, 256>>>(n);
    k_deg<<<(e / 2 + 255) / 256, 256>>>(ei, e);
    k_scan1<<<nb, 256>>>(n);
    k_scan2<<<1, 1024>>>(nb, n);
    k_scan3<<<nb, 256>>>(n);
    k_fill<<<(e / 2 + 255) / 256, 256>>>(ei, e);
    k_node1<<<(n + 255) / 256, 256>>>(x, n);
    k_conv1<<<(n + 255) / 256, 256>>>(n);
    k_start<<<(NG + 1 + 127) / 128, 128>>>(batch, n);
    k_gstats<<<NG, 128>>>();
    k_pq<<<(NG * HID + 255) / 256, 256>>>(W1, b1, g1, be1, a1);
    k_w2h<<<(HID * HID + 255) / 256, 256>>>(W2);
    k_gemm_mma<<<(n + 127) / 128, 256, SMEM_GEMM>>>(batch, n);
    k_aggregate<<<(n * 32 + 255) / 256, 256>>>(b2, n);
    k_norm2pool<<<NG, HID>>>(a2, g2, be2);
    k_head<<<NG, 96>>>(Wc1, bc1, Wc2, bc2, (float*)d_out);
}

// round 11
// speedup vs baseline: 2.5883x; 1.1407x over previous
#include <cuda_runtime.h>
#include <cuda_fp16.h>
#include <cstdint>

#define NN   100000
#define NE   1600000
#define NG   512
#define HID  192
#define H4   48      // HID/4
#define EPSN 1e-5f

#define SA_STRIDE 200   // halfs, conflict-free for ldmatrix
#define SB_STRIDE 200

// ---------------- scratch (no allocs allowed) ----------------
__device__ int    g_cnt[NN];
__device__ int    g_off[NN + 1];
__device__ int    g_cur[NN];
__device__ int    g_srcs[NE];
__device__ int    g_bsum[1024];
__device__ int    g_bpre[1024];
__device__ float  g_dinv[NN];
__device__ float  g_xs[NN];
__device__ float  g_agg[NN];
__device__ int    g_start[NG + 1];
__device__ float  g_gmean[NG];
__device__ float  g_gvar[NG];
__device__ float  g_P[NG * HID];
__device__ float  g_Q[NG * HID];
__device__ __half g_W2h[HID * HID];                 // fp16 copy of W2
__device__ __align__(16) __half2 g_ts16[NN * 96];   // dinv*(h1n@W2), fp16
__device__ __align__(16) __half2 g_acc2h[NN * 96];  // h2pre, fp16
__device__ float  g_pooled[NG * HID];

// ---------------- CSR build ----------------
__global__ void k_init(int n) {
    int i = blockIdx.x * blockDim.x + threadIdx.x;
    if (i < n) g_cnt[i] = 0;
}

__global__ void k_deg(const int* __restrict__ ei, int e) {
    int idx = (blockIdx.x * blockDim.x + threadIdx.x) * 2;
    if (idx + 1 < e) {
        int2 c2 = *(const int2*)&ei[e + idx];
        atomicAdd(&g_cnt[c2.x], 1);
        atomicAdd(&g_cnt[c2.y], 1);
    } else if (idx < e) {
        atomicAdd(&g_cnt[__ldg(&ei[e + idx])], 1);
    }
}

// 3-phase coalesced exclusive scan of g_cnt -> g_off (+ g_cur copy)
__global__ void k_scan1(int n) {                    // grid = ceil(n/256)
    __shared__ int sh[256];
    int b = blockIdx.x, tid = threadIdx.x;
    int i = b * 256 + tid;
    int v = (i < n) ? g_cnt[i] : 0;
    sh[tid] = v;
    __syncthreads();
    for (int o = 1; o < 256; o <<= 1) {
        int x = sh[tid];
        int y = (tid >= o) ? sh[tid - o] : 0;
        __syncthreads();
        sh[tid] = x + y;
        __syncthreads();
    }
    if (i < n) g_off[i] = sh[tid] - v;              // intra-block exclusive
    if (tid == 255) g_bsum[b] = sh[255];
}

__global__ __launch_bounds__(1024) void k_scan2(int nb, int n) {  // single block
    __shared__ int sh[1024];
    int tid = threadIdx.x;
    int v = (tid < nb) ? g_bsum[tid] : 0;
    sh[tid] = v;
    __syncthreads();
    for (int o = 1; o < 1024; o <<= 1) {
        int x = sh[tid];
        int y = (tid >= o) ? sh[tid - o] : 0;
        __syncthreads();
        sh[tid] = x + y;
        __syncthreads();
    }
    if (tid < nb) g_bpre[tid] = sh[tid] - v;
    if (tid == 1023) g_off[n] = sh[1023];
}

// scan add-back + node prep (dinv, xs) fused
__global__ void k_scan3(const float* __restrict__ x, int n) {
    int i = blockIdx.x * blockDim.x + threadIdx.x;
    if (i < n) {
        int o = g_off[i] + g_bpre[i >> 8];
        g_off[i] = o;
        g_cur[i] = o;
        float v = rsqrtf((float)(g_cnt[i] + 1));    // +1 self-loop
        g_dinv[i] = v;
        g_xs[i]   = x[i] * v;
    }
}

__global__ void k_fill(const int* __restrict__ ei, int e) {
    int idx = (blockIdx.x * blockDim.x + threadIdx.x) * 2;
    if (idx + 1 < e) {
        int2 r2 = *(const int2*)&ei[idx];
        int2 c2 = *(const int2*)&ei[e + idx];
        int p0 = atomicAdd(&g_cur[c2.x], 1);
        int p1 = atomicAdd(&g_cur[c2.y], 1);
        g_srcs[p0] = r2.x;
        g_srcs[p1] = r2.y;
    } else if (idx < e) {
        int r = __ldg(&ei[idx]);
        int c = __ldg(&ei[e + idx]);
        int p = atomicAdd(&g_cur[c], 1);
        g_srcs[p] = r;
    }
}

// ---------------- conv1 (scalar, CSR) ----------------
__global__ void k_conv1(int n) {
    int i = blockIdx.x * blockDim.x + threadIdx.x;
    if (i >= n) return;
    int off = g_off[i], end = g_off[i + 1];
    float s = g_xs[i];
    int k = off;
    for (; k + 4 <= end; k += 4) {
        int s0 = __ldg(&g_srcs[k]);
        int s1 = __ldg(&g_srcs[k + 1]);
        int s2 = __ldg(&g_srcs[k + 2]);
        int s3 = __ldg(&g_srcs[k + 3]);
        float x0 = __ldg(&g_xs[s0]);
        float x1 = __ldg(&g_xs[s1]);
        float x2 = __ldg(&g_xs[s2]);
        float x3 = __ldg(&g_xs[s3]);
        s += (x0 + x1) + (x2 + x3);
    }
    for (; k < end; k++) s += __ldg(&g_xs[__ldg(&g_srcs[k])]);
    g_agg[i] = g_dinv[i] * s;
}

// ---------------- graph stats for norm1 ----------------
__global__ void k_start(const int* __restrict__ batch, int n) {
    int g = blockIdx.x * blockDim.x + threadIdx.x;
    if (g > NG) return;
    int lo = 0, hi = n;
    while (lo < hi) {
        int mid = (lo + hi) >> 1;
        if (batch[mid] < g) lo = mid + 1; else hi = mid;
    }
    g_start[g] = lo;
}

__global__ void k_gstats() {
    int g = blockIdx.x;
    int s = g_start[g], t = g_start[g + 1];
    int tid = threadIdx.x;
    float sum = 0.f, sq = 0.f;
    for (int i = s + tid; i < t; i += 128) {
        float a = g_agg[i];
        sum += a; sq += a * a;
    }
    __shared__ float ssum[128], ssq[128];
    ssum[tid] = sum; ssq[tid] = sq;
    __syncthreads();
    for (int o = 64; o > 0; o >>= 1) {
        if (tid < o) { ssum[tid] += ssum[tid + o]; ssq[tid] += ssq[tid + o]; }
        __syncthreads();
    }
    if (tid == 0) {
        float cnt = fmaxf((float)(t - s), 1.f);
        float m = ssum[0] / cnt;
        float v = ssq[0] / cnt - m * m;
        g_gmean[g] = m;
        g_gvar[g]  = fmaxf(v, 0.f);
    }
}

__global__ void k_pq(const float* __restrict__ W1, const float* __restrict__ b1,
                     const float* __restrict__ g1, const float* __restrict__ be1,
                     const float* __restrict__ a1) {
    int idx = blockIdx.x * blockDim.x + threadIdx.x;
    if (idx >= NG * HID) return;
    int g = idx / HID, j = idx % HID;
    float w = W1[j], bj = b1[j], aj = a1[j], gj = g1[j], bej = be1[j];
    float m = g_gmean[g], va = g_gvar[g];
    float eo  = (1.f - aj) * (w * m + bj);
    float var = w * w * va + eo * eo;
    float sc  = gj * rsqrtf(var + EPSN);
    g_P[idx] = sc * w;
    g_Q[idx] = sc * (bj * (1.f - aj) - w * aj * m) + bej;
}

// ---------------- W2 -> fp16 ----------------
__global__ void k_w2h(const float* __restrict__ W2) {
    int i = blockIdx.x * blockDim.x + threadIdx.x;
    if (i < HID * HID) g_W2h[i] = __float2half_rn(W2[i]);
}

// ---------------- tensor-core GEMM: ts16 = dinv * (relu(P*agg+Q) @ W2) ------
__global__ __launch_bounds__(256, 1) void k_gemm_mma(const int* __restrict__ batch, int n) {
    extern __shared__ __half smem[];
    __half* sA = smem;                       // [128][SA_STRIDE]
    __half* sB = smem + 128 * SA_STRIDE;     // [192][SB_STRIDE]

    int tid  = threadIdx.x;
    int row0 = blockIdx.x * 128;

#pragma unroll
    for (int u = 0; u < 144; u++) {
        int idx = u * 256 + tid;             // 36864 elems
        int k = idx / HID, nn2 = idx % HID;
        sB[k * SB_STRIDE + nn2] = g_W2h[idx];
    }

    {
        int row  = tid >> 1;
        int half = tid & 1;
        int grow = row0 + row;
        float ag = 0.f; int gb = 0;
        if (grow < n) { ag = g_agg[grow]; gb = __ldg(&batch[grow]); }
        const float* Pg = &g_P[gb * HID];
        const float* Qg = &g_Q[gb * HID];
        __half* dst = &sA[row * SA_STRIDE + half * 96];
#pragma unroll
        for (int c = 0; c < 96; c++) {
            int j = half * 96 + c;
            float v = fmaxf(fmaf(__ldg(&Pg[j]), ag, __ldg(&Qg[j])), 0.f);
            dst[c] = __float2half_rn(v);
        }
    }
    __syncthreads();

    int wid  = tid >> 5;
    int lane = tid & 31;
    int g8 = lane >> 3, r8 = lane & 7;

    float c[24][4];
#pragma unroll
    for (int t = 0; t < 24; t++)
#pragma unroll
        for (int q = 0; q < 4; q++) c[t][q] = 0.f;

    for (int ks = 0; ks < 12; ks++) {
        int k0 = ks * 16;
        uint32_t a0, a1, a2, a3;
        {
            int arow = wid * 16 + (g8 & 1) * 8 + r8;
            int acol = k0 + (g8 >> 1) * 8;
            uint32_t addr = (uint32_t)__cvta_generic_to_shared(&sA[arow * SA_STRIDE + acol]);
            asm volatile("ldmatrix.sync.aligned.m8n8.x4.shared.b16 {%0,%1,%2,%3}, [%4];"
                         : "=r"(a0), "=r"(a1), "=r"(a2), "=r"(a3) : "r"(addr));
        }
#pragma unroll
        for (int bt = 0; bt < 12; bt++) {
            int n0 = bt * 16;
            uint32_t b0, b1, b2, b3;
            int brow = k0 + (g8 & 1) * 8 + r8;
            int bcol = n0 + (g8 >> 1) * 8;
            uint32_t addr = (uint32_t)__cvta_generic_to_shared(&sB[brow * SB_STRIDE + bcol]);
            asm volatile("ldmatrix.sync.aligned.m8n8.x4.trans.shared.b16 {%0,%1,%2,%3}, [%4];"
                         : "=r"(b0), "=r"(b1), "=r"(b2), "=r"(b3) : "r"(addr));
            float* c0 = c[bt * 2];
            float* c1 = c[bt * 2 + 1];
            asm volatile("mma.sync.aligned.m16n8k16.row.col.f32.f16.f16.f32 "
                         "{%0,%1,%2,%3}, {%4,%5,%6,%7}, {%8,%9}, {%0,%1,%2,%3};"
                         : "+f"(c0[0]), "+f"(c0[1]), "+f"(c0[2]), "+f"(c0[3])
                         : "r"(a0), "r"(a1), "r"(a2), "r"(a3), "r"(b0), "r"(b1));
            asm volatile("mma.sync.aligned.m16n8k16.row.col.f32.f16.f16.f32 "
                         "{%0,%1,%2,%3}, {%4,%5,%6,%7}, {%8,%9}, {%0,%1,%2,%3};"
                         : "+f"(c1[0]), "+f"(c1[1]), "+f"(c1[2]), "+f"(c1[3])
                         : "r"(a0), "r"(a1), "r"(a2), "r"(a3), "r"(b2), "r"(b3));
        }
    }

    int r0 = row0 + wid * 16 + (lane >> 2);
    int r1 = r0 + 8;
    float dv0 = (r0 < n) ? g_dinv[r0] : 0.f;
    float dv1 = (r1 < n) ? g_dinv[r1] : 0.f;
#pragma unroll
    for (int t = 0; t < 24; t++) {
        int cc = t * 8 + (lane & 3) * 2;
        int o2 = cc >> 1;
        if (r0 < n)
            g_ts16[(size_t)r0 * 96 + o2] = __floats2half2_rn(c[t][0] * dv0, c[t][1] * dv0);
        if (r1 < n)
            g_ts16[(size_t)r1 * 96 + o2] = __floats2half2_rn(c[t][2] * dv1, c[t][3] * dv1);
    }
}

// ---------------- conv2 aggregate (warp per dst, even/odd split) -------------
__device__ __forceinline__ void add_u2(float4& a, uint2 u) {
    __half2 h0 = *reinterpret_cast<__half2*>(&u.x);
    __half2 h1 = *reinterpret_cast<__half2*>(&u.y);
    float2 f0 = __half22float2(h0);
    float2 f1 = __half22float2(h1);
    a.x += f0.x; a.y += f0.y; a.z += f1.x; a.w += f1.y;
}

__global__ __launch_bounds__(256) void k_aggregate(const float* __restrict__ b2, int n) {
    int t = blockIdx.x * blockDim.x + threadIdx.x;
    int node  = t >> 5;
    int lane  = t & 31;
    int hlane = lane & 15;
    int half  = lane >> 4;
    if (node >= n) return;

    const uint2* ts16 = (const uint2*)g_ts16;

    float4 a0 = make_float4(0.f, 0.f, 0.f, 0.f);
    float4 a1 = a0, a2 = a0;
    if (half == 0) {                          // self-loop row (fp16)
        const uint2* sp = ts16 + (size_t)node * 48 + hlane;
        add_u2(a0, __ldg(sp));
        add_u2(a1, __ldg(sp + 16));
        add_u2(a2, __ldg(sp + 32));
    }

    int off = g_off[node], end = g_off[node + 1];

    int k = off + half;                      // this half: every other neighbor
    for (; k + 6 < end; k += 8) {            // 4 neighbors per iteration
        int s0 = __ldg(&g_srcs[k]);
        int s1 = __ldg(&g_srcs[k + 2]);
        int s2 = __ldg(&g_srcs[k + 4]);
        int s3 = __ldg(&g_srcs[k + 6]);
        const uint2* p0 = ts16 + (size_t)s0 * 48 + hlane;
        const uint2* p1 = ts16 + (size_t)s1 * 48 + hlane;
        const uint2* p2 = ts16 + (size_t)s2 * 48 + hlane;
        const uint2* p3 = ts16 + (size_t)s3 * 48 + hlane;
        uint2 u00 = __ldg(p0), u01 = __ldg(p0 + 16), u02 = __ldg(p0 + 32);
        uint2 u10 = __ldg(p1), u11 = __ldg(p1 + 16), u12 = __ldg(p1 + 32);
        uint2 u20 = __ldg(p2), u21 = __ldg(p2 + 16), u22 = __ldg(p2 + 32);
        uint2 u30 = __ldg(p3), u31 = __ldg(p3 + 16), u32 = __ldg(p3 + 32);
        add_u2(a0, u00); add_u2(a1, u01); add_u2(a2, u02);
        add_u2(a0, u10); add_u2(a1, u11); add_u2(a2, u12);
        add_u2(a0, u20); add_u2(a1, u21); add_u2(a2, u22);
        add_u2(a0, u30); add_u2(a1, u31); add_u2(a2, u32);
    }
    for (; k < end; k += 2) {
        int s = __ldg(&g_srcs[k]);
        const uint2* rp = ts16 + (size_t)s * 48 + hlane;
        uint2 u0 = __ldg(rp);
        uint2 u1 = __ldg(rp + 16);
        uint2 u2 = __ldg(rp + 32);
        add_u2(a0, u0);
        add_u2(a1, u1);
        add_u2(a2, u2);
    }

    // combine halves (butterfly over lane bit 4)
    a0.x += __shfl_xor_sync(0xffffffffu, a0.x, 16);
    a0.y += __shfl_xor_sync(0xffffffffu, a0.y, 16);
    a0.z += __shfl_xor_sync(0xffffffffu, a0.z, 16);
    a0.w += __shfl_xor_sync(0xffffffffu, a0.w, 16);
    a1.x += __shfl_xor_sync(0xffffffffu, a1.x, 16);
    a1.y += __shfl_xor_sync(0xffffffffu, a1.y, 16);
    a1.z += __shfl_xor_sync(0xffffffffu, a1.z, 16);
    a1.w += __shfl_xor_sync(0xffffffffu, a1.w, 16);
    a2.x += __shfl_xor_sync(0xffffffffu, a2.x, 16);
    a2.y += __shfl_xor_sync(0xffffffffu, a2.y, 16);
    a2.z += __shfl_xor_sync(0xffffffffu, a2.z, 16);
    a2.w += __shfl_xor_sync(0xffffffffu, a2.w, 16);

    if (half == 0) {
        float dv = g_dinv[node];
        const float4* b24 = (const float4*)b2;
        float4 b_0 = __ldg(&b24[hlane]);
        float4 b_1 = __ldg(&b24[16 + hlane]);
        float4 b_2 = __ldg(&b24[32 + hlane]);
        // h2pre in fp32, store fp16
        uint2 o0, o1, o2;
        __half2 h;
        h = __floats2half2_rn(fmaf(dv, a0.x, b_0.x), fmaf(dv, a0.y, b_0.y)); o0.x = *(uint32_t*)&h;
        h = __floats2half2_rn(fmaf(dv, a0.z, b_0.z), fmaf(dv, a0.w, b_0.w)); o0.y = *(uint32_t*)&h;
        h = __floats2half2_rn(fmaf(dv, a1.x, b_1.x), fmaf(dv, a1.y, b_1.y)); o1.x = *(uint32_t*)&h;
        h = __floats2half2_rn(fmaf(dv, a1.z, b_1.z), fmaf(dv, a1.w, b_1.w)); o1.y = *(uint32_t*)&h;
        h = __floats2half2_rn(fmaf(dv, a2.x, b_2.x), fmaf(dv, a2.y, b_2.y)); o2.x = *(uint32_t*)&h;
        h = __floats2half2_rn(fmaf(dv, a2.z, b_2.z), fmaf(dv, a2.w, b_2.w)); o2.y = *(uint32_t*)&h;
        uint2* out = (uint2*)g_acc2h + (size_t)node * 48;
        out[hlane]      = o0;
        out[16 + hlane] = o1;
        out[32 + hlane] = o2;
    }
}

// ---------------- fused graph_norm2 stats + relu + mean-pool ----------------
__global__ void k_norm2pool(const float* __restrict__ a2, const float* __restrict__ g2,
                            const float* __restrict__ be2) {
    int g = blockIdx.x, j = threadIdx.x;      // 192 threads
    int s = g_start[g], t = g_start[g + 1];
    const __half* acc2 = (const __half*)g_acc2h;
    float sum = 0.f, sq = 0.f;
    int i = s;
    for (; i + 4 <= t; i += 4) {
        float v0 = __half2float(__ldg(&acc2[(size_t)(i + 0) * HID + j]));
        float v1 = __half2float(__ldg(&acc2[(size_t)(i + 1) * HID + j]));
        float v2 = __half2float(__ldg(&acc2[(size_t)(i + 2) * HID + j]));
        float v3 = __half2float(__ldg(&acc2[(size_t)(i + 3) * HID + j]));
        sum += (v0 + v1) + (v2 + v3);
        sq  += (v0 * v0 + v1 * v1) + (v2 * v2 + v3 * v3);
    }
    for (; i < t; i++) {
        float v = __half2float(__ldg(&acc2[(size_t)i * HID + j]));
        sum += v; sq += v * v;
    }
    float cnt  = fmaxf((float)(t - s), 1.f);
    float mean = sum / cnt;
    float aj   = a2[j];
    float var  = sq / cnt - (2.f * aj - aj * aj) * mean * mean;
    var = fmaxf(var, 0.f);
    float sc  = g2[j] * rsqrtf(var + EPSN);
    float am  = aj * mean;
    float bej = be2[j];
    float p = 0.f;
    i = s;
    for (; i + 4 <= t; i += 4) {
        float v0 = __half2float(__ldg(&acc2[(size_t)(i + 0) * HID + j]));
        float v1 = __half2float(__ldg(&acc2[(size_t)(i + 1) * HID + j]));
        float v2 = __half2float(__ldg(&acc2[(size_t)(i + 2) * HID + j]));
        float v3 = __half2float(__ldg(&acc2[(size_t)(i + 3) * HID + j]));
        p += fmaxf(fmaf(sc, v0 - am, bej), 0.f);
        p += fmaxf(fmaf(sc, v1 - am, bej), 0.f);
        p += fmaxf(fmaf(sc, v2 - am, bej), 0.f);
        p += fmaxf(fmaf(sc, v3 - am, bej), 0.f);
    }
    for (; i < t; i++) {
        float v = __half2float(__ldg(&acc2[(size_t)i * HID + j]));
        p += fmaxf(fmaf(sc, v - am, bej), 0.f);
    }
    g_pooled[g * HID + j] = p / cnt;
}

// ---------------- classifier head ----------------
__global__ void k_head(const float* __restrict__ Wc1, const float* __restrict__ bc1,
                       const float* __restrict__ Wc2, const float* __restrict__ bc2,
                       float* __restrict__ out) {
    __shared__ float sp[HID];
    __shared__ float sz[96];
    int g = blockIdx.x, t = threadIdx.x;      // 96 threads
    sp[t]      = g_pooled[g * HID + t];
    sp[t + 96] = g_pooled[g * HID + 96 + t];
    __syncthreads();
    float d = bc1[t];
#pragma unroll 8
    for (int k = 0; k < HID; k++) d = fmaf(sp[k], Wc1[k * 96 + t], d);
    sz[t] = fmaxf(d, 0.f);
    __syncthreads();
    if (t < 4) {
        float o = bc2[t];
#pragma unroll 8
        for (int k = 0; k < 96; k++) o = fmaf(sz[k], Wc2[k * 4 + t], o);
        out[g * 4 + t] = o;
    }
}

// ---------------- launch ----------------
extern "C" void kernel_launch(void* const* d_in, const int* in_sizes, int n_in,
                              void* d_out, int out_size) {
    const float* x     = (const float*)d_in[0];
    const int*   ei    = (const int*)d_in[1];
    const int*   batch = (const int*)d_in[2];
    const float* W1  = (const float*)d_in[3];
    const float* b1  = (const float*)d_in[4];
    const float* g1  = (const float*)d_in[5];
    const float* be1 = (const float*)d_in[6];
    const float* a1  = (const float*)d_in[7];
    const float* W2  = (const float*)d_in[8];
    const float* b2  = (const float*)d_in[9];
    const float* g2  = (const float*)d_in[10];
    const float* be2 = (const float*)d_in[11];
    const float* a2  = (const float*)d_in[12];
    const float* Wc1 = (const float*)d_in[13];
    const float* bc1 = (const float*)d_in[14];
    const float* Wc2 = (const float*)d_in[15];
    const float* bc2 = (const float*)d_in[16];

    int n = in_sizes[0];        // 100000
    int e = in_sizes[1] / 2;    // 1600000
    int nb = (n + 255) / 256;   // scan blocks

    const int SMEM_GEMM = (128 * SA_STRIDE + HID * SB_STRIDE) * 2;  // 128000 B
    cudaFuncSetAttribute(k_gemm_mma, cudaFuncAttributeMaxDynamicSharedMemorySize, SMEM_GEMM);

    k_init<<<(n + 255) / 256, 256>>>(n);
    k_deg<<<(e / 2 + 255) / 256, 256>>>(ei, e);
    k_scan1<<<nb, 256>>>(n);
    k_scan2<<<1, 1024>>>(nb, n);
    k_scan3<<<nb, 256>>>(x, n);
    k_fill<<<(e / 2 + 255) / 256, 256>>>(ei, e);
    k_conv1<<<(n + 255) / 256, 256>>>(n);
    k_start<<<(NG + 1 + 127) / 128, 128>>>(batch, n);
    k_gstats<<<NG, 128>>>();
    k_pq<<<(NG * HID + 255) / 256, 256>>>(W1, b1, g1, be1, a1);
    k_w2h<<<(HID * HID + 255) / 256, 256>>>(W2);
    k_gemm_mma<<<(n + 127) / 128, 256, SMEM_GEMM>>>(batch, n);
    k_aggregate<<<(n * 32 + 255) / 256, 256>>>(b2, n);
    k_norm2pool<<<NG, HID>>>(a2, g2, be2);
    k_head<<<NG, 96>>>(Wc1, bc1, Wc2, bc2, (float*)d_out);
}

// round 13
// speedup vs baseline: 3.0498x; 1.1783x over previous
#include <cuda_runtime.h>
#include <cuda_fp16.h>
#include <cstdint>

#define NN   100000
#define NE   1600000
#define NG   512
#define HID  192
#define H4   48      // HID/4
#define EPSN 1e-5f

#define SA_STRIDE 200   // halfs, conflict-free for ldmatrix
#define SB_STRIDE 200

// ---------------- scratch (no allocs allowed) ----------------
__device__ int    g_cnt[NN];
__device__ int    g_off[NN + 1];
__device__ int    g_cur[NN];
__device__ int    g_srcs[NE];
__device__ int    g_bsum[1024];
__device__ int    g_bpre[1024];
__device__ float  g_dinv[NN];
__device__ float  g_xs[NN];
__device__ float  g_agg[NN];
__device__ int    g_start[NG + 1];
__device__ float  g_gmean[NG];
__device__ float  g_gvar[NG];
__device__ float  g_P[NG * HID];
__device__ float  g_Q[NG * HID];
__device__ __half g_W2h[HID * HID];                 // fp16 copy of W2
__device__ __align__(16) __half2 g_ts16[NN * 96];   // dinv*(h1n@W2), fp16
__device__ __align__(16) __half2 g_acc2h[NN * 96];  // h2pre, fp16

// ---------------- CSR build ----------------
__global__ void k_init(int n) {
    int i = blockIdx.x * blockDim.x + threadIdx.x;
    if (i < n) g_cnt[i] = 0;
}

__global__ void k_deg(const int* __restrict__ ei, int e) {
    int idx = (blockIdx.x * blockDim.x + threadIdx.x) * 2;
    if (idx + 1 < e) {
        int2 c2 = *(const int2*)&ei[e + idx];
        atomicAdd(&g_cnt[c2.x], 1);
        atomicAdd(&g_cnt[c2.y], 1);
    } else if (idx < e) {
        atomicAdd(&g_cnt[__ldg(&ei[e + idx])], 1);
    }
}

// 3-phase coalesced exclusive scan of g_cnt -> g_off (+ g_cur copy)
__global__ void k_scan1(int n) {                    // grid = ceil(n/256)
    __shared__ int sh[256];
    int b = blockIdx.x, tid = threadIdx.x;
    int i = b * 256 + tid;
    int v = (i < n) ? g_cnt[i] : 0;
    sh[tid] = v;
    __syncthreads();
    for (int o = 1; o < 256; o <<= 1) {
        int x = sh[tid];
        int y = (tid >= o) ? sh[tid - o] : 0;
        __syncthreads();
        sh[tid] = x + y;
        __syncthreads();
    }
    if (i < n) g_off[i] = sh[tid] - v;              // intra-block exclusive
    if (tid == 255) g_bsum[b] = sh[255];
}

__global__ __launch_bounds__(1024) void k_scan2(int nb, int n) {  // single block
    __shared__ int sh[1024];
    int tid = threadIdx.x;
    int v = (tid < nb) ? g_bsum[tid] : 0;
    sh[tid] = v;
    __syncthreads();
    for (int o = 1; o < 1024; o <<= 1) {
        int x = sh[tid];
        int y = (tid >= o) ? sh[tid - o] : 0;
        __syncthreads();
        sh[tid] = x + y;
        __syncthreads();
    }
    if (tid < nb) g_bpre[tid] = sh[tid] - v;
    if (tid == 1023) g_off[n] = sh[1023];
}

// scan add-back + node prep (dinv, xs) + graph-start binary search, fused
__global__ void k_scan3(const float* __restrict__ x, const int* __restrict__ batch, int n) {
    int i = blockIdx.x * blockDim.x + threadIdx.x;
    if (i < n) {
        int o = g_off[i] + g_bpre[i >> 8];
        g_off[i] = o;
        g_cur[i] = o;
        float v = rsqrtf((float)(g_cnt[i] + 1));    // +1 self-loop
        g_dinv[i] = v;
        g_xs[i]   = x[i] * v;
    }
    if (i <= NG) {                                   // graph range starts
        int lo = 0, hi = n;
        while (lo < hi) {
            int mid = (lo + hi) >> 1;
            if (__ldg(&batch[mid]) < i) lo = mid + 1; else hi = mid;
        }
        g_start[i] = lo;
    }
}

__global__ void k_fill(const int* __restrict__ ei, int e) {
    int idx = (blockIdx.x * blockDim.x + threadIdx.x) * 2;
    if (idx + 1 < e) {
        int2 r2 = *(const int2*)&ei[idx];
        int2 c2 = *(const int2*)&ei[e + idx];
        int p0 = atomicAdd(&g_cur[c2.x], 1);
        int p1 = atomicAdd(&g_cur[c2.y], 1);
        g_srcs[p0] = r2.x;
        g_srcs[p1] = r2.y;
    } else if (idx < e) {
        int r = __ldg(&ei[idx]);
        int c = __ldg(&ei[e + idx]);
        int p = atomicAdd(&g_cur[c], 1);
        g_srcs[p] = r;
    }
}

// ---------------- conv1 (scalar, CSR) ----------------
__global__ void k_conv1(int n) {
    int i = blockIdx.x * blockDim.x + threadIdx.x;
    if (i >= n) return;
    int off = g_off[i], end = g_off[i + 1];
    float s = g_xs[i];
    int k = off;
    for (; k + 4 <= end; k += 4) {
        int s0 = __ldg(&g_srcs[k]);
        int s1 = __ldg(&g_srcs[k + 1]);
        int s2 = __ldg(&g_srcs[k + 2]);
        int s3 = __ldg(&g_srcs[k + 3]);
        float x0 = __ldg(&g_xs[s0]);
        float x1 = __ldg(&g_xs[s1]);
        float x2 = __ldg(&g_xs[s2]);
        float x3 = __ldg(&g_xs[s3]);
        s += (x0 + x1) + (x2 + x3);
    }
    for (; k < end; k++) s += __ldg(&g_xs[__ldg(&g_srcs[k])]);
    g_agg[i] = g_dinv[i] * s;
}

// ---------------- graph stats for norm1 ----------------
__global__ void k_gstats() {
    int g = blockIdx.x;
    int s = g_start[g], t = g_start[g + 1];
    int tid = threadIdx.x;
    float sum = 0.f, sq = 0.f;
    for (int i = s + tid; i < t; i += 128) {
        float a = g_agg[i];
        sum += a; sq += a * a;
    }
    __shared__ float ssum[128], ssq[128];
    ssum[tid] = sum; ssq[tid] = sq;
    __syncthreads();
    for (int o = 64; o > 0; o >>= 1) {
        if (tid < o) { ssum[tid] += ssum[tid + o]; ssq[tid] += ssq[tid + o]; }
        __syncthreads();
    }
    if (tid == 0) {
        float cnt = fmaxf((float)(t - s), 1.f);
        float m = ssum[0] / cnt;
        float v = ssq[0] / cnt - m * m;
        g_gmean[g] = m;
        g_gvar[g]  = fmaxf(v, 0.f);
    }
}

// P/Q tables + W2->fp16 conversion fused (disjoint index ranges)
__global__ void k_pq(const float* __restrict__ W1, const float* __restrict__ b1,
                     const float* __restrict__ g1, const float* __restrict__ be1,
                     const float* __restrict__ a1, const float* __restrict__ W2) {
    int idx = blockIdx.x * blockDim.x + threadIdx.x;
    if (idx < NG * HID) {
        int g = idx / HID, j = idx % HID;
        float w = W1[j], bj = b1[j], aj = a1[j], gj = g1[j], bej = be1[j];
        float m = g_gmean[g], va = g_gvar[g];
        float eo  = (1.f - aj) * (w * m + bj);
        float var = w * w * va + eo * eo;
        float sc  = gj * rsqrtf(var + EPSN);
        g_P[idx] = sc * w;
        g_Q[idx] = sc * (bj * (1.f - aj) - w * aj * m) + bej;
    } else if (idx < NG * HID + HID * HID) {
        int k = idx - NG * HID;
        g_W2h[k] = __float2half_rn(W2[k]);
    }
}

// ---------------- tensor-core GEMM: ts16 = dinv * (relu(P*agg+Q) @ W2) ------
// 256 rows per block (two 128-row tiles reuse one smem W2 load), 8 warps.
__global__ __launch_bounds__(256, 1) void k_gemm_mma(const int* __restrict__ batch, int n) {
    extern __shared__ __half smem[];
    __half* sA = smem;                       // [128][SA_STRIDE]
    __half* sB = smem + 128 * SA_STRIDE;     // [192][SB_STRIDE]

    int tid  = threadIdx.x;
    int blk0 = blockIdx.x * 256;

#pragma unroll
    for (int u = 0; u < 144; u++) {
        int idx = u * 256 + tid;             // 36864 elems
        int k = idx / HID, nn2 = idx % HID;
        sB[k * SB_STRIDE + nn2] = g_W2h[idx];
    }

    int wid  = tid >> 5;
    int lane = tid & 31;
    int g8 = lane >> 3, r8 = lane & 7;

    for (int tile = 0; tile < 2; tile++) {
        int row0 = blk0 + tile * 128;
        if (tile) __syncthreads();           // all warps done reading sA

        {   // generate h1n tile in fp16: 2 threads per row, 96 cols each
            int row  = tid >> 1;
            int half = tid & 1;
            int grow = row0 + row;
            float ag = 0.f; int gb = 0;
            if (grow < n) { ag = g_agg[grow]; gb = __ldg(&batch[grow]); }
            const float* Pg = &g_P[gb * HID];
            const float* Qg = &g_Q[gb * HID];
            __half* dst = &sA[row * SA_STRIDE + half * 96];
#pragma unroll
            for (int c = 0; c < 96; c++) {
                int j = half * 96 + c;
                float v = fmaxf(fmaf(__ldg(&Pg[j]), ag, __ldg(&Qg[j])), 0.f);
                dst[c] = __float2half_rn(v);
            }
        }
        __syncthreads();

        float c[24][4];
#pragma unroll
        for (int t = 0; t < 24; t++)
#pragma unroll
            for (int q = 0; q < 4; q++) c[t][q] = 0.f;

        for (int ks = 0; ks < 12; ks++) {
            int k0 = ks * 16;
            uint32_t a0, a1, a2, a3;
            {
                int arow = wid * 16 + (g8 & 1) * 8 + r8;
                int acol = k0 + (g8 >> 1) * 8;
                uint32_t addr = (uint32_t)__cvta_generic_to_shared(&sA[arow * SA_STRIDE + acol]);
                asm volatile("ldmatrix.sync.aligned.m8n8.x4.shared.b16 {%0,%1,%2,%3}, [%4];"
                             : "=r"(a0), "=r"(a1), "=r"(a2), "=r"(a3) : "r"(addr));
            }
#pragma unroll
            for (int bt = 0; bt < 12; bt++) {
                int n0 = bt * 16;
                uint32_t b0, b1, b2, b3;
                int brow = k0 + (g8 & 1) * 8 + r8;
                int bcol = n0 + (g8 >> 1) * 8;
                uint32_t addr = (uint32_t)__cvta_generic_to_shared(&sB[brow * SB_STRIDE + bcol]);
                asm volatile("ldmatrix.sync.aligned.m8n8.x4.trans.shared.b16 {%0,%1,%2,%3}, [%4];"
                             : "=r"(b0), "=r"(b1), "=r"(b2), "=r"(b3) : "r"(addr));
                float* c0 = c[bt * 2];
                float* c1 = c[bt * 2 + 1];
                asm volatile("mma.sync.aligned.m16n8k16.row.col.f32.f16.f16.f32 "
                             "{%0,%1,%2,%3}, {%4,%5,%6,%7}, {%8,%9}, {%0,%1,%2,%3};"
                             : "+f"(c0[0]), "+f"(c0[1]), "+f"(c0[2]), "+f"(c0[3])
                             : "r"(a0), "r"(a1), "r"(a2), "r"(a3), "r"(b0), "r"(b1));
                asm volatile("mma.sync.aligned.m16n8k16.row.col.f32.f16.f16.f32 "
                             "{%0,%1,%2,%3}, {%4,%5,%6,%7}, {%8,%9}, {%0,%1,%2,%3};"
                             : "+f"(c1[0]), "+f"(c1[1]), "+f"(c1[2]), "+f"(c1[3])
                             : "r"(a0), "r"(a1), "r"(a2), "r"(a3), "r"(b2), "r"(b3));
            }
        }

        int r0 = row0 + wid * 16 + (lane >> 2);
        int r1 = r0 + 8;
        float dv0 = (r0 < n) ? g_dinv[r0] : 0.f;
        float dv1 = (r1 < n) ? g_dinv[r1] : 0.f;
#pragma unroll
        for (int t = 0; t < 24; t++) {
            int cc = t * 8 + (lane & 3) * 2;
            int o2 = cc >> 1;
            if (r0 < n)
                g_ts16[(size_t)r0 * 96 + o2] = __floats2half2_rn(c[t][0] * dv0, c[t][1] * dv0);
            if (r1 < n)
                g_ts16[(size_t)r1 * 96 + o2] = __floats2half2_rn(c[t][2] * dv1, c[t][3] * dv1);
        }
    }
}

// ---------------- conv2 aggregate (warp per dst, even/odd split) -------------
__device__ __forceinline__ void add_u2(float4& a, uint2 u) {
    __half2 h0 = *reinterpret_cast<__half2*>(&u.x);
    __half2 h1 = *reinterpret_cast<__half2*>(&u.y);
    float2 f0 = __half22float2(h0);
    float2 f1 = __half22float2(h1);
    a.x += f0.x; a.y += f0.y; a.z += f1.x; a.w += f1.y;
}

__global__ __launch_bounds__(256) void k_aggregate(const float* __restrict__ b2, int n) {
    int t = blockIdx.x * blockDim.x + threadIdx.x;
    int node  = t >> 5;
    int lane  = t & 31;
    int hlane = lane & 15;
    int half  = lane >> 4;
    if (node >= n) return;

    const uint2* ts16 = (const uint2*)g_ts16;

    float4 a0 = make_float4(0.f, 0.f, 0.f, 0.f);
    float4 a1 = a0, a2 = a0;
    if (half == 0) {                          // self-loop row (fp16)
        const uint2* sp = ts16 + (size_t)node * 48 + hlane;
        add_u2(a0, __ldg(sp));
        add_u2(a1, __ldg(sp + 16));
        add_u2(a2, __ldg(sp + 32));
    }

    int off = g_off[node], end = g_off[node + 1];

    int k = off + half;                      // this half: every other neighbor
    for (; k + 6 < end; k += 8) {            // 4 neighbors per iteration
        int s0 = __ldg(&g_srcs[k]);
        int s1 = __ldg(&g_srcs[k + 2]);
        int s2 = __ldg(&g_srcs[k + 4]);
        int s3 = __ldg(&g_srcs[k + 6]);
        const uint2* p0 = ts16 + (size_t)s0 * 48 + hlane;
        const uint2* p1 = ts16 + (size_t)s1 * 48 + hlane;
        const uint2* p2 = ts16 + (size_t)s2 * 48 + hlane;
        const uint2* p3 = ts16 + (size_t)s3 * 48 + hlane;
        uint2 u00 = __ldg(p0), u01 = __ldg(p0 + 16), u02 = __ldg(p0 + 32);
        uint2 u10 = __ldg(p1), u11 = __ldg(p1 + 16), u12 = __ldg(p1 + 32);
        uint2 u20 = __ldg(p2), u21 = __ldg(p2 + 16), u22 = __ldg(p2 + 32);
        uint2 u30 = __ldg(p3), u31 = __ldg(p3 + 16), u32 = __ldg(p3 + 32);
        add_u2(a0, u00); add_u2(a1, u01); add_u2(a2, u02);
        add_u2(a0, u10); add_u2(a1, u11); add_u2(a2, u12);
        add_u2(a0, u20); add_u2(a1, u21); add_u2(a2, u22);
        add_u2(a0, u30); add_u2(a1, u31); add_u2(a2, u32);
    }
    for (; k < end; k += 2) {
        int s = __ldg(&g_srcs[k]);
        const uint2* rp = ts16 + (size_t)s * 48 + hlane;
        uint2 u0 = __ldg(rp);
        uint2 u1 = __ldg(rp + 16);
        uint2 u2 = __ldg(rp + 32);
        add_u2(a0, u0);
        add_u2(a1, u1);
        add_u2(a2, u2);
    }

    // combine halves (butterfly over lane bit 4)
    a0.x += __shfl_xor_sync(0xffffffffu, a0.x, 16);
    a0.y += __shfl_xor_sync(0xffffffffu, a0.y, 16);
    a0.z += __shfl_xor_sync(0xffffffffu, a0.z, 16);
    a0.w += __shfl_xor_sync(0xffffffffu, a0.w, 16);
    a1.x += __shfl_xor_sync(0xffffffffu, a1.x, 16);
    a1.y += __shfl_xor_sync(0xffffffffu, a1.y, 16);
    a1.z += __shfl_xor_sync(0xffffffffu, a1.z, 16);
    a1.w += __shfl_xor_sync(0xffffffffu, a1.w, 16);
    a2.x += __shfl_xor_sync(0xffffffffu, a2.x, 16);
    a2.y += __shfl_xor_sync(0xffffffffu, a2.y, 16);
    a2.z += __shfl_xor_sync(0xffffffffu, a2.z, 16);
    a2.w += __shfl_xor_sync(0xffffffffu, a2.w, 16);

    if (half == 0) {
        float dv = g_dinv[node];
        const float4* b24 = (const float4*)b2;
        float4 b_0 = __ldg(&b24[hlane]);
        float4 b_1 = __ldg(&b24[16 + hlane]);
        float4 b_2 = __ldg(&b24[32 + hlane]);
        uint2 o0, o1, o2;
        __half2 h;
        h = __floats2half2_rn(fmaf(dv, a0.x, b_0.x), fmaf(dv, a0.y, b_0.y)); o0.x = *(uint32_t*)&h;
        h = __floats2half2_rn(fmaf(dv, a0.z, b_0.z), fmaf(dv, a0.w, b_0.w)); o0.y = *(uint32_t*)&h;
        h = __floats2half2_rn(fmaf(dv, a1.x, b_1.x), fmaf(dv, a1.y, b_1.y)); o1.x = *(uint32_t*)&h;
        h = __floats2half2_rn(fmaf(dv, a1.z, b_1.z), fmaf(dv, a1.w, b_1.w)); o1.y = *(uint32_t*)&h;
        h = __floats2half2_rn(fmaf(dv, a2.x, b_2.x), fmaf(dv, a2.y, b_2.y)); o2.x = *(uint32_t*)&h;
        h = __floats2half2_rn(fmaf(dv, a2.z, b_2.z), fmaf(dv, a2.w, b_2.w)); o2.y = *(uint32_t*)&h;
        uint2* out = (uint2*)g_acc2h + (size_t)node * 48;
        out[hlane]      = o0;
        out[16 + hlane] = o1;
        out[32 + hlane] = o2;
    }
}

// -------- fused graph_norm2 stats + relu + mean-pool + classifier head -------
// 384 threads: (j = tid%192 feature, half = tid/192 row parity)
__global__ __launch_bounds__(384) void k_norm2pool(
        const float* __restrict__ a2, const float* __restrict__ g2,
        const float* __restrict__ be2,
        const float* __restrict__ Wc1, const float* __restrict__ bc1,
        const float* __restrict__ Wc2, const float* __restrict__ bc2,
        float* __restrict__ out) {
    __shared__ float ssum[384], ssq[384];
    __shared__ float s_sc[192], s_am[192];
    __shared__ float s_pool[384];
    __shared__ float sz[96];

    int g = blockIdx.x;
    int tid = threadIdx.x;
    int j = tid % 192;
    int half = tid / 192;
    int s = g_start[g], t = g_start[g + 1];
    const __half* acc2 = (const __half*)g_acc2h;

    float sum = 0.f, sq = 0.f;
    int i = s + half;
    for (; i + 6 < t; i += 8) {
        float v0 = __half2float(__ldg(&acc2[(size_t)(i + 0) * HID + j]));
        float v1 = __half2float(__ldg(&acc2[(size_t)(i + 2) * HID + j]));
        float v2 = __half2float(__ldg(&acc2[(size_t)(i + 4) * HID + j]));
        float v3 = __half2float(__ldg(&acc2[(size_t)(i + 6) * HID + j]));
        sum += (v0 + v1) + (v2 + v3);
        sq  += (v0 * v0 + v1 * v1) + (v2 * v2 + v3 * v3);
    }
    for (; i < t; i += 2) {
        float v = __half2float(__ldg(&acc2[(size_t)i * HID + j]));
        sum += v; sq += v * v;
    }
    ssum[tid] = sum; ssq[tid] = sq;
    __syncthreads();

    float cnt = fmaxf((float)(t - s), 1.f);
    if (tid < 192) {
        float S  = ssum[tid] + ssum[tid + 192];
        float Q  = ssq[tid]  + ssq[tid + 192];
        float mean = S / cnt;
        float aj   = a2[tid];
        float var  = Q / cnt - (2.f * aj - aj * aj) * mean * mean;
        var = fmaxf(var, 0.f);
        s_sc[tid] = g2[tid] * rsqrtf(var + EPSN);
        s_am[tid] = aj * mean;
    }
    __syncthreads();

    float sc  = s_sc[j];
    float am  = s_am[j];
    float bej = be2[j];
    float p = 0.f;
    i = s + half;
    for (; i + 6 < t; i += 8) {
        float v0 = __half2float(__ldg(&acc2[(size_t)(i + 0) * HID + j]));
        float v1 = __half2float(__ldg(&acc2[(size_t)(i + 2) * HID + j]));
        float v2 = __half2float(__ldg(&acc2[(size_t)(i + 4) * HID + j]));
        float v3 = __half2float(__ldg(&acc2[(size_t)(i + 6) * HID + j]));
        p += fmaxf(fmaf(sc, v0 - am, bej), 0.f);
        p += fmaxf(fmaf(sc, v1 - am, bej), 0.f);
        p += fmaxf(fmaf(sc, v2 - am, bej), 0.f);
        p += fmaxf(fmaf(sc, v3 - am, bej), 0.f);
    }
    for (; i < t; i += 2) {
        float v = __half2float(__ldg(&acc2[(size_t)i * HID + j]));
        p += fmaxf(fmaf(sc, v - am, bej), 0.f);
    }
    s_pool[tid] = p;
    __syncthreads();
    if (tid < 192) s_pool[tid] = (s_pool[tid] + s_pool[tid + 192]) / cnt;
    __syncthreads();

    // classifier head on s_pool[0..191]
    if (tid < 96) {
        float d = bc1[tid];
#pragma unroll 8
        for (int k = 0; k < HID; k++) d = fmaf(s_pool[k], __ldg(&Wc1[k * 96 + tid]), d);
        sz[tid] = fmaxf(d, 0.f);
    }
    __syncthreads();
    if (tid < 4) {
        float o = bc2[tid];
#pragma unroll 8
        for (int k = 0; k < 96; k++) o = fmaf(sz[k], __ldg(&Wc2[k * 4 + tid]), o);
        out[g * 4 + tid] = o;
    }
}

// ---------------- launch ----------------
extern "C" void kernel_launch(void* const* d_in, const int* in_sizes, int n_in,
                              void* d_out, int out_size) {
    const float* x     = (const float*)d_in[0];
    const int*   ei    = (const int*)d_in[1];
    const int*   batch = (const int*)d_in[2];
    const float* W1  = (const float*)d_in[3];
    const float* b1  = (const float*)d_in[4];
    const float* g1  = (const float*)d_in[5];
    const float* be1 = (const float*)d_in[6];
    const float* a1  = (const float*)d_in[7];
    const float* W2  = (const float*)d_in[8];
    const float* b2  = (const float*)d_in[9];
    const float* g2  = (const float*)d_in[10];
    const float* be2 = (const float*)d_in[11];
    const float* a2  = (const float*)d_in[12];
    const float* Wc1 = (const float*)d_in[13];
    const float* bc1 = (const float*)d_in[14];
    const float* Wc2 = (const float*)d_in[15];
    const float* bc2 = (const float*)d_in[16];

    int n = in_sizes[0];        // 100000
    int e = in_sizes[1] / 2;    // 1600000
    int nb = (n + 255) / 256;   // scan blocks

    const int SMEM_GEMM = (128 * SA_STRIDE + HID * SB_STRIDE) * 2;  // 128000 B
    cudaFuncSetAttribute(k_gemm_mma, cudaFuncAttributeMaxDynamicSharedMemorySize, SMEM_GEMM);

    k_init<<<(n + 255) / 256, 256>>>(n);
    k_deg<<<(e / 2 + 255) / 256, 256>>>(ei, e);
    k_scan1<<<nb, 256>>>(n);
    k_scan2<<<1, 1024>>>(nb, n);
    k_scan3<<<nb, 256>>>(x, batch, n);
    k_fill<<<(e / 2 + 255) / 256, 256>>>(ei, e);
    k_conv1<<<(n + 255) / 256, 256>>>(n);
    k_gstats<<<NG, 128>>>();
    k_pq<<<(NG * HID + HID * HID + 255) / 256, 256>>>(W1, b1, g1, be1, a1, W2);
    k_gemm_mma<<<(n + 255) / 256, 256, SMEM_GEMM>>>(batch, n);
    k_aggregate<<<(n * 32 + 255) / 256, 256>>>(b2, n);
    k_norm2pool<<<NG, 384>>>(a2, g2, be2, Wc1, bc1, Wc2, bc2, (float*)d_out);
}

// round 14
// speedup vs baseline: 3.1033x; 1.0175x over previous
#include <cuda_runtime.h>
#include <cuda_fp16.h>
#include <cstdint>

#define NN   100000
#define NE   1600000
#define NG   512
#define HID  192
#define EPSN 1e-5f

#define SA_STRIDE 200   // halfs, conflict-free for ldmatrix
#define SB_STRIDE 200

// ---------------- scratch (no allocs allowed) ----------------
__device__ int    g_cnt[NN];
__device__ int    g_off[NN + 1];
__device__ int    g_cur[NN];
__device__ int    g_srcs[NE];
__device__ int    g_bsum[1024];
__device__ float  g_dinv[NN];
__device__ float  g_xs[NN];
__device__ float  g_agg[NN];
__device__ int    g_start[NG + 1];
__device__ float  g_P[NG * HID];
__device__ float  g_Q[NG * HID];
__device__ __half g_W2h[HID * HID];                 // fp16 copy of W2
__device__ __align__(16) __half2 g_ts16[NN * 96];   // dinv*(h1n@W2), fp16
__device__ __align__(16) __half2 g_acc2h[NN * 96];  // h2pre, fp16

// ---------------- init: zero histogram + W2->fp16 (disjoint work) ----------
__global__ void k_init(const float* __restrict__ W2, int n) {
    int i = blockIdx.x * blockDim.x + threadIdx.x;
    if (i < n) g_cnt[i] = 0;
    if (i < HID * HID) g_W2h[i] = __float2half_rn(W2[i]);
}

__global__ void k_deg(const int* __restrict__ ei, int e) {
    int idx = (blockIdx.x * blockDim.x + threadIdx.x) * 4;
    if (idx + 3 < e) {
        int4 c4 = *(const int4*)&ei[e + idx];
        atomicAdd(&g_cnt[c4.x], 1);
        atomicAdd(&g_cnt[c4.y], 1);
        atomicAdd(&g_cnt[c4.z], 1);
        atomicAdd(&g_cnt[c4.w], 1);
    } else {
        for (int k = idx; k < e; k++) atomicAdd(&g_cnt[__ldg(&ei[e + k])], 1);
    }
}

// phase-1 scan: intra-block exclusive prefix of g_cnt
__global__ void k_scan1(int n) {                    // grid = ceil(n/256)
    __shared__ int sh[256];
    int b = blockIdx.x, tid = threadIdx.x;
    int i = b * 256 + tid;
    int v = (i < n) ? g_cnt[i] : 0;
    sh[tid] = v;
    __syncthreads();
    for (int o = 1; o < 256; o <<= 1) {
        int x = sh[tid];
        int y = (tid >= o) ? sh[tid - o] : 0;
        __syncthreads();
        sh[tid] = x + y;
        __syncthreads();
    }
    if (i < n) g_off[i] = sh[tid] - v;              // intra-block exclusive
    if (tid == 255) g_bsum[b] = sh[255];
}

// phase-2+3 fused: per-block redundant prefix over g_bsum + add-back
// + node prep (dinv, xs) + graph-start binary search
__global__ void k_scan3(const float* __restrict__ x, const int* __restrict__ batch, int n) {
    __shared__ int red[256];
    int b = blockIdx.x, tid = threadIdx.x;
    int partial = 0;
    for (int k = tid; k < b; k += 256) partial += g_bsum[k];
    red[tid] = partial;
    __syncthreads();
    for (int o = 128; o > 0; o >>= 1) {
        if (tid < o) red[tid] += red[tid + o];
        __syncthreads();
    }
    int pre = red[0];
    int i = b * 256 + tid;
    if (i < n) {
        int o = g_off[i] + pre;
        g_off[i] = o;
        g_cur[i] = o;
        float v = rsqrtf((float)(g_cnt[i] + 1));    // +1 self-loop
        g_dinv[i] = v;
        g_xs[i]   = x[i] * v;
        if (i == n - 1) g_off[n] = o + g_cnt[i];
    }
    if (i <= NG) {                                   // graph range starts
        int lo = 0, hi = n;
        while (lo < hi) {
            int mid = (lo + hi) >> 1;
            if (__ldg(&batch[mid]) < i) lo = mid + 1; else hi = mid;
        }
        g_start[i] = lo;
    }
}

__global__ void k_fill(const int* __restrict__ ei, int e) {
    int idx = (blockIdx.x * blockDim.x + threadIdx.x) * 4;
    if (idx + 3 < e) {
        int4 r4 = *(const int4*)&ei[idx];
        int4 c4 = *(const int4*)&ei[e + idx];
        g_srcs[atomicAdd(&g_cur[c4.x], 1)] = r4.x;
        g_srcs[atomicAdd(&g_cur[c4.y], 1)] = r4.y;
        g_srcs[atomicAdd(&g_cur[c4.z], 1)] = r4.z;
        g_srcs[atomicAdd(&g_cur[c4.w], 1)] = r4.w;
    } else {
        for (int k = idx; k < e; k++) {
            int r = __ldg(&ei[k]);
            int c = __ldg(&ei[e + k]);
            g_srcs[atomicAdd(&g_cur[c], 1)] = r;
        }
    }
}

// ---------------- conv1 (scalar, CSR) ----------------
__global__ void k_conv1(int n) {
    int i = blockIdx.x * blockDim.x + threadIdx.x;
    if (i >= n) return;
    int off = g_off[i], end = g_off[i + 1];
    float s = g_xs[i];
    int k = off;
    for (; k + 4 <= end; k += 4) {
        int s0 = __ldg(&g_srcs[k]);
        int s1 = __ldg(&g_srcs[k + 1]);
        int s2 = __ldg(&g_srcs[k + 2]);
        int s3 = __ldg(&g_srcs[k + 3]);
        float x0 = __ldg(&g_xs[s0]);
        float x1 = __ldg(&g_xs[s1]);
        float x2 = __ldg(&g_xs[s2]);
        float x3 = __ldg(&g_xs[s3]);
        s += (x0 + x1) + (x2 + x3);
    }
    for (; k < end; k++) s += __ldg(&g_xs[__ldg(&g_srcs[k])]);
    g_agg[i] = g_dinv[i] * s;
}

// --------- graph stats for norm1 + P/Q table emission, fused per graph ------
__global__ void k_gstats_pq(const float* __restrict__ W1, const float* __restrict__ b1,
                            const float* __restrict__ g1, const float* __restrict__ be1,
                            const float* __restrict__ a1) {
    int g = blockIdx.x;
    int s = g_start[g], t = g_start[g + 1];
    int tid = threadIdx.x;
    float sum = 0.f, sq = 0.f;
    for (int i = s + tid; i < t; i += 128) {
        float a = g_agg[i];
        sum += a; sq += a * a;
    }
    __shared__ float ssum[128], ssq[128];
    __shared__ float s_m, s_v;
    ssum[tid] = sum; ssq[tid] = sq;
    __syncthreads();
    for (int o = 64; o > 0; o >>= 1) {
        if (tid < o) { ssum[tid] += ssum[tid + o]; ssq[tid] += ssq[tid + o]; }
        __syncthreads();
    }
    if (tid == 0) {
        float cnt = fmaxf((float)(t - s), 1.f);
        float m = ssum[0] / cnt;
        float v = ssq[0] / cnt - m * m;
        s_m = m;
        s_v = fmaxf(v, 0.f);
    }
    __syncthreads();
    float m = s_m, va = s_v;
    for (int j = tid; j < HID; j += 128) {
        float w = __ldg(&W1[j]), bj = __ldg(&b1[j]), aj = __ldg(&a1[j]);
        float gj = __ldg(&g1[j]), bej = __ldg(&be1[j]);
        float eo  = (1.f - aj) * (w * m + bj);
        float var = w * w * va + eo * eo;
        float sc  = gj * rsqrtf(var + EPSN);
        g_P[g * HID + j] = sc * w;
        g_Q[g * HID + j] = sc * (bj * (1.f - aj) - w * aj * m) + bej;
    }
}

// ---------------- tensor-core GEMM: ts16 = dinv * (relu(P*agg+Q) @ W2) ------
// 256 rows per block (two 128-row tiles reuse one smem W2 load), 8 warps.
__global__ __launch_bounds__(256, 1) void k_gemm_mma(const int* __restrict__ batch, int n) {
    extern __shared__ __half smem[];
    __half* sA = smem;                       // [128][SA_STRIDE]
    __half* sB = smem + 128 * SA_STRIDE;     // [192][SB_STRIDE]

    int tid  = threadIdx.x;
    int blk0 = blockIdx.x * 256;

#pragma unroll
    for (int u = 0; u < 144; u++) {
        int idx = u * 256 + tid;             // 36864 elems
        int k = idx / HID, nn2 = idx % HID;
        sB[k * SB_STRIDE + nn2] = g_W2h[idx];
    }

    int wid  = tid >> 5;
    int lane = tid & 31;
    int g8 = lane >> 3, r8 = lane & 7;

    for (int tile = 0; tile < 2; tile++) {
        int row0 = blk0 + tile * 128;
        if (tile) __syncthreads();           // all warps done reading sA

        {   // generate h1n tile in fp16: 2 threads per row, 96 cols each
            int row  = tid >> 1;
            int half = tid & 1;
            int grow = row0 + row;
            float ag = 0.f; int gb = 0;
            if (grow < n) { ag = g_agg[grow]; gb = __ldg(&batch[grow]); }
            const float* Pg = &g_P[gb * HID];
            const float* Qg = &g_Q[gb * HID];
            __half* dst = &sA[row * SA_STRIDE + half * 96];
#pragma unroll
            for (int c = 0; c < 96; c++) {
                int j = half * 96 + c;
                float v = fmaxf(fmaf(__ldg(&Pg[j]), ag, __ldg(&Qg[j])), 0.f);
                dst[c] = __float2half_rn(v);
            }
        }
        __syncthreads();

        float c[24][4];
#pragma unroll
        for (int t = 0; t < 24; t++)
#pragma unroll
            for (int q = 0; q < 4; q++) c[t][q] = 0.f;

        for (int ks = 0; ks < 12; ks++) {
            int k0 = ks * 16;
            uint32_t a0, a1, a2, a3;
            {
                int arow = wid * 16 + (g8 & 1) * 8 + r8;
                int acol = k0 + (g8 >> 1) * 8;
                uint32_t addr = (uint32_t)__cvta_generic_to_shared(&sA[arow * SA_STRIDE + acol]);
                asm volatile("ldmatrix.sync.aligned.m8n8.x4.shared.b16 {%0,%1,%2,%3}, [%4];"
                             : "=r"(a0), "=r"(a1), "=r"(a2), "=r"(a3) : "r"(addr));
            }
#pragma unroll
            for (int bt = 0; bt < 12; bt++) {
                int n0 = bt * 16;
                uint32_t b0, b1, b2, b3;
                int brow = k0 + (g8 & 1) * 8 + r8;
                int bcol = n0 + (g8 >> 1) * 8;
                uint32_t addr = (uint32_t)__cvta_generic_to_shared(&sB[brow * SB_STRIDE + bcol]);
                asm volatile("ldmatrix.sync.aligned.m8n8.x4.trans.shared.b16 {%0,%1,%2,%3}, [%4];"
                             : "=r"(b0), "=r"(b1), "=r"(b2), "=r"(b3) : "r"(addr));
                float* c0 = c[bt * 2];
                float* c1 = c[bt * 2 + 1];
                asm volatile("mma.sync.aligned.m16n8k16.row.col.f32.f16.f16.f32 "
                             "{%0,%1,%2,%3}, {%4,%5,%6,%7}, {%8,%9}, {%0,%1,%2,%3};"
                             : "+f"(c0[0]), "+f"(c0[1]), "+f"(c0[2]), "+f"(c0[3])
                             : "r"(a0), "r"(a1), "r"(a2), "r"(a3), "r"(b0), "r"(b1));
                asm volatile("mma.sync.aligned.m16n8k16.row.col.f32.f16.f16.f32 "
                             "{%0,%1,%2,%3}, {%4,%5,%6,%7}, {%8,%9}, {%0,%1,%2,%3};"
                             : "+f"(c1[0]), "+f"(c1[1]), "+f"(c1[2]), "+f"(c1[3])
                             : "r"(a0), "r"(a1), "r"(a2), "r"(a3), "r"(b2), "r"(b3));
            }
        }

        int r0 = row0 + wid * 16 + (lane >> 2);
        int r1 = r0 + 8;
        float dv0 = (r0 < n) ? g_dinv[r0] : 0.f;
        float dv1 = (r1 < n) ? g_dinv[r1] : 0.f;
#pragma unroll
        for (int t = 0; t < 24; t++) {
            int cc = t * 8 + (lane & 3) * 2;
            int o2 = cc >> 1;
            if (r0 < n)
                g_ts16[(size_t)r0 * 96 + o2] = __floats2half2_rn(c[t][0] * dv0, c[t][1] * dv0);
            if (r1 < n)
                g_ts16[(size_t)r1 * 96 + o2] = __floats2half2_rn(c[t][2] * dv1, c[t][3] * dv1);
        }
    }
}

// ---------------- conv2 aggregate (warp per dst, even/odd split) -------------
__device__ __forceinline__ void add_u2(float4& a, uint2 u) {
    __half2 h0 = *reinterpret_cast<__half2*>(&u.x);
    __half2 h1 = *reinterpret_cast<__half2*>(&u.y);
    float2 f0 = __half22float2(h0);
    float2 f1 = __half22float2(h1);
    a.x += f0.x; a.y += f0.y; a.z += f1.x; a.w += f1.y;
}

__global__ __launch_bounds__(256) void k_aggregate(const float* __restrict__ b2, int n) {
    int t = blockIdx.x * blockDim.x + threadIdx.x;
    int node  = t >> 5;
    int lane  = t & 31;
    int hlane = lane & 15;
    int half  = lane >> 4;
    if (node >= n) return;

    const uint2* ts16 = (const uint2*)g_ts16;

    float4 a0 = make_float4(0.f, 0.f, 0.f, 0.f);
    float4 a1 = a0, a2 = a0;
    if (half == 0) {                          // self-loop row (fp16)
        const uint2* sp = ts16 + (size_t)node * 48 + hlane;
        add_u2(a0, __ldg(sp));
        add_u2(a1, __ldg(sp + 16));
        add_u2(a2, __ldg(sp + 32));
    }

    int off = g_off[node], end = g_off[node + 1];

    int k = off + half;                      // this half: every other neighbor
    for (; k + 6 < end; k += 8) {            // 4 neighbors per iteration
        int s0 = __ldg(&g_srcs[k]);
        int s1 = __ldg(&g_srcs[k + 2]);
        int s2 = __ldg(&g_srcs[k + 4]);
        int s3 = __ldg(&g_srcs[k + 6]);
        const uint2* p0 = ts16 + (size_t)s0 * 48 + hlane;
        const uint2* p1 = ts16 + (size_t)s1 * 48 + hlane;
        const uint2* p2 = ts16 + (size_t)s2 * 48 + hlane;
        const uint2* p3 = ts16 + (size_t)s3 * 48 + hlane;
        uint2 u00 = __ldg(p0), u01 = __ldg(p0 + 16), u02 = __ldg(p0 + 32);
        uint2 u10 = __ldg(p1), u11 = __ldg(p1 + 16), u12 = __ldg(p1 + 32);
        uint2 u20 = __ldg(p2), u21 = __ldg(p2 + 16), u22 = __ldg(p2 + 32);
        uint2 u30 = __ldg(p3), u31 = __ldg(p3 + 16), u32 = __ldg(p3 + 32);
        add_u2(a0, u00); add_u2(a1, u01); add_u2(a2, u02);
        add_u2(a0, u10); add_u2(a1, u11); add_u2(a2, u12);
        add_u2(a0, u20); add_u2(a1, u21); add_u2(a2, u22);
        add_u2(a0, u30); add_u2(a1, u31); add_u2(a2, u32);
    }
    for (; k < end; k += 2) {
        int s = __ldg(&g_srcs[k]);
        const uint2* rp = ts16 + (size_t)s * 48 + hlane;
        uint2 u0 = __ldg(rp);
        uint2 u1 = __ldg(rp + 16);
        uint2 u2 = __ldg(rp + 32);
        add_u2(a0, u0);
        add_u2(a1, u1);
        add_u2(a2, u2);
    }

    // combine halves (butterfly over lane bit 4)
    a0.x += __shfl_xor_sync(0xffffffffu, a0.x, 16);
    a0.y += __shfl_xor_sync(0xffffffffu, a0.y, 16);
    a0.z += __shfl_xor_sync(0xffffffffu, a0.z, 16);
    a0.w += __shfl_xor_sync(0xffffffffu, a0.w, 16);
    a1.x += __shfl_xor_sync(0xffffffffu, a1.x, 16);
    a1.y += __shfl_xor_sync(0xffffffffu, a1.y, 16);
    a1.z += __shfl_xor_sync(0xffffffffu, a1.z, 16);
    a1.w += __shfl_xor_sync(0xffffffffu, a1.w, 16);
    a2.x += __shfl_xor_sync(0xffffffffu, a2.x, 16);
    a2.y += __shfl_xor_sync(0xffffffffu, a2.y, 16);
    a2.z += __shfl_xor_sync(0xffffffffu, a2.z, 16);
    a2.w += __shfl_xor_sync(0xffffffffu, a2.w, 16);

    if (half == 0) {
        float dv = g_dinv[node];
        const float4* b24 = (const float4*)b2;
        float4 b_0 = __ldg(&b24[hlane]);
        float4 b_1 = __ldg(&b24[16 + hlane]);
        float4 b_2 = __ldg(&b24[32 + hlane]);
        uint2 o0, o1, o2;
        __half2 h;
        h = __floats2half2_rn(fmaf(dv, a0.x, b_0.x), fmaf(dv, a0.y, b_0.y)); o0.x = *(uint32_t*)&h;
        h = __floats2half2_rn(fmaf(dv, a0.z, b_0.z), fmaf(dv, a0.w, b_0.w)); o0.y = *(uint32_t*)&h;
        h = __floats2half2_rn(fmaf(dv, a1.x, b_1.x), fmaf(dv, a1.y, b_1.y)); o1.x = *(uint32_t*)&h;
        h = __floats2half2_rn(fmaf(dv, a1.z, b_1.z), fmaf(dv, a1.w, b_1.w)); o1.y = *(uint32_t*)&h;
        h = __floats2half2_rn(fmaf(dv, a2.x, b_2.x), fmaf(dv, a2.y, b_2.y)); o2.x = *(uint32_t*)&h;
        h = __floats2half2_rn(fmaf(dv, a2.z, b_2.z), fmaf(dv, a2.w, b_2.w)); o2.y = *(uint32_t*)&h;
        uint2* out = (uint2*)g_acc2h + (size_t)node * 48;
        out[hlane]      = o0;
        out[16 + hlane] = o1;
        out[32 + hlane] = o2;
    }
}

// -------- fused graph_norm2 stats + relu + mean-pool + classifier head -------
// 384 threads: (j = tid%192 feature, half = tid/192 row parity)
__global__ __launch_bounds__(384) void k_norm2pool(
        const float* __restrict__ a2, const float* __restrict__ g2,
        const float* __restrict__ be2,
        const float* __restrict__ Wc1, const float* __restrict__ bc1,
        const float* __restrict__ Wc2, const float* __restrict__ bc2,
        float* __restrict__ out) {
    __shared__ float ssum[384], ssq[384];
    __shared__ float s_sc[192], s_am[192];
    __shared__ float s_pool[384];
    __shared__ float sz[96];

    int g = blockIdx.x;
    int tid = threadIdx.x;
    int j = tid % 192;
    int half = tid / 192;
    int s = g_start[g], t = g_start[g + 1];
    const __half* acc2 = (const __half*)g_acc2h;

    float sum = 0.f, sq = 0.f;
    int i = s + half;
    for (; i + 6 < t; i += 8) {
        float v0 = __half2float(__ldg(&acc2[(size_t)(i + 0) * HID + j]));
        float v1 = __half2float(__ldg(&acc2[(size_t)(i + 2) * HID + j]));
        float v2 = __half2float(__ldg(&acc2[(size_t)(i + 4) * HID + j]));
        float v3 = __half2float(__ldg(&acc2[(size_t)(i + 6) * HID + j]));
        sum += (v0 + v1) + (v2 + v3);
        sq  += (v0 * v0 + v1 * v1) + (v2 * v2 + v3 * v3);
    }
    for (; i < t; i += 2) {
        float v = __half2float(__ldg(&acc2[(size_t)i * HID + j]));
        sum += v; sq += v * v;
    }
    ssum[tid] = sum; ssq[tid] = sq;
    __syncthreads();

    float cnt = fmaxf((float)(t - s), 1.f);
    if (tid < 192) {
        float S  = ssum[tid] + ssum[tid + 192];
        float Q  = ssq[tid]  + ssq[tid + 192];
        float mean = S / cnt;
        float aj   = a2[tid];
        float var  = Q / cnt - (2.f * aj - aj * aj) * mean * mean;
        var = fmaxf(var, 0.f);
        s_sc[tid] = g2[tid] * rsqrtf(var + EPSN);
        s_am[tid] = aj * mean;
    }
    __syncthreads();

    float sc  = s_sc[j];
    float am  = s_am[j];
    float bej = be2[j];
    float p = 0.f;
    i = s + half;
    for (; i + 6 < t; i += 8) {
        float v0 = __half2float(__ldg(&acc2[(size_t)(i + 0) * HID + j]));
        float v1 = __half2float(__ldg(&acc2[(size_t)(i + 2) * HID + j]));
        float v2 = __half2float(__ldg(&acc2[(size_t)(i + 4) * HID + j]));
        float v3 = __half2float(__ldg(&acc2[(size_t)(i + 6) * HID + j]));
        p += fmaxf(fmaf(sc, v0 - am, bej), 0.f);
        p += fmaxf(fmaf(sc, v1 - am, bej), 0.f);
        p += fmaxf(fmaf(sc, v2 - am, bej), 0.f);
        p += fmaxf(fmaf(sc, v3 - am, bej), 0.f);
    }
    for (; i < t; i += 2) {
        float v = __half2float(__ldg(&acc2[(size_t)i * HID + j]));
        p += fmaxf(fmaf(sc, v - am, bej), 0.f);
    }
    s_pool[tid] = p;
    __syncthreads();
    if (tid < 192) s_pool[tid] = (s_pool[tid] + s_pool[tid + 192]) / cnt;
    __syncthreads();

    // classifier head on s_pool[0..191]
    if (tid < 96) {
        float d = bc1[tid];
#pragma unroll 8
        for (int k = 0; k < HID; k++) d = fmaf(s_pool[k], __ldg(&Wc1[k * 96 + tid]), d);
        sz[tid] = fmaxf(d, 0.f);
    }
    __syncthreads();
    if (tid < 4) {
        float o = bc2[tid];
#pragma unroll 8
        for (int k = 0; k < 96; k++) o = fmaf(sz[k], __ldg(&Wc2[k * 4 + tid]), o);
        out[g * 4 + tid] = o;
    }
}

// ---------------- launch ----------------
extern "C" void kernel_launch(void* const* d_in, const int* in_sizes, int n_in,
                              void* d_out, int out_size) {
    const float* x     = (const float*)d_in[0];
    const int*   ei    = (const int*)d_in[1];
    const int*   batch = (const int*)d_in[2];
    const float* W1  = (const float*)d_in[3];
    const float* b1  = (const float*)d_in[4];
    const float* g1  = (const float*)d_in[5];
    const float* be1 = (const float*)d_in[6];
    const float* a1  = (const float*)d_in[7];
    const float* W2  = (const float*)d_in[8];
    const float* b2  = (const float*)d_in[9];
    const float* g2  = (const float*)d_in[10];
    const float* be2 = (const float*)d_in[11];
    const float* a2  = (const float*)d_in[12];
    const float* Wc1 = (const float*)d_in[13];
    const float* bc1 = (const float*)d_in[14];
    const float* Wc2 = (const float*)d_in[15];
    const float* bc2 = (const float*)d_in[16];

    int n = in_sizes[0];        // 100000
    int e = in_sizes[1] / 2;    // 1600000
    int nb = (n + 255) / 256;   // scan blocks

    const int SMEM_GEMM = (128 * SA_STRIDE + HID * SB_STRIDE) * 2;  // 128000 B
    cudaFuncSetAttribute(k_gemm_mma, cudaFuncAttributeMaxDynamicSharedMemorySize, SMEM_GEMM);

    k_init<<<(n + 255) / 256, 256>>>(W2, n);
    k_deg<<<(e / 4 + 255) / 256, 256>>>(ei, e);
    k_scan1<<<nb, 256>>>(n);
    k_scan3<<<nb, 256>>>(x, batch, n);
    k_fill<<<(e / 4 + 255) / 256, 256>>>(ei, e);
    k_conv1<<<(n + 255) / 256, 256>>>(n);
    k_gstats_pq<<<NG, 128>>>(W1, b1, g1, be1, a1);
    k_gemm_mma<<<(n + 255) / 256, 256, SMEM_GEMM>>>(batch, n);
    k_aggregate<<<(n * 32 + 255) / 256, 256>>>(b2, n);
    k_norm2pool<<<NG, 384>>>(a2, g2, be2, Wc1, bc1, Wc2, bc2, (float*)d_out);
}

// round 16
// speedup vs baseline: 3.3222x; 1.0705x over previous
#include <cuda_runtime.h>
#include <cuda_fp16.h>
#include <cstdint>

#define NN   100000
#define NE   1600000
#define NG   512
#define HID  192
#define EPSN 1e-5f

#define SA_STRIDE 200   // halfs, conflict-free for ldmatrix; 400 B/row
#define SB_STRIDE 200

// ---------------- scratch (no allocs allowed) ----------------
__device__ int    g_cnt[NN];
__device__ int    g_off[NN + 1];
__device__ int    g_cur[NN];
__device__ int    g_srcs[NE];
__device__ int    g_bsum[1024];
__device__ float  g_dinv[NN];
__device__ float  g_xs[NN];
__device__ float  g_agg[NN];
__device__ int    g_start[NG + 1];
__device__ __align__(16) float g_P[NG * HID];
__device__ __align__(16) float g_Q[NG * HID];
__device__ __half g_W2h[HID * HID];                 // fp16 copy of W2
__device__ __align__(16) __half2 g_ts16[NN * 96];   // dinv*(h1n@W2), fp16
__device__ __align__(16) __half2 g_acc2h[NN * 96];  // h2pre, fp16

// ---------------- init: zero histogram + W2->fp16 (disjoint work) ----------
__global__ void k_init(const float* __restrict__ W2, int n) {
    int i = blockIdx.x * blockDim.x + threadIdx.x;
    if (i < n) g_cnt[i] = 0;
    if (i < HID * HID) g_W2h[i] = __float2half_rn(W2[i]);
}

__global__ void k_deg(const int* __restrict__ ei, int e) {
    int idx = (blockIdx.x * blockDim.x + threadIdx.x) * 4;
    if (idx + 3 < e) {
        int4 c4 = *(const int4*)&ei[e + idx];
        atomicAdd(&g_cnt[c4.x], 1);
        atomicAdd(&g_cnt[c4.y], 1);
        atomicAdd(&g_cnt[c4.z], 1);
        atomicAdd(&g_cnt[c4.w], 1);
    } else {
        for (int k = idx; k < e; k++) atomicAdd(&g_cnt[__ldg(&ei[e + k])], 1);
    }
}

// phase-1 scan: intra-block exclusive prefix of g_cnt
__global__ void k_scan1(int n) {                    // grid = ceil(n/256)
    __shared__ int sh[256];
    int b = blockIdx.x, tid = threadIdx.x;
    int i = b * 256 + tid;
    int v = (i < n) ? g_cnt[i] : 0;
    sh[tid] = v;
    __syncthreads();
    for (int o = 1; o < 256; o <<= 1) {
        int x = sh[tid];
        int y = (tid >= o) ? sh[tid - o] : 0;
        __syncthreads();
        sh[tid] = x + y;
        __syncthreads();
    }
    if (i < n) g_off[i] = sh[tid] - v;              // intra-block exclusive
    if (tid == 255) g_bsum[b] = sh[255];
}

// phase-2+3 fused: per-block redundant prefix over g_bsum + add-back
// + node prep (dinv, xs) + graph-start boundary detection (no binary search)
__global__ void k_scan3(const float* __restrict__ x, const int* __restrict__ batch, int n) {
    __shared__ int red[256];
    int b = blockIdx.x, tid = threadIdx.x;
    int partial = 0;
    for (int k = tid; k < b; k += 256) partial += g_bsum[k];
    red[tid] = partial;
    __syncthreads();
    for (int o = 128; o > 0; o >>= 1) {
        if (tid < o) red[tid] += red[tid + o];
        __syncthreads();
    }
    int pre = red[0];
    int i = b * 256 + tid;
    if (i < n) {
        int o = g_off[i] + pre;
        g_off[i] = o;
        g_cur[i] = o;
        float v = rsqrtf((float)(g_cnt[i] + 1));    // +1 self-loop
        g_dinv[i] = v;
        g_xs[i]   = x[i] * v;
        if (i == n - 1) g_off[n] = o + g_cnt[i];
        // graph range starts: batch sorted -> boundary detection
        int bi = __ldg(&batch[i]);
        int bn = (i + 1 < n) ? __ldg(&batch[i + 1]) : NG;
        if (i == 0)
            for (int g = 0; g <= bi; g++) g_start[g] = 0;
        for (int g = bi + 1; g <= bn; g++) g_start[g] = i + 1;
    }
}

__global__ void k_fill(const int* __restrict__ ei, int e) {
    int idx = (blockIdx.x * blockDim.x + threadIdx.x) * 4;
    if (idx + 3 < e) {
        int4 r4 = *(const int4*)&ei[idx];
        int4 c4 = *(const int4*)&ei[e + idx];
        g_srcs[atomicAdd(&g_cur[c4.x], 1)] = r4.x;
        g_srcs[atomicAdd(&g_cur[c4.y], 1)] = r4.y;
        g_srcs[atomicAdd(&g_cur[c4.z], 1)] = r4.z;
        g_srcs[atomicAdd(&g_cur[c4.w], 1)] = r4.w;
    } else {
        for (int k = idx; k < e; k++) {
            int r = __ldg(&ei[k]);
            int c = __ldg(&ei[e + k]);
            g_srcs[atomicAdd(&g_cur[c], 1)] = r;
        }
    }
}

// ---------------- conv1 (scalar, CSR) ----------------
__global__ void k_conv1(int n) {
    int i = blockIdx.x * blockDim.x + threadIdx.x;
    if (i >= n) return;
    int off = g_off[i], end = g_off[i + 1];
    float s = g_xs[i];
    int k = off;
    for (; k + 4 <= end; k += 4) {
        int s0 = __ldg(&g_srcs[k]);
        int s1 = __ldg(&g_srcs[k + 1]);
        int s2 = __ldg(&g_srcs[k + 2]);
        int s3 = __ldg(&g_srcs[k + 3]);
        float x0 = __ldg(&g_xs[s0]);
        float x1 = __ldg(&g_xs[s1]);
        float x2 = __ldg(&g_xs[s2]);
        float x3 = __ldg(&g_xs[s3]);
        s += (x0 + x1) + (x2 + x3);
    }
    for (; k < end; k++) s += __ldg(&g_xs[__ldg(&g_srcs[k])]);
    g_agg[i] = g_dinv[i] * s;
}

// --------- graph stats for norm1 + P/Q table emission, fused per graph ------
__global__ void k_gstats_pq(const float* __restrict__ W1, const float* __restrict__ b1,
                            const float* __restrict__ g1, const float* __restrict__ be1,
                            const float* __restrict__ a1) {
    int g = blockIdx.x;
    int s = g_start[g], t = g_start[g + 1];
    int tid = threadIdx.x;
    float sum = 0.f, sq = 0.f;
    for (int i = s + tid; i < t; i += 128) {
        float a = g_agg[i];
        sum += a; sq += a * a;
    }
    __shared__ float ssum[128], ssq[128];
    __shared__ float s_m, s_v;
    ssum[tid] = sum; ssq[tid] = sq;
    __syncthreads();
    for (int o = 64; o > 0; o >>= 1) {
        if (tid < o) { ssum[tid] += ssum[tid + o]; ssq[tid] += ssq[tid + o]; }
        __syncthreads();
    }
    if (tid == 0) {
        float cnt = fmaxf((float)(t - s), 1.f);
        float m = ssum[0] / cnt;
        float v = ssq[0] / cnt - m * m;
        s_m = m;
        s_v = fmaxf(v, 0.f);
    }
    __syncthreads();
    float m = s_m, va = s_v;
    for (int j = tid; j < HID; j += 128) {
        float w = __ldg(&W1[j]), bj = __ldg(&b1[j]), aj = __ldg(&a1[j]);
        float gj = __ldg(&g1[j]), bej = __ldg(&be1[j]);
        float eo  = (1.f - aj) * (w * m + bj);
        float var = w * w * va + eo * eo;
        float sc  = gj * rsqrtf(var + EPSN);
        g_P[g * HID + j] = sc * w;
        g_Q[g * HID + j] = sc * (bj * (1.f - aj) - w * aj * m) + bej;
    }
}

// ---------------- tensor-core GEMM: ts16 = dinv * (relu(P*agg+Q) @ W2) ------
// 256 rows per block (two 128-row tiles reuse one smem W2 load), 8 warps.
// h1n gen via float4 P/Q loads; epilogue staged through sA for coalesced STG.128.
__global__ __launch_bounds__(256, 1) void k_gemm_mma(const int* __restrict__ batch, int n) {
    extern __shared__ __half smem[];
    __half* sA = smem;                       // [128][SA_STRIDE]
    __half* sB = smem + 128 * SA_STRIDE;     // [192][SB_STRIDE]

    int tid  = threadIdx.x;
    int blk0 = blockIdx.x * 256;

#pragma unroll
    for (int u = 0; u < 144; u++) {
        int idx = u * 256 + tid;             // 36864 elems
        int k = idx / HID, nn2 = idx % HID;
        sB[k * SB_STRIDE + nn2] = g_W2h[idx];
    }

    int wid  = tid >> 5;
    int lane = tid & 31;
    int g8 = lane >> 3, r8 = lane & 7;

    for (int tile = 0; tile < 2; tile++) {
        int row0 = blk0 + tile * 128;
        if (tile) __syncthreads();           // all warps done with sA (prev tile copy-out)

        {   // generate h1n tile in fp16: 2 threads per row, 96 cols each (float4 path)
            int row  = tid >> 1;
            int half = tid & 1;
            int grow = row0 + row;
            float ag = 0.f; int gb = 0;
            if (grow < n) { ag = g_agg[grow]; gb = __ldg(&batch[grow]); }
            const float4* P4 = (const float4*)(g_P + gb * HID + half * 96);
            const float4* Q4 = (const float4*)(g_Q + gb * HID + half * 96);
            uint2* dst = (uint2*)&sA[row * SA_STRIDE + half * 96];
#pragma unroll
            for (int q = 0; q < 24; q++) {
                float4 p  = __ldg(&P4[q]);
                float4 qq = __ldg(&Q4[q]);
                float v0 = fmaxf(fmaf(p.x, ag, qq.x), 0.f);
                float v1 = fmaxf(fmaf(p.y, ag, qq.y), 0.f);
                float v2 = fmaxf(fmaf(p.z, ag, qq.z), 0.f);
                float v3 = fmaxf(fmaf(p.w, ag, qq.w), 0.f);
                __half2 h0 = __floats2half2_rn(v0, v1);
                __half2 h1 = __floats2half2_rn(v2, v3);
                uint2 u;
                u.x = *(uint32_t*)&h0;
                u.y = *(uint32_t*)&h1;
                dst[q] = u;
            }
        }
        __syncthreads();

        float c[24][4];
#pragma unroll
        for (int t = 0; t < 24; t++)
#pragma unroll
            for (int q = 0; q < 4; q++) c[t][q] = 0.f;

        for (int ks = 0; ks < 12; ks++) {
            int k0 = ks * 16;
            uint32_t a0, a1, a2, a3;
            {
                int arow = wid * 16 + (g8 & 1) * 8 + r8;
                int acol = k0 + (g8 >> 1) * 8;
                uint32_t addr = (uint32_t)__cvta_generic_to_shared(&sA[arow * SA_STRIDE + acol]);
                asm volatile("ldmatrix.sync.aligned.m8n8.x4.shared.b16 {%0,%1,%2,%3}, [%4];"
                             : "=r"(a0), "=r"(a1), "=r"(a2), "=r"(a3) : "r"(addr));
            }
#pragma unroll
            for (int bt = 0; bt < 12; bt++) {
                int n0 = bt * 16;
                uint32_t b0, b1, b2, b3;
                int brow = k0 + (g8 & 1) * 8 + r8;
                int bcol = n0 + (g8 >> 1) * 8;
                uint32_t addr = (uint32_t)__cvta_generic_to_shared(&sB[brow * SB_STRIDE + bcol]);
                asm volatile("ldmatrix.sync.aligned.m8n8.x4.trans.shared.b16 {%0,%1,%2,%3}, [%4];"
                             : "=r"(b0), "=r"(b1), "=r"(b2), "=r"(b3) : "r"(addr));
                float* c0 = c[bt * 2];
                float* c1 = c[bt * 2 + 1];
                asm volatile("mma.sync.aligned.m16n8k16.row.col.f32.f16.f16.f32 "
                             "{%0,%1,%2,%3}, {%4,%5,%6,%7}, {%8,%9}, {%0,%1,%2,%3};"
                             : "+f"(c0[0]), "+f"(c0[1]), "+f"(c0[2]), "+f"(c0[3])
                             : "r"(a0), "r"(a1), "r"(a2), "r"(a3), "r"(b0), "r"(b1));
                asm volatile("mma.sync.aligned.m16n8k16.row.col.f32.f16.f16.f32 "
                             "{%0,%1,%2,%3}, {%4,%5,%6,%7}, {%8,%9}, {%0,%1,%2,%3};"
                             : "+f"(c1[0]), "+f"(c1[1]), "+f"(c1[2]), "+f"(c1[3])
                             : "r"(a0), "r"(a1), "r"(a2), "r"(a3), "r"(b2), "r"(b3));
            }
        }

        // epilogue: scale by dinv, stage into sA rows owned by this warp,
        // then coalesced uint4 copy-out. (Each warp's A-fragment reads only its
        // own 16 rows of sA, so staging needs no pre-sync.)
        int lr0 = wid * 16 + (lane >> 2);    // local row 0..127
        int lr1 = lr0 + 8;
        int r0 = row0 + lr0;
        int r1 = row0 + lr1;
        float dv0 = (r0 < n) ? g_dinv[r0] : 0.f;
        float dv1 = (r1 < n) ? g_dinv[r1] : 0.f;
        __half2* sA2 = (__half2*)sA;         // row stride 100 half2
#pragma unroll
        for (int t = 0; t < 24; t++) {
            int c2 = t * 4 + (lane & 3);     // half2 column 0..95
            sA2[lr0 * 100 + c2] = __floats2half2_rn(c[t][0] * dv0, c[t][1] * dv0);
            sA2[lr1 * 100 + c2] = __floats2half2_rn(c[t][2] * dv1, c[t][3] * dv1);
        }
        __syncthreads();
#pragma unroll
        for (int u = 0; u < 12; u++) {       // 128 rows * 24 uint4 = 3072
            int idx = u * 256 + tid;
            int row = idx / 24, q = idx % 24;
            int grow = row0 + row;
            if (grow < n)
                *(uint4*)((char*)g_ts16 + (size_t)grow * 384 + q * 16) =
                    *(const uint4*)((const char*)sA + row * 400 + q * 16);
        }
    }
}

// ---------------- conv2 aggregate (warp per dst, even/odd split) -------------
__device__ __forceinline__ void add_u2(float4& a, uint2 u) {
    __half2 h0 = *reinterpret_cast<__half2*>(&u.x);
    __half2 h1 = *reinterpret_cast<__half2*>(&u.y);
    float2 f0 = __half22float2(h0);
    float2 f1 = __half22float2(h1);
    a.x += f0.x; a.y += f0.y; a.z += f1.x; a.w += f1.y;
}

__global__ __launch_bounds__(256) void k_aggregate(const float* __restrict__ b2, int n) {
    int t = blockIdx.x * blockDim.x + threadIdx.x;
    int node  = t >> 5;
    int lane  = t & 31;
    int hlane = lane & 15;
    int half  = lane >> 4;
    if (node >= n) return;

    const uint2* ts16 = (const uint2*)g_ts16;

    float4 a0 = make_float4(0.f, 0.f, 0.f, 0.f);
    float4 a1 = a0, a2 = a0;
    if (half == 0) {                          // self-loop row (fp16)
        const uint2* sp = ts16 + (size_t)node * 48 + hlane;
        add_u2(a0, __ldg(sp));
        add_u2(a1, __ldg(sp + 16));
        add_u2(a2, __ldg(sp + 32));
    }

    int off = g_off[node], end = g_off[node + 1];

    int k = off + half;                      // this half: every other neighbor
    for (; k + 6 < end; k += 8) {            // 4 neighbors per iteration
        int s0 = __ldg(&g_srcs[k]);
        int s1 = __ldg(&g_srcs[k + 2]);
        int s2 = __ldg(&g_srcs[k + 4]);
        int s3 = __ldg(&g_srcs[k + 6]);
        const uint2* p0 = ts16 + (size_t)s0 * 48 + hlane;
        const uint2* p1 = ts16 + (size_t)s1 * 48 + hlane;
        const uint2* p2 = ts16 + (size_t)s2 * 48 + hlane;
        const uint2* p3 = ts16 + (size_t)s3 * 48 + hlane;
        uint2 u00 = __ldg(p0), u01 = __ldg(p0 + 16), u02 = __ldg(p0 + 32);
        uint2 u10 = __ldg(p1), u11 = __ldg(p1 + 16), u12 = __ldg(p1 + 32);
        uint2 u20 = __ldg(p2), u21 = __ldg(p2 + 16), u22 = __ldg(p2 + 32);
        uint2 u30 = __ldg(p3), u31 = __ldg(p3 + 16), u32 = __ldg(p3 + 32);
        add_u2(a0, u00); add_u2(a1, u01); add_u2(a2, u02);
        add_u2(a0, u10); add_u2(a1, u11); add_u2(a2, u12);
        add_u2(a0, u20); add_u2(a1, u21); add_u2(a2, u22);
        add_u2(a0, u30); add_u2(a1, u31); add_u2(a2, u32);
    }
    for (; k < end; k += 2) {
        int s = __ldg(&g_srcs[k]);
        const uint2* rp = ts16 + (size_t)s * 48 + hlane;
        uint2 u0 = __ldg(rp);
        uint2 u1 = __ldg(rp + 16);
        uint2 u2 = __ldg(rp + 32);
        add_u2(a0, u0);
        add_u2(a1, u1);
        add_u2(a2, u2);
    }

    // combine halves (butterfly over lane bit 4)
    a0.x += __shfl_xor_sync(0xffffffffu, a0.x, 16);
    a0.y += __shfl_xor_sync(0xffffffffu, a0.y, 16);
    a0.z += __shfl_xor_sync(0xffffffffu, a0.z, 16);
    a0.w += __shfl_xor_sync(0xffffffffu, a0.w, 16);
    a1.x += __shfl_xor_sync(0xffffffffu, a1.x, 16);
    a1.y += __shfl_xor_sync(0xffffffffu, a1.y, 16);
    a1.z += __shfl_xor_sync(0xffffffffu, a1.z, 16);
    a1.w += __shfl_xor_sync(0xffffffffu, a1.w, 16);
    a2.x += __shfl_xor_sync(0xffffffffu, a2.x, 16);
    a2.y += __shfl_xor_sync(0xffffffffu, a2.y, 16);
    a2.z += __shfl_xor_sync(0xffffffffu, a2.z, 16);
    a2.w += __shfl_xor_sync(0xffffffffu, a2.w, 16);

    if (half == 0) {
        float dv = g_dinv[node];
        const float4* b24 = (const float4*)b2;
        float4 b_0 = __ldg(&b24[hlane]);
        float4 b_1 = __ldg(&b24[16 + hlane]);
        float4 b_2 = __ldg(&b24[32 + hlane]);
        uint2 o0, o1, o2;
        __half2 h;
        h = __floats2half2_rn(fmaf(dv, a0.x, b_0.x), fmaf(dv, a0.y, b_0.y)); o0.x = *(uint32_t*)&h;
        h = __floats2half2_rn(fmaf(dv, a0.z, b_0.z), fmaf(dv, a0.w, b_0.w)); o0.y = *(uint32_t*)&h;
        h = __floats2half2_rn(fmaf(dv, a1.x, b_1.x), fmaf(dv, a1.y, b_1.y)); o1.x = *(uint32_t*)&h;
        h = __floats2half2_rn(fmaf(dv, a1.z, b_1.z), fmaf(dv, a1.w, b_1.w)); o1.y = *(uint32_t*)&h;
        h = __floats2half2_rn(fmaf(dv, a2.x, b_2.x), fmaf(dv, a2.y, b_2.y)); o2.x = *(uint32_t*)&h;
        h = __floats2half2_rn(fmaf(dv, a2.z, b_2.z), fmaf(dv, a2.w, b_2.w)); o2.y = *(uint32_t*)&h;
        uint2* out = (uint2*)g_acc2h + (size_t)node * 48;
        out[hlane]      = o0;
        out[16 + hlane] = o1;
        out[32 + hlane] = o2;
    }
}

// -------- fused graph_norm2 stats + relu + mean-pool + classifier head -------
// 384 threads: (j = tid%192 feature, half = tid/192 row parity)
__global__ __launch_bounds__(384) void k_norm2pool(
        const float* __restrict__ a2, const float* __restrict__ g2,
        const float* __restrict__ be2,
        const float* __restrict__ Wc1, const float* __restrict__ bc1,
        const float* __restrict__ Wc2, const float* __restrict__ bc2,
        float* __restrict__ out) {
    __shared__ float ssum[384], ssq[384];
    __shared__ float s_sc[192], s_am[192];
    __shared__ float s_pool[384];
    __shared__ float sz[96];

    int g = blockIdx.x;
    int tid = threadIdx.x;
    int j = tid % 192;
    int half = tid / 192;
    int s = g_start[g], t = g_start[g + 1];
    const __half* acc2 = (const __half*)g_acc2h;

    float sum = 0.f, sq = 0.f;
    int i = s + half;
    for (; i + 6 < t; i += 8) {
        float v0 = __half2float(__ldg(&acc2[(size_t)(i + 0) * HID + j]));
        float v1 = __half2float(__ldg(&acc2[(size_t)(i + 2) * HID + j]));
        float v2 = __half2float(__ldg(&acc2[(size_t)(i + 4) * HID + j]));
        float v3 = __half2float(__ldg(&acc2[(size_t)(i + 6) * HID + j]));
        sum += (v0 + v1) + (v2 + v3);
        sq  += (v0 * v0 + v1 * v1) + (v2 * v2 + v3 * v3);
    }
    for (; i < t; i += 2) {
        float v = __half2float(__ldg(&acc2[(size_t)i * HID + j]));
        sum += v; sq += v * v;
    }
    ssum[tid] = sum; ssq[tid] = sq;
    __syncthreads();

    float cnt = fmaxf((float)(t - s), 1.f);
    if (tid < 192) {
        float S  = ssum[tid] + ssum[tid + 192];
        float Q  = ssq[tid]  + ssq[tid + 192];
        float mean = S / cnt;
        float aj   = a2[tid];
        float var  = Q / cnt - (2.f * aj - aj * aj) * mean * mean;
        var = fmaxf(var, 0.f);
        s_sc[tid] = g2[tid] * rsqrtf(var + EPSN);
        s_am[tid] = aj * mean;
    }
    __syncthreads();

    float sc  = s_sc[j];
    float am  = s_am[j];
    float bej = be2[j];
    float p = 0.f;
    i = s + half;
    for (; i + 6 < t; i += 8) {
        float v0 = __half2float(__ldg(&acc2[(size_t)(i + 0) * HID + j]));
        float v1 = __half2float(__ldg(&acc2[(size_t)(i + 2) * HID + j]));
        float v2 = __half2float(__ldg(&acc2[(size_t)(i + 4) * HID + j]));
        float v3 = __half2float(__ldg(&acc2[(size_t)(i + 6) * HID + j]));
        p += fmaxf(fmaf(sc, v0 - am, bej), 0.f);
        p += fmaxf(fmaf(sc, v1 - am, bej), 0.f);
        p += fmaxf(fmaf(sc, v2 - am, bej), 0.f);
        p += fmaxf(fmaf(sc, v3 - am, bej), 0.f);
    }
    for (; i < t; i += 2) {
        float v = __half2float(__ldg(&acc2[(size_t)i * HID + j]));
        p += fmaxf(fmaf(sc, v - am, bej), 0.f);
    }
    s_pool[tid] = p;
    __syncthreads();
    if (tid < 192) s_pool[tid] = (s_pool[tid] + s_pool[tid + 192]) / cnt;
    __syncthreads();

    // classifier head on s_pool[0..191]
    if (tid < 96) {
        float d = bc1[tid];
#pragma unroll 8
        for (int k = 0; k < HID; k++) d = fmaf(s_pool[k], __ldg(&Wc1[k * 96 + tid]), d);
        sz[tid] = fmaxf(d, 0.f);
    }
    __syncthreads();
    if (tid < 4) {
        float o = bc2[tid];
#pragma unroll 8
        for (int k = 0; k < 96; k++) o = fmaf(sz[k], __ldg(&Wc2[k * 4 + tid]), o);
        out[g * 4 + tid] = o;
    }
}

// ---------------- launch ----------------
extern "C" void kernel_launch(void* const* d_in, const int* in_sizes, int n_in,
                              void* d_out, int out_size) {
    const float* x     = (const float*)d_in[0];
    const int*   ei    = (const int*)d_in[1];
    const int*   batch = (const int*)d_in[2];
    const float* W1  = (const float*)d_in[3];
    const float* b1  = (const float*)d_in[4];
    const float* g1  = (const float*)d_in[5];
    const float* be1 = (const float*)d_in[6];
    const float* a1  = (const float*)d_in[7];
    const float* W2  = (const float*)d_in[8];
    const float* b2  = (const float*)d_in[9];
    const float* g2  = (const float*)d_in[10];
    const float* be2 = (const float*)d_in[11];
    const float* a2  = (const float*)d_in[12];
    const float* Wc1 = (const float*)d_in[13];
    const float* bc1 = (const float*)d_in[14];
    const float* Wc2 = (const float*)d_in[15];
    const float* bc2 = (const float*)d_in[16];

    int n = in_sizes[0];        // 100000
    int e = in_sizes[1] / 2;    // 1600000
    int nb = (n + 255) / 256;   // scan blocks

    const int SMEM_GEMM = (128 * SA_STRIDE + HID * SB_STRIDE) * 2;  // 128000 B
    cudaFuncSetAttribute(k_gemm_mma, cudaFuncAttributeMaxDynamicSharedMemorySize, SMEM_GEMM);

    k_init<<<(n + 255) / 256, 256>>>(W2, n);
    k_deg<<<(e / 4 + 255) / 256, 256>>>(ei, e);
    k_scan1<<<nb, 256>>>(n);
    k_scan3<<<nb, 256>>>(x, batch, n);
    k_fill<<<(e / 4 + 255) / 256, 256>>>(ei, e);
    k_conv1<<<(n + 255) / 256, 256>>>(n);
    k_gstats_pq<<<NG, 128>>>(W1, b1, g1, be1, a1);
    k_gemm_mma<<<(n + 255) / 256, 256, SMEM_GEMM>>>(batch, n);
    k_aggregate<<<(n * 32 + 255) / 256, 256>>>(b2, n);
    k_norm2pool<<<NG, 384>>>(a2, g2, be2, Wc1, bc1, Wc2, bc2, (float*)d_out);
}